// round 1
// baseline (speedup 1.0000x reference)
#include <cuda_runtime.h>
#include <math.h>

#define EMBED 2048
#define NH 16
#define NKV 4
#define HD 128
#define FF 5632
#define BB 2
#define SS 2048
#define ROWS (BB*SS)                 // 4096 tokens
#define QKV_N ((NH + 2*NKV)*HD)      // 3072

// ---------------- scratch (device globals; no allocations allowed) ----------
__device__ float g_hnorm[ROWS*EMBED];
__device__ float g_qkv [ROWS*QKV_N];
__device__ float g_qt  [BB*NH *SS*HD];
__device__ float g_kt  [BB*NKV*SS*HD];
__device__ float g_vt  [BB*NKV*SS*HD];
__device__ float g_attn[ROWS*EMBED];
__device__ float g_h1  [ROWS*EMBED];
__device__ float g_u1  [ROWS*FF];
__device__ float g_u2  [ROWS*FF];

// ---------------- RMSNorm: one block per row of 2048 ------------------------
__global__ __launch_bounds__(256) void rmsnorm_kernel(
    const float* __restrict__ x, const float* __restrict__ w,
    float* __restrict__ out)
{
    __shared__ float red[8];
    int row = blockIdx.x;
    int tid = threadIdx.x;
    const float4* xr = (const float4*)(x + (size_t)row * EMBED);
    const float4* w4 = (const float4*)w;
    float4 v0 = xr[tid];
    float4 v1 = xr[tid + 256];
    float ss = v0.x*v0.x + v0.y*v0.y + v0.z*v0.z + v0.w*v0.w
             + v1.x*v1.x + v1.y*v1.y + v1.z*v1.z + v1.w*v1.w;
    #pragma unroll
    for (int o = 16; o > 0; o >>= 1) ss += __shfl_xor_sync(0xffffffffu, ss, o);
    if ((tid & 31) == 0) red[tid >> 5] = ss;
    __syncthreads();
    float tot = red[0] + red[1] + red[2] + red[3] + red[4] + red[5] + red[6] + red[7];
    float inv = rsqrtf(tot * (1.0f / EMBED) + 1e-5f);
    float4 wa = w4[tid], wb = w4[tid + 256];
    float4 o0, o1;
    o0.x = v0.x*inv*wa.x; o0.y = v0.y*inv*wa.y; o0.z = v0.z*inv*wa.z; o0.w = v0.w*inv*wa.w;
    o1.x = v1.x*inv*wb.x; o1.y = v1.y*inv*wb.y; o1.z = v1.z*inv*wb.z; o1.w = v1.w*inv*wb.w;
    float4* orow = (float4*)(out + (size_t)row * EMBED);
    orow[tid] = o0;
    orow[tid + 256] = o1;
}

// ---------------- SGEMM: C[M,N] = A[M,K] * B[N,K]^T (+ addend) --------------
// 128x128 tile, BK=16, 256 threads, 8x8 microtile.
__global__ __launch_bounds__(256) void sgemm_nt(
    const float* __restrict__ A, const float* __restrict__ B,
    float* __restrict__ C, const float* __restrict__ addend,
    int M, int N, int K)
{
    const int BK = 16;
    __shared__ float As[BK * 132];
    __shared__ float Bs[BK * 132];
    int tid = threadIdx.x;
    int bn = blockIdx.x * 128, bm = blockIdx.y * 128;
    int lr = tid >> 2;              // 0..63
    int lc = (tid & 3) << 2;        // 0,4,8,12
    const float* Ap = A + (size_t)(bm + lr) * K + lc;
    const float* Bp = B + (size_t)(bn + lr) * K + lc;
    int tx = tid & 15, ty = tid >> 4;
    float acc[8][8];
    #pragma unroll
    for (int i = 0; i < 8; i++)
        #pragma unroll
        for (int j = 0; j < 8; j++) acc[i][j] = 0.f;

    for (int k0 = 0; k0 < K; k0 += BK) {
        float4 a0 = *(const float4*)(Ap + k0);
        float4 a1 = *(const float4*)(Ap + (size_t)64 * K + k0);
        float4 b0 = *(const float4*)(Bp + k0);
        float4 b1 = *(const float4*)(Bp + (size_t)64 * K + k0);
        As[(lc+0)*132 + lr] = a0.x; As[(lc+1)*132 + lr] = a0.y;
        As[(lc+2)*132 + lr] = a0.z; As[(lc+3)*132 + lr] = a0.w;
        As[(lc+0)*132 + lr+64] = a1.x; As[(lc+1)*132 + lr+64] = a1.y;
        As[(lc+2)*132 + lr+64] = a1.z; As[(lc+3)*132 + lr+64] = a1.w;
        Bs[(lc+0)*132 + lr] = b0.x; Bs[(lc+1)*132 + lr] = b0.y;
        Bs[(lc+2)*132 + lr] = b0.z; Bs[(lc+3)*132 + lr] = b0.w;
        Bs[(lc+0)*132 + lr+64] = b1.x; Bs[(lc+1)*132 + lr+64] = b1.y;
        Bs[(lc+2)*132 + lr+64] = b1.z; Bs[(lc+3)*132 + lr+64] = b1.w;
        __syncthreads();
        #pragma unroll
        for (int kk = 0; kk < BK; kk++) {
            float ar[8], br[8];
            *(float4*)(ar)   = *(const float4*)&As[kk*132 + ty*8];
            *(float4*)(ar+4) = *(const float4*)&As[kk*132 + ty*8 + 4];
            *(float4*)(br)   = *(const float4*)&Bs[kk*132 + tx*8];
            *(float4*)(br+4) = *(const float4*)&Bs[kk*132 + tx*8 + 4];
            #pragma unroll
            for (int i = 0; i < 8; i++)
                #pragma unroll
                for (int j = 0; j < 8; j++)
                    acc[i][j] += ar[i] * br[j];
        }
        __syncthreads();
    }
    #pragma unroll
    for (int i = 0; i < 8; i++) {
        size_t row = (size_t)(bm + ty*8 + i);
        float* Cp = C + row * N + bn + tx*8;
        float4 c0 = make_float4(acc[i][0], acc[i][1], acc[i][2], acc[i][3]);
        float4 c1 = make_float4(acc[i][4], acc[i][5], acc[i][6], acc[i][7]);
        if (addend) {
            const float* Adp = addend + row * N + bn + tx*8;
            float4 d0 = *(const float4*)(Adp);
            float4 d1 = *(const float4*)(Adp + 4);
            c0.x += d0.x; c0.y += d0.y; c0.z += d0.z; c0.w += d0.w;
            c1.x += d1.x; c1.y += d1.y; c1.z += d1.z; c1.w += d1.w;
        }
        *(float4*)(Cp)     = c0;
        *(float4*)(Cp + 4) = c1;
    }
}

// ---------------- RoPE + head transpose --------------------------------------
// qkv row layout: [NH*HD q | NKV*HD k | NKV*HD v]; rope on q,k (consecutive pairs)
__global__ __launch_bounds__(256) void rope_kernel(
    const float* __restrict__ qkv, const float* __restrict__ freqs,
    float* __restrict__ qt, float* __restrict__ kt, float* __restrict__ vt)
{
    int s = blockIdx.x, b = blockIdx.y, tid = threadIdx.x;
    const float* row = qkv + ((size_t)b * SS + s) * QKV_N;
    const float* f = freqs + (size_t)s * HD;   // (HD/2, 2) cos/sin pairs

    // Q: NH*64 = 1024 pairs
    for (int p = tid; p < NH * 64; p += 256) {
        int h = p >> 6, i = p & 63;
        float x0 = row[h*HD + 2*i], x1 = row[h*HD + 2*i + 1];
        float c = f[2*i], sn = f[2*i+1];
        float* dst = qt + (((size_t)(b*NH + h) * SS + s) * HD);
        dst[2*i]   = x0*c - x1*sn;
        dst[2*i+1] = x1*c + x0*sn;
    }
    // K: NKV*64 = 256 pairs
    for (int p = tid; p < NKV * 64; p += 256) {
        int h = p >> 6, i = p & 63;
        float x0 = row[NH*HD + h*HD + 2*i], x1 = row[NH*HD + h*HD + 2*i + 1];
        float c = f[2*i], sn = f[2*i+1];
        float* dst = kt + (((size_t)(b*NKV + h) * SS + s) * HD);
        dst[2*i]   = x0*c - x1*sn;
        dst[2*i+1] = x1*c + x0*sn;
    }
    // V: copy NKV*HD = 512 floats
    for (int p = tid; p < NKV * HD; p += 256) {
        int h = p >> 7, d = p & 127;
        vt[(((size_t)(b*NKV + h) * SS + s) * HD) + d] = row[(NH + NKV)*HD + p];
    }
}

// ---------------- Flash attention (fp32, causal, GQA 4:1) --------------------
// Block: 64 q-rows x full HD. Tiles of 64 keys. 256 threads.
#define FL_SMEM_FLOATS (128*68*2 + 64*128 + 64*68 + 192)
__global__ __launch_bounds__(256) void flash_kernel()
{
    extern __shared__ float sm[];
    float* Qts   = sm;                 // [128][68] d-major, scaled
    float* Kts   = Qts + 128*68;       // [128][68] d-major
    float* Vs    = Kts + 128*68;       // [64][128]
    float* Sts   = Vs + 64*128;        // [64 kc][68 qr]
    float* row_m = Sts + 64*68;
    float* row_l = row_m + 64;
    float* row_sc= row_l + 64;

    int tid = threadIdx.x;
    int qb = blockIdx.x, hb = blockIdx.y, bb = blockIdx.z;
    const float scale = 0.02209708691207961f;   // 1/sqrt(2048)

    const float* Qg    = g_qt + (((size_t)(bb*NH + hb) * SS + (size_t)qb*64) * HD);
    const float* Kbase = g_kt + (((size_t)(bb*NKV + (hb >> 2)) * SS) * HD);
    const float* Vbase = g_vt + (((size_t)(bb*NKV + (hb >> 2)) * SS) * HD);

    for (int i = tid; i < 64*32; i += 256) {
        int r = i >> 5, d4 = (i & 31) << 2;
        float4 q4 = *(const float4*)(Qg + r*HD + d4);
        Qts[(d4+0)*68 + r] = q4.x * scale;
        Qts[(d4+1)*68 + r] = q4.y * scale;
        Qts[(d4+2)*68 + r] = q4.z * scale;
        Qts[(d4+3)*68 + r] = q4.w * scale;
    }
    if (tid < 64) { row_m[tid] = -1e30f; row_l[tid] = 0.f; }

    int txq = tid & 15, tyk = tid >> 4;   // S roles: q-group, k-group
    int txc = tid & 15, tyr = tid >> 4;   // PV roles: col-group (x8), row-group (x4)
    float acc[4][8];
    #pragma unroll
    for (int i = 0; i < 4; i++)
        #pragma unroll
        for (int j = 0; j < 8; j++) acc[i][j] = 0.f;

    for (int kb = 0; kb <= qb; kb++) {
        __syncthreads();
        const float* Kg = Kbase + (size_t)kb * 64 * HD;
        const float* Vg = Vbase + (size_t)kb * 64 * HD;
        for (int i = tid; i < 64*32; i += 256) {
            int r = i >> 5, d4 = (i & 31) << 2;
            float4 k4 = *(const float4*)(Kg + r*HD + d4);
            Kts[(d4+0)*68 + r] = k4.x;
            Kts[(d4+1)*68 + r] = k4.y;
            Kts[(d4+2)*68 + r] = k4.z;
            Kts[(d4+3)*68 + r] = k4.w;
            *(float4*)&Vs[r*HD + d4] = *(const float4*)(Vg + r*HD + d4);
        }
        __syncthreads();
        // S = Q·K^T  (64x64), thread computes 4x4
        float s[4][4];
        #pragma unroll
        for (int i = 0; i < 4; i++)
            #pragma unroll
            for (int j = 0; j < 4; j++) s[i][j] = 0.f;
        #pragma unroll 4
        for (int d = 0; d < 128; d++) {
            float qr[4], kr[4];
            *(float4*)qr = *(const float4*)&Qts[d*68 + txq*4];
            *(float4*)kr = *(const float4*)&Kts[d*68 + tyk*4];
            #pragma unroll
            for (int i = 0; i < 4; i++)
                #pragma unroll
                for (int j = 0; j < 4; j++)
                    s[i][j] += qr[i] * kr[j];
        }
        #pragma unroll
        for (int i = 0; i < 4; i++)
            #pragma unroll
            for (int j = 0; j < 4; j++)
                Sts[(tyk*4 + j)*68 + txq*4 + i] = s[i][j];
        __syncthreads();
        // online softmax per q-row (64 threads)
        if (tid < 64) {
            int r = tid;
            int valid = (kb == qb) ? (r + 1) : 64;
            float mx = row_m[r];
            for (int kc = 0; kc < valid; kc++) mx = fmaxf(mx, Sts[kc*68 + r]);
            float fac = __expf(row_m[r] - mx);
            float l = row_l[r] * fac;
            for (int kc = 0; kc < 64; kc++) {
                float p = (kc < valid) ? __expf(Sts[kc*68 + r] - mx) : 0.f;
                Sts[kc*68 + r] = p;
                l += p;
            }
            row_m[r] = mx; row_l[r] = l; row_sc[r] = fac;
        }
        __syncthreads();
        // acc = acc*fac + P·V   (thread: 4 rows x 8 cols)
        float fc[4];
        #pragma unroll
        for (int i = 0; i < 4; i++) fc[i] = row_sc[tyr*4 + i];
        #pragma unroll
        for (int i = 0; i < 4; i++)
            #pragma unroll
            for (int j = 0; j < 8; j++) acc[i][j] *= fc[i];
        #pragma unroll 2
        for (int kk = 0; kk < 64; kk++) {
            float pr[4], vv[8];
            *(float4*)pr     = *(const float4*)&Sts[kk*68 + tyr*4];
            *(float4*)vv     = *(const float4*)&Vs[kk*128 + txc*8];
            *(float4*)(vv+4) = *(const float4*)&Vs[kk*128 + txc*8 + 4];
            #pragma unroll
            for (int i = 0; i < 4; i++)
                #pragma unroll
                for (int j = 0; j < 8; j++)
                    acc[i][j] += pr[i] * vv[j];
        }
    }
    // write out: g_attn[(b*S + s), h*HD + d]
    #pragma unroll
    for (int i = 0; i < 4; i++) {
        float inv = 1.f / row_l[tyr*4 + i];
        size_t grow = (size_t)bb * SS + (size_t)qb*64 + tyr*4 + i;
        float* Op = g_attn + grow * EMBED + hb*HD + txc*8;
        float4 o0 = make_float4(acc[i][0]*inv, acc[i][1]*inv, acc[i][2]*inv, acc[i][3]*inv);
        float4 o1 = make_float4(acc[i][4]*inv, acc[i][5]*inv, acc[i][6]*inv, acc[i][7]*inv);
        *(float4*)(Op)     = o0;
        *(float4*)(Op + 4) = o1;
    }
}

// ---------------- SwiGLU elementwise: u1 = silu(u1) * u2 ---------------------
__global__ __launch_bounds__(256) void silu_mul_kernel(
    float* __restrict__ u1, const float* __restrict__ u2, int n4)
{
    int i = blockIdx.x * 256 + threadIdx.x;
    if (i >= n4) return;
    float4 a = ((float4*)u1)[i];
    float4 b = ((const float4*)u2)[i];
    a.x = a.x / (1.f + __expf(-a.x)) * b.x;
    a.y = a.y / (1.f + __expf(-a.y)) * b.y;
    a.z = a.z / (1.f + __expf(-a.z)) * b.z;
    a.w = a.w / (1.f + __expf(-a.w)) * b.w;
    ((float4*)u1)[i] = a;
}

// ---------------- driver ------------------------------------------------------
extern "C" void kernel_launch(void* const* d_in, const int* in_sizes, int n_in,
                              void* d_out, int out_size)
{
    const float* x       = (const float*)d_in[0];
    const float* freqs   = (const float*)d_in[2];
    const float* w_qkv   = (const float*)d_in[4];
    const float* w_fc    = (const float*)d_in[5];
    const float* w1      = (const float*)d_in[6];
    const float* w2      = (const float*)d_in[7];
    const float* w3      = (const float*)d_in[8];
    const float* attn_nw = (const float*)d_in[9];
    const float* ff_nw   = (const float*)d_in[10];
    float* out = (float*)d_out;

    float *hnorm, *qkv, *qt, *kt, *vt, *attn, *h1, *u1, *u2;
    cudaGetSymbolAddress((void**)&hnorm, g_hnorm);
    cudaGetSymbolAddress((void**)&qkv,   g_qkv);
    cudaGetSymbolAddress((void**)&qt,    g_qt);
    cudaGetSymbolAddress((void**)&kt,    g_kt);
    cudaGetSymbolAddress((void**)&vt,    g_vt);
    cudaGetSymbolAddress((void**)&attn,  g_attn);
    cudaGetSymbolAddress((void**)&h1,    g_h1);
    cudaGetSymbolAddress((void**)&u1,    g_u1);
    cudaGetSymbolAddress((void**)&u2,    g_u2);

    // 1. attn rmsnorm
    rmsnorm_kernel<<<ROWS, 256>>>(x, attn_nw, hnorm);
    // 2. qkv projection
    sgemm_nt<<<dim3(QKV_N/128, ROWS/128), 256>>>(hnorm, w_qkv, qkv, nullptr, ROWS, QKV_N, EMBED);
    // 3. rope + head-major transpose
    rope_kernel<<<dim3(SS, BB), 256>>>(qkv, freqs, qt, kt, vt);
    // 4. flash attention
    const int fl_bytes = FL_SMEM_FLOATS * 4;
    cudaFuncSetAttribute(flash_kernel, cudaFuncAttributeMaxDynamicSharedMemorySize, fl_bytes);
    flash_kernel<<<dim3(SS/64, NH, BB), 256, fl_bytes>>>();
    // 5. output projection + residual
    sgemm_nt<<<dim3(EMBED/128, ROWS/128), 256>>>(attn, w_fc, h1, x, ROWS, EMBED, EMBED);
    // 6. ffn rmsnorm
    rmsnorm_kernel<<<ROWS, 256>>>(h1, ff_nw, hnorm);
    // 7-8. gate / up projections
    sgemm_nt<<<dim3(FF/128, ROWS/128), 256>>>(hnorm, w1, u1, nullptr, ROWS, FF, EMBED);
    sgemm_nt<<<dim3(FF/128, ROWS/128), 256>>>(hnorm, w2, u2, nullptr, ROWS, FF, EMBED);
    // 9. swiglu
    silu_mul_kernel<<<(ROWS*FF/4 + 255)/256, 256>>>(u1, u2, ROWS*FF/4);
    // 10. down projection + residual -> out
    sgemm_nt<<<dim3(EMBED/128, ROWS/128), 256>>>(u1, w3, out, h1, ROWS, EMBED, FF);
}

// round 3
// speedup vs baseline: 3.4170x; 3.4170x over previous
#include <cuda_runtime.h>
#include <cuda_bf16.h>
#include <math.h>
#include <stdint.h>

#define EMBED 2048
#define NH 16
#define NKV 4
#define HD 128
#define FF 5632
#define BB 2
#define SS 2048
#define ROWS (BB*SS)                 // 4096 tokens
#define QKV_N ((NH + 2*NKV)*HD)      // 3072

#if defined(__CUDA_ARCH_FEAT_SM103_ALL) || defined(__CUDA_ARCH_FEAT_SM100_ALL)
#define USE_TCGEN05 1
#else
#define USE_TCGEN05 0
#endif

// ---------------- scratch (device globals; no allocations allowed) ----------
__device__ float g_hnorm[ROWS*EMBED];
__device__ float g_qkv [ROWS*QKV_N];
__device__ float g_qt  [BB*NH *SS*HD];
__device__ float g_kt  [BB*NKV*SS*HD];
__device__ float g_vt  [BB*NKV*SS*HD];
__device__ float g_attn[ROWS*EMBED];
__device__ float g_h1  [ROWS*EMBED];
__device__ float g_u1  [ROWS*FF];
__device__ float g_u2  [ROWS*FF];
// bf16 split buffers (hi/lo) for activations and weights
__device__ __nv_bfloat16 g_ah[ROWS*FF];
__device__ __nv_bfloat16 g_al[ROWS*FF];
__device__ __nv_bfloat16 g_wh[FF*EMBED];
__device__ __nv_bfloat16 g_wl[FF*EMBED];

// GEMM launch config shared by both paths: BM=128, BN=256
#define GM_STAGE_BYTES 98304
#define GM_SMEM_BYTES (1024 + 2*GM_STAGE_BYTES)

// ======================= split fp32 -> bf16 hi/lo ============================
__global__ __launch_bounds__(256) void split_kernel(
    const float* __restrict__ x, __nv_bfloat16* __restrict__ hi,
    __nv_bfloat16* __restrict__ lo, int n4)
{
    int i = blockIdx.x * 256 + threadIdx.x;
    if (i >= n4) return;
    float4 v = ((const float4*)x)[i];
    __nv_bfloat16 h0 = __float2bfloat16(v.x);
    __nv_bfloat16 h1 = __float2bfloat16(v.y);
    __nv_bfloat16 h2 = __float2bfloat16(v.z);
    __nv_bfloat16 h3 = __float2bfloat16(v.w);
    __nv_bfloat16 l0 = __float2bfloat16(v.x - __bfloat162float(h0));
    __nv_bfloat16 l1 = __float2bfloat16(v.y - __bfloat162float(h1));
    __nv_bfloat16 l2 = __float2bfloat16(v.z - __bfloat162float(h2));
    __nv_bfloat16 l3 = __float2bfloat16(v.w - __bfloat162float(h3));
    __nv_bfloat162* H = (__nv_bfloat162*)hi;
    __nv_bfloat162* L = (__nv_bfloat162*)lo;
    H[2*i]   = __nv_bfloat162(h0, h1);
    H[2*i+1] = __nv_bfloat162(h2, h3);
    L[2*i]   = __nv_bfloat162(l0, l1);
    L[2*i+1] = __nv_bfloat162(l2, l3);
}

#if USE_TCGEN05
// ======================= tcgen05 path (sm_103a pass only) ====================
__device__ __forceinline__ uint32_t elect_one_pred() {
    uint32_t pred;
    asm volatile(
        "{\n\t.reg .pred p;\n\telect.sync _|p, 0xFFFFFFFF;\n\tselp.b32 %0, 1, 0, p;\n\t}"
        : "=r"(pred));
    return pred;
}
__device__ __forceinline__ uint32_t smem_u32(const void* p) {
    uint32_t a;
    asm("{ .reg .u64 t; cvta.to.shared.u64 t, %1; cvt.u32.u64 %0, t; }" : "=r"(a) : "l"(p));
    return a;
}
#define MBAR_INIT(addr, cnt) \
    asm volatile("mbarrier.init.shared.b64 [%0], %1;" :: "r"(addr), "r"((uint32_t)(cnt)) : "memory")
#define MBAR_INVAL(addr) \
    asm volatile("mbarrier.inval.shared.b64 [%0];" :: "r"(addr) : "memory")
#define MBAR_WAIT(addr, parity) do { \
    uint32_t _m = (addr); uint32_t _p = (parity); uint32_t _d; \
    asm volatile("{\n\t.reg .pred p;\n\tmbarrier.try_wait.parity.acquire.cta.shared::cta.b64 p, [%1], %2;\n\tselp.b32 %0, 1, 0, p;\n\t}" \
        : "=r"(_d) : "r"(_m), "r"(_p) : "memory"); \
    if (!_d) { \
        asm volatile("{\n\t.reg .pred P1;\n\tWL_%=:\n\tmbarrier.try_wait.parity.acquire.cta.shared::cta.b64 P1, [%0], %1, 0x989680;\n\t@P1 bra.uni WD_%=;\n\tbra.uni WL_%=;\n\tWD_%=:\n\t}" \
            :: "r"(_m), "r"(_p) : "memory"); \
    } } while(0)
#define TC_ALLOC(smem_addr, n) \
    asm volatile("tcgen05.alloc.cta_group::1.sync.aligned.shared::cta.b32 [%0], %1;" \
        :: "r"((uint32_t)(smem_addr)), "r"((uint32_t)(n)) : "memory")
#define TC_DEALLOC(tmem_addr, n) \
    asm volatile("tcgen05.dealloc.cta_group::1.sync.aligned.b32 %0, %1;" :: "r"(tmem_addr), "r"((uint32_t)(n)))
#define TC_RELINQ() \
    asm volatile("tcgen05.relinquish_alloc_permit.cta_group::1.sync.aligned;")
#define TC_COMMIT(mbar) \
    asm volatile("tcgen05.commit.cta_group::1.mbarrier::arrive::one.shared::cluster.b64 [%0];" \
        :: "r"((uint32_t)(mbar)) : "memory")
#define TC_FENCE_AFTER() asm volatile("tcgen05.fence::after_thread_sync;" ::: "memory")
#define TC_FENCE_BEFORE() asm volatile("tcgen05.fence::before_thread_sync;" ::: "memory")
#define TC_WAIT_LD() asm volatile("tcgen05.wait::ld.sync.aligned;" ::: "memory")
#define FENCE_ASYNC_SHARED() asm volatile("fence.proxy.async.shared::cta;" ::: "memory")
#define TC_LD_X32(r, tmem_addr) \
    asm volatile("tcgen05.ld.sync.aligned.32x32b.x32.b32 " \
        "{%0, %1, %2, %3, %4, %5, %6, %7, %8, %9, %10, %11, %12, %13, %14, %15, " \
        " %16, %17, %18, %19, %20, %21, %22, %23, %24, %25, %26, %27, %28, %29, %30, %31}, [%32];" \
        : "=r"((r)[0]),  "=r"((r)[1]),  "=r"((r)[2]),  "=r"((r)[3]), \
          "=r"((r)[4]),  "=r"((r)[5]),  "=r"((r)[6]),  "=r"((r)[7]), \
          "=r"((r)[8]),  "=r"((r)[9]),  "=r"((r)[10]), "=r"((r)[11]), \
          "=r"((r)[12]), "=r"((r)[13]), "=r"((r)[14]), "=r"((r)[15]), \
          "=r"((r)[16]), "=r"((r)[17]), "=r"((r)[18]), "=r"((r)[19]), \
          "=r"((r)[20]), "=r"((r)[21]), "=r"((r)[22]), "=r"((r)[23]), \
          "=r"((r)[24]), "=r"((r)[25]), "=r"((r)[26]), "=r"((r)[27]), \
          "=r"((r)[28]), "=r"((r)[29]), "=r"((r)[30]), "=r"((r)[31]) \
        : "r"(tmem_addr))

__device__ __forceinline__ uint64_t mk_desc(uint32_t addr) {
    const uint64_t base = (2ull << 61) | (1ull << 46) | (64ull << 32) | (1ull << 16);
    return base | ((uint64_t)(addr >> 4) & 0x3FFF);
}
__device__ __forceinline__ void mma_f16_ss(uint32_t d, uint64_t da, uint64_t db,
                                           uint32_t idesc, uint32_t en) {
    asm volatile(
        "{\n\t.reg .pred p;\n\tsetp.ne.u32 p, %5, 0;\n\t"
        "tcgen05.mma.cta_group::1.kind::f16 [%0], %1, %2, %3, {%4,%4,%4,%4}, p;\n\t}"
        :: "r"(d), "l"(da), "l"(db), "r"(idesc), "r"(0u), "r"(en) : "memory");
}

#define GM_IDESC 0x8400490u              // F32 acc, bf16 a/b, M=128, N=256

__device__ __forceinline__ void gm_load_chunk(
    char* smem, uint32_t st_off,
    const __nv_bfloat16* __restrict__ Ah, const __nv_bfloat16* __restrict__ Al,
    const __nv_bfloat16* __restrict__ Bh, const __nv_bfloat16* __restrict__ Bl,
    int bm, int bn, int K, int kc, int tid)
{
    if (tid >= 32) {
        int lt = tid - 32;
        for (int v = lt; v < 1024; v += 224) {          // A: 128 rows x 8 vec4
            int r = v >> 3, cv = v & 7;
            uint32_t off = (uint32_t)(r*128 + cv*16);
            uint32_t sw = off ^ ((off >> 3) & 0x70);
            const uint4* pa = (const uint4*)(Ah + (size_t)(bm + r)*K + kc);
            const uint4* pl = (const uint4*)(Al + (size_t)(bm + r)*K + kc);
            *(uint4*)(smem + st_off + sw)         = pa[cv];
            *(uint4*)(smem + st_off + 16384 + sw) = pl[cv];
        }
        for (int v = lt; v < 2048; v += 224) {          // B: 256 rows x 8 vec4
            int r = v >> 3, cv = v & 7;
            uint32_t off = (uint32_t)(r*128 + cv*16);
            uint32_t sw = off ^ ((off >> 3) & 0x70);
            const uint4* pb = (const uint4*)(Bh + (size_t)(bn + r)*K + kc);
            const uint4* pl = (const uint4*)(Bl + (size_t)(bn + r)*K + kc);
            *(uint4*)(smem + st_off + 32768 + sw) = pb[cv];
            *(uint4*)(smem + st_off + 65536 + sw) = pl[cv];
        }
        FENCE_ASYNC_SHARED();
    }
}

__global__ __launch_bounds__(256, 1) void tc_gemm(
    const __nv_bfloat16* __restrict__ Ah, const __nv_bfloat16* __restrict__ Al,
    const __nv_bfloat16* __restrict__ Bh, const __nv_bfloat16* __restrict__ Bl,
    float* __restrict__ C, const float* __restrict__ addend,
    int M, int N, int K)
{
    extern __shared__ char smem[];
    uint32_t sb = smem_u32(smem);
    int tid = threadIdx.x;
    int wid = tid >> 5, lane = tid & 31;
    int bn = blockIdx.x * 256, bm = blockIdx.y * 128;

    if (wid == 0) { TC_ALLOC(sb, 256); TC_RELINQ(); }
    if (tid == 0) { MBAR_INIT(sb + 8, 1); MBAR_INIT(sb + 16, 1); }
    __syncthreads();
    uint32_t tmem;
    asm volatile("ld.shared.b32 %0, [%1];" : "=r"(tmem) : "r"(sb));

    const int NC = K / 64;
    int ph0 = 0, ph1 = 0;

    gm_load_chunk(smem, 1024, Ah, Al, Bh, Bl, bm, bn, K, 0, tid);
    __syncthreads();

    for (int c = 0; c < NC; c++) {
        int s = c & 1;
        uint32_t stb = sb + 1024 + (uint32_t)s * GM_STAGE_BYTES;
        if (wid == 0 && elect_one_pred()) {
            uint64_t dAh = mk_desc(stb);
            uint64_t dAl = mk_desc(stb + 16384);
            uint64_t dBh = mk_desc(stb + 32768);
            uint64_t dBl = mk_desc(stb + 65536);
            #pragma unroll
            for (int k = 0; k < 4; k++)
                mma_f16_ss(tmem, dAh + k*2, dBh + k*2, GM_IDESC, (c > 0) || (k > 0));
            #pragma unroll
            for (int k = 0; k < 4; k++)
                mma_f16_ss(tmem, dAh + k*2, dBl + k*2, GM_IDESC, 1u);
            #pragma unroll
            for (int k = 0; k < 4; k++)
                mma_f16_ss(tmem, dAl + k*2, dBh + k*2, GM_IDESC, 1u);
            TC_COMMIT(sb + 8 + (uint32_t)s * 8);
        }
        if (c + 1 < NC) {
            int s2 = (c + 1) & 1;
            if (c >= 1) {
                if (tid >= 32) {   // loaders must not overwrite until MMA c-1 done
                    if (s2 == 0) { MBAR_WAIT(sb + 8, ph0); }
                    else         { MBAR_WAIT(sb + 16, ph1); }
                }
                if (s2 == 0) ph0 ^= 1; else ph1 ^= 1;
            }
            gm_load_chunk(smem, 1024 + (uint32_t)s2 * GM_STAGE_BYTES,
                          Ah, Al, Bh, Bl, bm, bn, K, (c + 1) * 64, tid);
            __syncthreads();
        }
    }
    int sl = (NC - 1) & 1;
    if (sl == 0) { MBAR_WAIT(sb + 8, ph0); } else { MBAR_WAIT(sb + 16, ph1); }
    TC_FENCE_AFTER();

    // epilogue: 8 warps; wg0 cols 0-127, wg1 cols 128-255; warp%4 -> rows
    int wg = wid >> 2, ws = wid & 3;
    size_t row = (size_t)(bm + ws * 32 + lane);
    #pragma unroll
    for (int cb = 0; cb < 4; cb++) {
        uint32_t regs[32];
        TC_LD_X32(regs, tmem + (uint32_t)(wg * 128 + cb * 32));
        TC_WAIT_LD();
        int col = bn + wg * 128 + cb * 32;
        float* Cp = C + row * (size_t)N + col;
        if (addend) {
            const float* Ap = addend + row * (size_t)N + col;
            #pragma unroll
            for (int j = 0; j < 32; j += 4) {
                float4 a = *(const float4*)(Ap + j);
                float4 o = make_float4(__uint_as_float(regs[j])   + a.x,
                                       __uint_as_float(regs[j+1]) + a.y,
                                       __uint_as_float(regs[j+2]) + a.z,
                                       __uint_as_float(regs[j+3]) + a.w);
                *(float4*)(Cp + j) = o;
            }
        } else {
            #pragma unroll
            for (int j = 0; j < 32; j += 4) {
                float4 o = make_float4(__uint_as_float(regs[j]),
                                       __uint_as_float(regs[j+1]),
                                       __uint_as_float(regs[j+2]),
                                       __uint_as_float(regs[j+3]));
                *(float4*)(Cp + j) = o;
            }
        }
    }
    TC_FENCE_BEFORE();
    __syncthreads();
    if (tid == 0) { MBAR_INVAL(sb + 8); MBAR_INVAL(sb + 16); }
    if (wid == 0) { TC_DEALLOC(tmem, 256); }
}

#else
// ======================= mma.sync fallback (any sm_80+ target) ===============
// Same tile (BM=128, BN=256), split-bf16 3-pass via m16n8k16 HMMA.
__device__ __forceinline__ void mma16816(float* c, const uint32_t* a, const uint32_t* b) {
    asm volatile("mma.sync.aligned.m16n8k16.row.col.f32.bf16.bf16.f32 "
        "{%0,%1,%2,%3}, {%4,%5,%6,%7}, {%8,%9}, {%0,%1,%2,%3};"
        : "+f"(c[0]), "+f"(c[1]), "+f"(c[2]), "+f"(c[3])
        : "r"(a[0]), "r"(a[1]), "r"(a[2]), "r"(a[3]), "r"(b[0]), "r"(b[1]));
}

#define FB_LD 40   // padded bf16 row stride

__global__ __launch_bounds__(256, 1) void tc_gemm(
    const __nv_bfloat16* __restrict__ Ah, const __nv_bfloat16* __restrict__ Al,
    const __nv_bfloat16* __restrict__ Bh, const __nv_bfloat16* __restrict__ Bl,
    float* __restrict__ C, const float* __restrict__ addend,
    int M, int N, int K)
{
    extern __shared__ char smem[];
    __nv_bfloat16* sAh = (__nv_bfloat16*)smem;        // [128][40]
    __nv_bfloat16* sAl = sAh + 128*FB_LD;
    __nv_bfloat16* sBh = sAl + 128*FB_LD;             // [256][40]
    __nv_bfloat16* sBl = sBh + 256*FB_LD;
    int tid = threadIdx.x, lane = tid & 31, wid = tid >> 5;
    int bn = blockIdx.x * 256, bm = blockIdx.y * 128;
    int wm = wid >> 2, wn = wid & 3;        // warp tile: 64m x 64n
    int g = lane >> 2, tig = lane & 3;

    float acc[4][8][4];
    #pragma unroll
    for (int mt = 0; mt < 4; mt++)
        #pragma unroll
        for (int nt = 0; nt < 8; nt++)
            #pragma unroll
            for (int q = 0; q < 4; q++) acc[mt][nt][q] = 0.f;

    for (int k0 = 0; k0 < K; k0 += 32) {
        __syncthreads();
        for (int v = tid; v < 512; v += 256) {        // A hi/lo: 128 rows x 4 uint4
            int r = v >> 2, q = v & 3;
            *(uint4*)&sAh[r*FB_LD + q*8] = *(const uint4*)(Ah + (size_t)(bm+r)*K + k0 + q*8);
            *(uint4*)&sAl[r*FB_LD + q*8] = *(const uint4*)(Al + (size_t)(bm+r)*K + k0 + q*8);
        }
        for (int v = tid; v < 1024; v += 256) {       // B hi/lo: 256 rows x 4 uint4
            int r = v >> 2, q = v & 3;
            *(uint4*)&sBh[r*FB_LD + q*8] = *(const uint4*)(Bh + (size_t)(bn+r)*K + k0 + q*8);
            *(uint4*)&sBl[r*FB_LD + q*8] = *(const uint4*)(Bl + (size_t)(bn+r)*K + k0 + q*8);
        }
        __syncthreads();
        #pragma unroll
        for (int ks = 0; ks < 2; ks++) {
            int kk = ks * 16 + tig * 2;
            uint32_t ah[4][4], al[4][4], bh[8][2], bl[8][2];
            #pragma unroll
            for (int mt = 0; mt < 4; mt++) {
                int mr = (wm*64 + mt*16 + g)*FB_LD + kk;
                ah[mt][0] = *(const uint32_t*)&sAh[mr];
                ah[mt][1] = *(const uint32_t*)&sAh[mr + 8*FB_LD];
                ah[mt][2] = *(const uint32_t*)&sAh[mr + 8];
                ah[mt][3] = *(const uint32_t*)&sAh[mr + 8*FB_LD + 8];
                al[mt][0] = *(const uint32_t*)&sAl[mr];
                al[mt][1] = *(const uint32_t*)&sAl[mr + 8*FB_LD];
                al[mt][2] = *(const uint32_t*)&sAl[mr + 8];
                al[mt][3] = *(const uint32_t*)&sAl[mr + 8*FB_LD + 8];
            }
            #pragma unroll
            for (int nt = 0; nt < 8; nt++) {
                int nr = (wn*64 + nt*8 + g)*FB_LD + kk;
                bh[nt][0] = *(const uint32_t*)&sBh[nr];
                bh[nt][1] = *(const uint32_t*)&sBh[nr + 8];
                bl[nt][0] = *(const uint32_t*)&sBl[nr];
                bl[nt][1] = *(const uint32_t*)&sBl[nr + 8];
            }
            #pragma unroll
            for (int mt = 0; mt < 4; mt++)
                #pragma unroll
                for (int nt = 0; nt < 8; nt++) {
                    mma16816(acc[mt][nt], ah[mt], bh[nt]);
                    mma16816(acc[mt][nt], ah[mt], bl[nt]);
                    mma16816(acc[mt][nt], al[mt], bh[nt]);
                }
        }
    }
    // epilogue
    #pragma unroll
    for (int mt = 0; mt < 4; mt++) {
        #pragma unroll
        for (int nt = 0; nt < 8; nt++) {
            size_t r0 = (size_t)(bm + wm*64 + mt*16 + g);
            int col = bn + wn*64 + nt*8 + tig*2;
            float2 v0 = make_float2(acc[mt][nt][0], acc[mt][nt][1]);
            float2 v1 = make_float2(acc[mt][nt][2], acc[mt][nt][3]);
            if (addend) {
                float2 a0 = *(const float2*)(addend + r0*N + col);
                float2 a1 = *(const float2*)(addend + (r0+8)*N + col);
                v0.x += a0.x; v0.y += a0.y; v1.x += a1.x; v1.y += a1.y;
            }
            *(float2*)(C + r0*N + col)     = v0;
            *(float2*)(C + (r0+8)*N + col) = v1;
        }
    }
}
#endif  // USE_TCGEN05

// ---------------- RMSNorm ----------------------------------------------------
__global__ __launch_bounds__(256) void rmsnorm_kernel(
    const float* __restrict__ x, const float* __restrict__ w,
    float* __restrict__ out)
{
    __shared__ float red[8];
    int row = blockIdx.x;
    int tid = threadIdx.x;
    const float4* xr = (const float4*)(x + (size_t)row * EMBED);
    const float4* w4 = (const float4*)w;
    float4 v0 = xr[tid];
    float4 v1 = xr[tid + 256];
    float ss = v0.x*v0.x + v0.y*v0.y + v0.z*v0.z + v0.w*v0.w
             + v1.x*v1.x + v1.y*v1.y + v1.z*v1.z + v1.w*v1.w;
    #pragma unroll
    for (int o = 16; o > 0; o >>= 1) ss += __shfl_xor_sync(0xffffffffu, ss, o);
    if ((tid & 31) == 0) red[tid >> 5] = ss;
    __syncthreads();
    float tot = red[0] + red[1] + red[2] + red[3] + red[4] + red[5] + red[6] + red[7];
    float inv = rsqrtf(tot * (1.0f / EMBED) + 1e-5f);
    float4 wa = w4[tid], wb = w4[tid + 256];
    float4 o0, o1;
    o0.x = v0.x*inv*wa.x; o0.y = v0.y*inv*wa.y; o0.z = v0.z*inv*wa.z; o0.w = v0.w*inv*wa.w;
    o1.x = v1.x*inv*wb.x; o1.y = v1.y*inv*wb.y; o1.z = v1.z*inv*wb.z; o1.w = v1.w*inv*wb.w;
    float4* orow = (float4*)(out + (size_t)row * EMBED);
    orow[tid] = o0;
    orow[tid + 256] = o1;
}

// ---------------- RoPE + head transpose --------------------------------------
__global__ __launch_bounds__(256) void rope_kernel(
    const float* __restrict__ qkv, const float* __restrict__ freqs,
    float* __restrict__ qt, float* __restrict__ kt, float* __restrict__ vt)
{
    int s = blockIdx.x, b = blockIdx.y, tid = threadIdx.x;
    const float* row = qkv + ((size_t)b * SS + s) * QKV_N;
    const float* f = freqs + (size_t)s * HD;

    for (int p = tid; p < NH * 64; p += 256) {
        int h = p >> 6, i = p & 63;
        float x0 = row[h*HD + 2*i], x1 = row[h*HD + 2*i + 1];
        float c = f[2*i], sn = f[2*i+1];
        float* dst = qt + (((size_t)(b*NH + h) * SS + s) * HD);
        dst[2*i]   = x0*c - x1*sn;
        dst[2*i+1] = x1*c + x0*sn;
    }
    for (int p = tid; p < NKV * 64; p += 256) {
        int h = p >> 6, i = p & 63;
        float x0 = row[NH*HD + h*HD + 2*i], x1 = row[NH*HD + h*HD + 2*i + 1];
        float c = f[2*i], sn = f[2*i+1];
        float* dst = kt + (((size_t)(b*NKV + h) * SS + s) * HD);
        dst[2*i]   = x0*c - x1*sn;
        dst[2*i+1] = x1*c + x0*sn;
    }
    for (int p = tid; p < NKV * HD; p += 256) {
        int h = p >> 7, d = p & 127;
        vt[(((size_t)(b*NKV + h) * SS + s) * HD) + d] = row[(NH + NKV)*HD + p];
    }
}

// ---------------- Flash attention (fp32, causal, GQA 4:1) --------------------
#define FL_SMEM_FLOATS (128*68*2 + 64*128 + 64*68 + 192)
__global__ __launch_bounds__(256) void flash_kernel()
{
    extern __shared__ float sm[];
    float* Qts   = sm;
    float* Kts   = Qts + 128*68;
    float* Vs    = Kts + 128*68;
    float* Sts   = Vs + 64*128;
    float* row_m = Sts + 64*68;
    float* row_l = row_m + 64;
    float* row_sc= row_l + 64;

    int tid = threadIdx.x;
    int qb = blockIdx.x, hb = blockIdx.y, bb = blockIdx.z;
    const float scale = 0.02209708691207961f;

    const float* Qg    = g_qt + (((size_t)(bb*NH + hb) * SS + (size_t)qb*64) * HD);
    const float* Kbase = g_kt + (((size_t)(bb*NKV + (hb >> 2)) * SS) * HD);
    const float* Vbase = g_vt + (((size_t)(bb*NKV + (hb >> 2)) * SS) * HD);

    for (int i = tid; i < 64*32; i += 256) {
        int r = i >> 5, d4 = (i & 31) << 2;
        float4 q4 = *(const float4*)(Qg + r*HD + d4);
        Qts[(d4+0)*68 + r] = q4.x * scale;
        Qts[(d4+1)*68 + r] = q4.y * scale;
        Qts[(d4+2)*68 + r] = q4.z * scale;
        Qts[(d4+3)*68 + r] = q4.w * scale;
    }
    if (tid < 64) { row_m[tid] = -1e30f; row_l[tid] = 0.f; }

    int txq = tid & 15, tyk = tid >> 4;
    int txc = tid & 15, tyr = tid >> 4;
    float acc[4][8];
    #pragma unroll
    for (int i = 0; i < 4; i++)
        #pragma unroll
        for (int j = 0; j < 8; j++) acc[i][j] = 0.f;

    for (int kb = 0; kb <= qb; kb++) {
        __syncthreads();
        const float* Kg = Kbase + (size_t)kb * 64 * HD;
        const float* Vg = Vbase + (size_t)kb * 64 * HD;
        for (int i = tid; i < 64*32; i += 256) {
            int r = i >> 5, d4 = (i & 31) << 2;
            float4 k4 = *(const float4*)(Kg + r*HD + d4);
            Kts[(d4+0)*68 + r] = k4.x;
            Kts[(d4+1)*68 + r] = k4.y;
            Kts[(d4+2)*68 + r] = k4.z;
            Kts[(d4+3)*68 + r] = k4.w;
            *(float4*)&Vs[r*HD + d4] = *(const float4*)(Vg + r*HD + d4);
        }
        __syncthreads();
        float s[4][4];
        #pragma unroll
        for (int i = 0; i < 4; i++)
            #pragma unroll
            for (int j = 0; j < 4; j++) s[i][j] = 0.f;
        #pragma unroll 4
        for (int d = 0; d < 128; d++) {
            float qr[4], kr[4];
            *(float4*)qr = *(const float4*)&Qts[d*68 + txq*4];
            *(float4*)kr = *(const float4*)&Kts[d*68 + tyk*4];
            #pragma unroll
            for (int i = 0; i < 4; i++)
                #pragma unroll
                for (int j = 0; j < 4; j++)
                    s[i][j] += qr[i] * kr[j];
        }
        #pragma unroll
        for (int i = 0; i < 4; i++)
            #pragma unroll
            for (int j = 0; j < 4; j++)
                Sts[(tyk*4 + j)*68 + txq*4 + i] = s[i][j];
        __syncthreads();
        if (tid < 64) {
            int r = tid;
            int valid = (kb == qb) ? (r + 1) : 64;
            float mx = row_m[r];
            for (int kc = 0; kc < valid; kc++) mx = fmaxf(mx, Sts[kc*68 + r]);
            float fac = __expf(row_m[r] - mx);
            float l = row_l[r] * fac;
            for (int kc = 0; kc < 64; kc++) {
                float p = (kc < valid) ? __expf(Sts[kc*68 + r] - mx) : 0.f;
                Sts[kc*68 + r] = p;
                l += p;
            }
            row_m[r] = mx; row_l[r] = l; row_sc[r] = fac;
        }
        __syncthreads();
        float fc[4];
        #pragma unroll
        for (int i = 0; i < 4; i++) fc[i] = row_sc[tyr*4 + i];
        #pragma unroll
        for (int i = 0; i < 4; i++)
            #pragma unroll
            for (int j = 0; j < 8; j++) acc[i][j] *= fc[i];
        #pragma unroll 2
        for (int kk = 0; kk < 64; kk++) {
            float pr[4], vv[8];
            *(float4*)pr     = *(const float4*)&Sts[kk*68 + tyr*4];
            *(float4*)vv     = *(const float4*)&Vs[kk*128 + txc*8];
            *(float4*)(vv+4) = *(const float4*)&Vs[kk*128 + txc*8 + 4];
            #pragma unroll
            for (int i = 0; i < 4; i++)
                #pragma unroll
                for (int j = 0; j < 8; j++)
                    acc[i][j] += pr[i] * vv[j];
        }
    }
    #pragma unroll
    for (int i = 0; i < 4; i++) {
        float inv = 1.f / row_l[tyr*4 + i];
        size_t grow = (size_t)bb * SS + (size_t)qb*64 + tyr*4 + i;
        float* Op = g_attn + grow * EMBED + hb*HD + txc*8;
        float4 o0 = make_float4(acc[i][0]*inv, acc[i][1]*inv, acc[i][2]*inv, acc[i][3]*inv);
        float4 o1 = make_float4(acc[i][4]*inv, acc[i][5]*inv, acc[i][6]*inv, acc[i][7]*inv);
        *(float4*)(Op)     = o0;
        *(float4*)(Op + 4) = o1;
    }
}

// ---------------- SwiGLU elementwise -----------------------------------------
__global__ __launch_bounds__(256) void silu_mul_kernel(
    float* __restrict__ u1, const float* __restrict__ u2, int n4)
{
    int i = blockIdx.x * 256 + threadIdx.x;
    if (i >= n4) return;
    float4 a = ((float4*)u1)[i];
    float4 b = ((const float4*)u2)[i];
    a.x = a.x / (1.f + __expf(-a.x)) * b.x;
    a.y = a.y / (1.f + __expf(-a.y)) * b.y;
    a.z = a.z / (1.f + __expf(-a.z)) * b.z;
    a.w = a.w / (1.f + __expf(-a.w)) * b.w;
    ((float4*)u1)[i] = a;
}

// ---------------- driver ------------------------------------------------------
static inline void split_launch(const float* src, __nv_bfloat16* hi, __nv_bfloat16* lo, size_t n)
{
    int n4 = (int)(n / 4);
    split_kernel<<<(n4 + 255)/256, 256>>>(src, hi, lo, n4);
}

extern "C" void kernel_launch(void* const* d_in, const int* in_sizes, int n_in,
                              void* d_out, int out_size)
{
    const float* x       = (const float*)d_in[0];
    const float* freqs   = (const float*)d_in[2];
    const float* w_qkv   = (const float*)d_in[4];
    const float* w_fc    = (const float*)d_in[5];
    const float* w1      = (const float*)d_in[6];
    const float* w2      = (const float*)d_in[7];
    const float* w3      = (const float*)d_in[8];
    const float* attn_nw = (const float*)d_in[9];
    const float* ff_nw   = (const float*)d_in[10];
    float* out = (float*)d_out;

    float *hnorm, *qkv, *qt, *kt, *vt, *attn, *h1, *u1, *u2;
    __nv_bfloat16 *ah, *al, *wh, *wl;
    cudaGetSymbolAddress((void**)&hnorm, g_hnorm);
    cudaGetSymbolAddress((void**)&qkv,   g_qkv);
    cudaGetSymbolAddress((void**)&qt,    g_qt);
    cudaGetSymbolAddress((void**)&kt,    g_kt);
    cudaGetSymbolAddress((void**)&vt,    g_vt);
    cudaGetSymbolAddress((void**)&attn,  g_attn);
    cudaGetSymbolAddress((void**)&h1,    g_h1);
    cudaGetSymbolAddress((void**)&u1,    g_u1);
    cudaGetSymbolAddress((void**)&u2,    g_u2);
    cudaGetSymbolAddress((void**)&ah,    g_ah);
    cudaGetSymbolAddress((void**)&al,    g_al);
    cudaGetSymbolAddress((void**)&wh,    g_wh);
    cudaGetSymbolAddress((void**)&wl,    g_wl);

    cudaFuncSetAttribute(tc_gemm, cudaFuncAttributeMaxDynamicSharedMemorySize, GM_SMEM_BYTES);

    // 1. attn rmsnorm
    rmsnorm_kernel<<<ROWS, 256>>>(x, attn_nw, hnorm);
    // 2. qkv projection
    split_launch(hnorm, ah, al, (size_t)ROWS*EMBED);
    split_launch(w_qkv, wh, wl, (size_t)QKV_N*EMBED);
    tc_gemm<<<dim3(QKV_N/256, ROWS/128), 256, GM_SMEM_BYTES>>>(
        ah, al, wh, wl, qkv, nullptr, ROWS, QKV_N, EMBED);
    // 3. rope + transpose
    rope_kernel<<<dim3(SS, BB), 256>>>(qkv, freqs, qt, kt, vt);
    // 4. flash attention
    const int fl_bytes = FL_SMEM_FLOATS * 4;
    cudaFuncSetAttribute(flash_kernel, cudaFuncAttributeMaxDynamicSharedMemorySize, fl_bytes);
    flash_kernel<<<dim3(SS/64, NH, BB), 256, fl_bytes>>>();
    // 5. output projection + residual
    split_launch(attn, ah, al, (size_t)ROWS*EMBED);
    split_launch(w_fc, wh, wl, (size_t)EMBED*EMBED);
    tc_gemm<<<dim3(EMBED/256, ROWS/128), 256, GM_SMEM_BYTES>>>(
        ah, al, wh, wl, h1, x, ROWS, EMBED, EMBED);
    // 6. ffn rmsnorm
    rmsnorm_kernel<<<ROWS, 256>>>(h1, ff_nw, hnorm);
    // 7-8. gate / up projections
    split_launch(hnorm, ah, al, (size_t)ROWS*EMBED);
    split_launch(w1, wh, wl, (size_t)FF*EMBED);
    tc_gemm<<<dim3(FF/256, ROWS/128), 256, GM_SMEM_BYTES>>>(
        ah, al, wh, wl, u1, nullptr, ROWS, FF, EMBED);
    split_launch(w2, wh, wl, (size_t)FF*EMBED);
    tc_gemm<<<dim3(FF/256, ROWS/128), 256, GM_SMEM_BYTES>>>(
        ah, al, wh, wl, u2, nullptr, ROWS, FF, EMBED);
    // 9. swiglu
    silu_mul_kernel<<<(ROWS*FF/4 + 255)/256, 256>>>(u1, u2, ROWS*FF/4);
    // 10. down projection + residual -> out
    split_launch(u1, ah, al, (size_t)ROWS*FF);
    split_launch(w3, wh, wl, (size_t)EMBED*FF);
    tc_gemm<<<dim3(EMBED/256, ROWS/128), 256, GM_SMEM_BYTES>>>(
        ah, al, wh, wl, out, h1, ROWS, EMBED, FF);
}

// round 4
// speedup vs baseline: 5.5809x; 1.6333x over previous
#include <cuda_runtime.h>
#include <cuda_bf16.h>
#include <math.h>
#include <stdint.h>

#define EMBED 2048
#define NH 16
#define NKV 4
#define HD 128
#define FF 5632
#define BB 2
#define SS 2048
#define ROWS (BB*SS)                 // 4096 tokens
#define QKV_N ((NH + 2*NKV)*HD)      // 3072

#if defined(__CUDA_ARCH_FEAT_SM103_ALL) || defined(__CUDA_ARCH_FEAT_SM100_ALL)
#define USE_TCGEN05 1
#else
#define USE_TCGEN05 0
#endif

// ---------------- scratch (device globals; no allocations allowed) ----------
__device__ float g_qkv [ROWS*QKV_N];
__device__ float g_qt  [BB*NH *SS*HD];
__device__ float g_kt  [BB*NKV*SS*HD];
__device__ float g_vt  [BB*NKV*SS*HD];
__device__ float g_h1  [ROWS*EMBED];
__device__ float g_u1  [ROWS*FF];
__device__ float g_u2  [ROWS*FF];
// bf16 split buffers (hi/lo) for activations and weights
__device__ __nv_bfloat16 g_ah[ROWS*FF];
__device__ __nv_bfloat16 g_al[ROWS*FF];
__device__ __nv_bfloat16 g_wh[FF*EMBED];
__device__ __nv_bfloat16 g_wl[FF*EMBED];

// GEMM launch config shared by both paths: BM=128, BN=256
#define GM_STAGE_BYTES 98304
#define GM_SMEM_BYTES (1024 + 2*GM_STAGE_BYTES)

__device__ __forceinline__ void split2(float f, __nv_bfloat16& h, __nv_bfloat16& l) {
    h = __float2bfloat16(f);
    l = __float2bfloat16(f - __bfloat162float(h));
}

// ======================= split fp32 -> bf16 hi/lo (weights) ==================
__global__ __launch_bounds__(256) void split_kernel(
    const float* __restrict__ x, __nv_bfloat16* __restrict__ hi,
    __nv_bfloat16* __restrict__ lo, int n4)
{
    int i = blockIdx.x * 256 + threadIdx.x;
    if (i >= n4) return;
    float4 v = ((const float4*)x)[i];
    __nv_bfloat16 h0, h1, h2, h3, l0, l1, l2, l3;
    split2(v.x, h0, l0); split2(v.y, h1, l1);
    split2(v.z, h2, l2); split2(v.w, h3, l3);
    __nv_bfloat162* H = (__nv_bfloat162*)hi;
    __nv_bfloat162* L = (__nv_bfloat162*)lo;
    H[2*i]   = __nv_bfloat162(h0, h1);
    H[2*i+1] = __nv_bfloat162(h2, h3);
    L[2*i]   = __nv_bfloat162(l0, l1);
    L[2*i+1] = __nv_bfloat162(l2, l3);
}

#if USE_TCGEN05
// ======================= tcgen05 path (sm_103a pass only) ====================
__device__ __forceinline__ uint32_t elect_one_pred() {
    uint32_t pred;
    asm volatile(
        "{\n\t.reg .pred p;\n\telect.sync _|p, 0xFFFFFFFF;\n\tselp.b32 %0, 1, 0, p;\n\t}"
        : "=r"(pred));
    return pred;
}
__device__ __forceinline__ uint32_t smem_u32(const void* p) {
    uint32_t a;
    asm("{ .reg .u64 t; cvta.to.shared.u64 t, %1; cvt.u32.u64 %0, t; }" : "=r"(a) : "l"(p));
    return a;
}
#define MBAR_INIT(addr, cnt) \
    asm volatile("mbarrier.init.shared.b64 [%0], %1;" :: "r"(addr), "r"((uint32_t)(cnt)) : "memory")
#define MBAR_INVAL(addr) \
    asm volatile("mbarrier.inval.shared.b64 [%0];" :: "r"(addr) : "memory")
#define MBAR_WAIT(addr, parity) do { \
    uint32_t _m = (addr); uint32_t _p = (parity); uint32_t _d; \
    asm volatile("{\n\t.reg .pred p;\n\tmbarrier.try_wait.parity.acquire.cta.shared::cta.b64 p, [%1], %2;\n\tselp.b32 %0, 1, 0, p;\n\t}" \
        : "=r"(_d) : "r"(_m), "r"(_p) : "memory"); \
    if (!_d) { \
        asm volatile("{\n\t.reg .pred P1;\n\tWL_%=:\n\tmbarrier.try_wait.parity.acquire.cta.shared::cta.b64 P1, [%0], %1, 0x989680;\n\t@P1 bra.uni WD_%=;\n\tbra.uni WL_%=;\n\tWD_%=:\n\t}" \
            :: "r"(_m), "r"(_p) : "memory"); \
    } } while(0)
#define TC_ALLOC(smem_addr, n) \
    asm volatile("tcgen05.alloc.cta_group::1.sync.aligned.shared::cta.b32 [%0], %1;" \
        :: "r"((uint32_t)(smem_addr)), "r"((uint32_t)(n)) : "memory")
#define TC_DEALLOC(tmem_addr, n) \
    asm volatile("tcgen05.dealloc.cta_group::1.sync.aligned.b32 %0, %1;" :: "r"(tmem_addr), "r"((uint32_t)(n)))
#define TC_RELINQ() \
    asm volatile("tcgen05.relinquish_alloc_permit.cta_group::1.sync.aligned;")
#define TC_COMMIT(mbar) \
    asm volatile("tcgen05.commit.cta_group::1.mbarrier::arrive::one.shared::cluster.b64 [%0];" \
        :: "r"((uint32_t)(mbar)) : "memory")
#define TC_FENCE_AFTER() asm volatile("tcgen05.fence::after_thread_sync;" ::: "memory")
#define TC_FENCE_BEFORE() asm volatile("tcgen05.fence::before_thread_sync;" ::: "memory")
#define TC_WAIT_LD() asm volatile("tcgen05.wait::ld.sync.aligned;" ::: "memory")
#define FENCE_ASYNC_SHARED() asm volatile("fence.proxy.async.shared::cta;" ::: "memory")
#define CP_COMMIT() asm volatile("cp.async.commit_group;" ::: "memory")
#define CP_WAIT0()  asm volatile("cp.async.wait_group 0;" ::: "memory")
#define TC_LD_X32(r, tmem_addr) \
    asm volatile("tcgen05.ld.sync.aligned.32x32b.x32.b32 " \
        "{%0, %1, %2, %3, %4, %5, %6, %7, %8, %9, %10, %11, %12, %13, %14, %15, " \
        " %16, %17, %18, %19, %20, %21, %22, %23, %24, %25, %26, %27, %28, %29, %30, %31}, [%32];" \
        : "=r"((r)[0]),  "=r"((r)[1]),  "=r"((r)[2]),  "=r"((r)[3]), \
          "=r"((r)[4]),  "=r"((r)[5]),  "=r"((r)[6]),  "=r"((r)[7]), \
          "=r"((r)[8]),  "=r"((r)[9]),  "=r"((r)[10]), "=r"((r)[11]), \
          "=r"((r)[12]), "=r"((r)[13]), "=r"((r)[14]), "=r"((r)[15]), \
          "=r"((r)[16]), "=r"((r)[17]), "=r"((r)[18]), "=r"((r)[19]), \
          "=r"((r)[20]), "=r"((r)[21]), "=r"((r)[22]), "=r"((r)[23]), \
          "=r"((r)[24]), "=r"((r)[25]), "=r"((r)[26]), "=r"((r)[27]), \
          "=r"((r)[28]), "=r"((r)[29]), "=r"((r)[30]), "=r"((r)[31]) \
        : "r"(tmem_addr))

__device__ __forceinline__ uint64_t mk_desc(uint32_t addr) {
    const uint64_t base = (2ull << 61) | (1ull << 46) | (64ull << 32) | (1ull << 16);
    return base | ((uint64_t)(addr >> 4) & 0x3FFF);
}
__device__ __forceinline__ void mma_f16_ss(uint32_t d, uint64_t da, uint64_t db,
                                           uint32_t idesc, uint32_t en) {
    asm volatile(
        "{\n\t.reg .pred p;\n\tsetp.ne.u32 p, %5, 0;\n\t"
        "tcgen05.mma.cta_group::1.kind::f16 [%0], %1, %2, %3, {%4,%4,%4,%4}, p;\n\t}"
        :: "r"(d), "l"(da), "l"(db), "r"(idesc), "r"(0u), "r"(en) : "memory");
}

#define GM_IDESC 0x8400490u              // F32 acc, bf16 a/b, M=128, N=256

__device__ __forceinline__ void cpa16(uint32_t saddr, const void* g) {
    asm volatile("cp.async.cg.shared.global [%0], [%1], 16;" :: "r"(saddr), "l"(g) : "memory");
}

// async-load one 64-K-column stage (Ah/Al 16KB each, Bh/Bl 32KB each)
__device__ __forceinline__ void gm_load_stage(
    uint32_t stb,
    const __nv_bfloat16* __restrict__ Ah, const __nv_bfloat16* __restrict__ Al,
    const __nv_bfloat16* __restrict__ Bh, const __nv_bfloat16* __restrict__ Bl,
    int bm, int bn, int K, int kc, int tid)
{
    #pragma unroll
    for (int it = 0; it < 4; it++) {                 // A: 128 rows x 8 vec8
        int v = tid + it * 256;
        int r = v >> 3, cv = v & 7;
        uint32_t off = (uint32_t)(r*128 + cv*16);
        uint32_t sw = off ^ ((off >> 3) & 0x70);
        size_t go = (size_t)(bm + r) * K + kc + cv*8;
        cpa16(stb + sw,         Ah + go);
        cpa16(stb + 16384 + sw, Al + go);
    }
    #pragma unroll
    for (int it = 0; it < 8; it++) {                 // B: 256 rows x 8 vec8
        int v = tid + it * 256;
        int r = v >> 3, cv = v & 7;
        uint32_t off = (uint32_t)(r*128 + cv*16);
        uint32_t sw = off ^ ((off >> 3) & 0x70);
        size_t go = (size_t)(bn + r) * K + kc + cv*8;
        cpa16(stb + 32768 + sw, Bh + go);
        cpa16(stb + 65536 + sw, Bl + go);
    }
    CP_COMMIT();
}

__global__ __launch_bounds__(256, 1) void tc_gemm(
    const __nv_bfloat16* __restrict__ Ah, const __nv_bfloat16* __restrict__ Al,
    const __nv_bfloat16* __restrict__ Bh, const __nv_bfloat16* __restrict__ Bl,
    float* __restrict__ C, const float* __restrict__ addend,
    int M, int N, int K)
{
    extern __shared__ char smem[];
    uint32_t sb = smem_u32(smem);
    int tid = threadIdx.x;
    int wid = tid >> 5, lane = tid & 31;
    int bn = blockIdx.x * 256, bm = blockIdx.y * 128;

    if (wid == 0) { TC_ALLOC(sb, 256); TC_RELINQ(); }
    if (tid == 0) { MBAR_INIT(sb + 8, 1); MBAR_INIT(sb + 16, 1); }
    __syncthreads();
    uint32_t tmem;
    asm volatile("ld.shared.b32 %0, [%1];" : "=r"(tmem) : "r"(sb));

    const int NC = K / 64;
    int ph0 = 0, ph1 = 0;

    gm_load_stage(sb + 1024, Ah, Al, Bh, Bl, bm, bn, K, 0, tid);

    for (int c = 0; c < NC; c++) {
        int s = c & 1;
        CP_WAIT0();
        __syncthreads();
        uint32_t stb = sb + 1024 + (uint32_t)s * GM_STAGE_BYTES;
        if (wid == 0 && elect_one_pred()) {
            FENCE_ASYNC_SHARED();
            uint64_t dAh = mk_desc(stb);
            uint64_t dAl = mk_desc(stb + 16384);
            uint64_t dBh = mk_desc(stb + 32768);
            uint64_t dBl = mk_desc(stb + 65536);
            #pragma unroll
            for (int k = 0; k < 4; k++)
                mma_f16_ss(tmem, dAh + k*2, dBh + k*2, GM_IDESC, (c > 0) || (k > 0));
            #pragma unroll
            for (int k = 0; k < 4; k++)
                mma_f16_ss(tmem, dAh + k*2, dBl + k*2, GM_IDESC, 1u);
            #pragma unroll
            for (int k = 0; k < 4; k++)
                mma_f16_ss(tmem, dAl + k*2, dBh + k*2, GM_IDESC, 1u);
            TC_COMMIT(sb + 8 + (uint32_t)s * 8);
        }
        if (c + 1 < NC) {
            int s2 = (c + 1) & 1;
            if (c >= 1) {    // MMA of chunk c-1 (stage s2) must finish first
                if (s2 == 0) { MBAR_WAIT(sb + 8, ph0);  ph0 ^= 1; }
                else         { MBAR_WAIT(sb + 16, ph1); ph1 ^= 1; }
            }
            gm_load_stage(sb + 1024 + (uint32_t)s2 * GM_STAGE_BYTES,
                          Ah, Al, Bh, Bl, bm, bn, K, (c + 1) * 64, tid);
        }
    }
    int sl = (NC - 1) & 1;
    if (sl == 0) { MBAR_WAIT(sb + 8, ph0); } else { MBAR_WAIT(sb + 16, ph1); }
    TC_FENCE_AFTER();

    // epilogue: 8 warps; wg0 cols 0-127, wg1 cols 128-255; warp%4 -> rows
    int wg = wid >> 2, ws = wid & 3;
    size_t row = (size_t)(bm + ws * 32 + lane);
    #pragma unroll
    for (int cb = 0; cb < 4; cb++) {
        uint32_t regs[32];
        TC_LD_X32(regs, tmem + (uint32_t)(wg * 128 + cb * 32));
        TC_WAIT_LD();
        int col = bn + wg * 128 + cb * 32;
        float* Cp = C + row * (size_t)N + col;
        if (addend) {
            const float* Ap = addend + row * (size_t)N + col;
            #pragma unroll
            for (int j = 0; j < 32; j += 4) {
                float4 a = *(const float4*)(Ap + j);
                float4 o = make_float4(__uint_as_float(regs[j])   + a.x,
                                       __uint_as_float(regs[j+1]) + a.y,
                                       __uint_as_float(regs[j+2]) + a.z,
                                       __uint_as_float(regs[j+3]) + a.w);
                *(float4*)(Cp + j) = o;
            }
        } else {
            #pragma unroll
            for (int j = 0; j < 32; j += 4) {
                float4 o = make_float4(__uint_as_float(regs[j]),
                                       __uint_as_float(regs[j+1]),
                                       __uint_as_float(regs[j+2]),
                                       __uint_as_float(regs[j+3]));
                *(float4*)(Cp + j) = o;
            }
        }
    }
    TC_FENCE_BEFORE();
    __syncthreads();
    if (tid == 0) { MBAR_INVAL(sb + 8); MBAR_INVAL(sb + 16); }
    if (wid == 0) { TC_DEALLOC(tmem, 256); }
}

#else
// ======================= mma.sync fallback (any sm_80+ target) ===============
__device__ __forceinline__ void mma16816(float* c, const uint32_t* a, const uint32_t* b) {
    asm volatile("mma.sync.aligned.m16n8k16.row.col.f32.bf16.bf16.f32 "
        "{%0,%1,%2,%3}, {%4,%5,%6,%7}, {%8,%9}, {%0,%1,%2,%3};"
        : "+f"(c[0]), "+f"(c[1]), "+f"(c[2]), "+f"(c[3])
        : "r"(a[0]), "r"(a[1]), "r"(a[2]), "r"(a[3]), "r"(b[0]), "r"(b[1]));
}

#define FB_LD 40   // padded bf16 row stride

__global__ __launch_bounds__(256, 1) void tc_gemm(
    const __nv_bfloat16* __restrict__ Ah, const __nv_bfloat16* __restrict__ Al,
    const __nv_bfloat16* __restrict__ Bh, const __nv_bfloat16* __restrict__ Bl,
    float* __restrict__ C, const float* __restrict__ addend,
    int M, int N, int K)
{
    extern __shared__ char smem[];
    __nv_bfloat16* sAh = (__nv_bfloat16*)smem;        // [128][40]
    __nv_bfloat16* sAl = sAh + 128*FB_LD;
    __nv_bfloat16* sBh = sAl + 128*FB_LD;             // [256][40]
    __nv_bfloat16* sBl = sBh + 256*FB_LD;
    int tid = threadIdx.x, lane = tid & 31, wid = tid >> 5;
    int bn = blockIdx.x * 256, bm = blockIdx.y * 128;
    int wm = wid >> 2, wn = wid & 3;        // warp tile: 64m x 64n
    int g = lane >> 2, tig = lane & 3;

    float acc[4][8][4];
    #pragma unroll
    for (int mt = 0; mt < 4; mt++)
        #pragma unroll
        for (int nt = 0; nt < 8; nt++)
            #pragma unroll
            for (int q = 0; q < 4; q++) acc[mt][nt][q] = 0.f;

    for (int k0 = 0; k0 < K; k0 += 32) {
        __syncthreads();
        for (int v = tid; v < 512; v += 256) {
            int r = v >> 2, q = v & 3;
            *(uint4*)&sAh[r*FB_LD + q*8] = *(const uint4*)(Ah + (size_t)(bm+r)*K + k0 + q*8);
            *(uint4*)&sAl[r*FB_LD + q*8] = *(const uint4*)(Al + (size_t)(bm+r)*K + k0 + q*8);
        }
        for (int v = tid; v < 1024; v += 256) {
            int r = v >> 2, q = v & 3;
            *(uint4*)&sBh[r*FB_LD + q*8] = *(const uint4*)(Bh + (size_t)(bn+r)*K + k0 + q*8);
            *(uint4*)&sBl[r*FB_LD + q*8] = *(const uint4*)(Bl + (size_t)(bn+r)*K + k0 + q*8);
        }
        __syncthreads();
        #pragma unroll
        for (int ks = 0; ks < 2; ks++) {
            int kk = ks * 16 + tig * 2;
            uint32_t ah[4][4], al[4][4], bh[8][2], bl[8][2];
            #pragma unroll
            for (int mt = 0; mt < 4; mt++) {
                int mr = (wm*64 + mt*16 + g)*FB_LD + kk;
                ah[mt][0] = *(const uint32_t*)&sAh[mr];
                ah[mt][1] = *(const uint32_t*)&sAh[mr + 8*FB_LD];
                ah[mt][2] = *(const uint32_t*)&sAh[mr + 8];
                ah[mt][3] = *(const uint32_t*)&sAh[mr + 8*FB_LD + 8];
                al[mt][0] = *(const uint32_t*)&sAl[mr];
                al[mt][1] = *(const uint32_t*)&sAl[mr + 8*FB_LD];
                al[mt][2] = *(const uint32_t*)&sAl[mr + 8];
                al[mt][3] = *(const uint32_t*)&sAl[mr + 8*FB_LD + 8];
            }
            #pragma unroll
            for (int nt = 0; nt < 8; nt++) {
                int nr = (wn*64 + nt*8 + g)*FB_LD + kk;
                bh[nt][0] = *(const uint32_t*)&sBh[nr];
                bh[nt][1] = *(const uint32_t*)&sBh[nr + 8];
                bl[nt][0] = *(const uint32_t*)&sBl[nr];
                bl[nt][1] = *(const uint32_t*)&sBl[nr + 8];
            }
            #pragma unroll
            for (int mt = 0; mt < 4; mt++)
                #pragma unroll
                for (int nt = 0; nt < 8; nt++) {
                    mma16816(acc[mt][nt], ah[mt], bh[nt]);
                    mma16816(acc[mt][nt], ah[mt], bl[nt]);
                    mma16816(acc[mt][nt], al[mt], bh[nt]);
                }
        }
    }
    #pragma unroll
    for (int mt = 0; mt < 4; mt++) {
        #pragma unroll
        for (int nt = 0; nt < 8; nt++) {
            size_t r0 = (size_t)(bm + wm*64 + mt*16 + g);
            int col = bn + wn*64 + nt*8 + tig*2;
            float2 v0 = make_float2(acc[mt][nt][0], acc[mt][nt][1]);
            float2 v1 = make_float2(acc[mt][nt][2], acc[mt][nt][3]);
            if (addend) {
                float2 a0 = *(const float2*)(addend + r0*N + col);
                float2 a1 = *(const float2*)(addend + (r0+8)*N + col);
                v0.x += a0.x; v0.y += a0.y; v1.x += a1.x; v1.y += a1.y;
            }
            *(float2*)(C + r0*N + col)     = v0;
            *(float2*)(C + (r0+8)*N + col) = v1;
        }
    }
}
#endif  // USE_TCGEN05

// ---------------- RMSNorm -> bf16 hi/lo --------------------------------------
__global__ __launch_bounds__(256) void rmsnorm_split_kernel(
    const float* __restrict__ x, const float* __restrict__ w,
    __nv_bfloat16* __restrict__ hi, __nv_bfloat16* __restrict__ lo)
{
    __shared__ float red[8];
    int row = blockIdx.x;
    int tid = threadIdx.x;
    const float4* xr = (const float4*)(x + (size_t)row * EMBED);
    const float4* w4 = (const float4*)w;
    float4 v0 = xr[tid];
    float4 v1 = xr[tid + 256];
    float ss = v0.x*v0.x + v0.y*v0.y + v0.z*v0.z + v0.w*v0.w
             + v1.x*v1.x + v1.y*v1.y + v1.z*v1.z + v1.w*v1.w;
    #pragma unroll
    for (int o = 16; o > 0; o >>= 1) ss += __shfl_xor_sync(0xffffffffu, ss, o);
    if ((tid & 31) == 0) red[tid >> 5] = ss;
    __syncthreads();
    float tot = red[0] + red[1] + red[2] + red[3] + red[4] + red[5] + red[6] + red[7];
    float inv = rsqrtf(tot * (1.0f / EMBED) + 1e-5f);
    float4 wa = w4[tid], wb = w4[tid + 256];
    float o0[4] = {v0.x*inv*wa.x, v0.y*inv*wa.y, v0.z*inv*wa.z, v0.w*inv*wa.w};
    float o1[4] = {v1.x*inv*wb.x, v1.y*inv*wb.y, v1.z*inv*wb.z, v1.w*inv*wb.w};
    __nv_bfloat16 h[4], l[4];
    __nv_bfloat162* H = (__nv_bfloat162*)(hi + (size_t)row * EMBED);
    __nv_bfloat162* L = (__nv_bfloat162*)(lo + (size_t)row * EMBED);
    #pragma unroll
    for (int j = 0; j < 4; j++) split2(o0[j], h[j], l[j]);
    H[2*tid]   = __nv_bfloat162(h[0], h[1]);  H[2*tid+1] = __nv_bfloat162(h[2], h[3]);
    L[2*tid]   = __nv_bfloat162(l[0], l[1]);  L[2*tid+1] = __nv_bfloat162(l[2], l[3]);
    #pragma unroll
    for (int j = 0; j < 4; j++) split2(o1[j], h[j], l[j]);
    H[2*(tid+256)]   = __nv_bfloat162(h[0], h[1]);  H[2*(tid+256)+1] = __nv_bfloat162(h[2], h[3]);
    L[2*(tid+256)]   = __nv_bfloat162(l[0], l[1]);  L[2*(tid+256)+1] = __nv_bfloat162(l[2], l[3]);
}

// ---------------- RoPE + head transpose --------------------------------------
__global__ __launch_bounds__(256) void rope_kernel(
    const float* __restrict__ qkv, const float* __restrict__ freqs,
    float* __restrict__ qt, float* __restrict__ kt, float* __restrict__ vt)
{
    int s = blockIdx.x, b = blockIdx.y, tid = threadIdx.x;
    const float* row = qkv + ((size_t)b * SS + s) * QKV_N;
    const float* f = freqs + (size_t)s * HD;

    for (int p = tid; p < NH * 64; p += 256) {
        int h = p >> 6, i = p & 63;
        float x0 = row[h*HD + 2*i], x1 = row[h*HD + 2*i + 1];
        float c = f[2*i], sn = f[2*i+1];
        float* dst = qt + (((size_t)(b*NH + h) * SS + s) * HD);
        dst[2*i]   = x0*c - x1*sn;
        dst[2*i+1] = x1*c + x0*sn;
    }
    for (int p = tid; p < NKV * 64; p += 256) {
        int h = p >> 6, i = p & 63;
        float x0 = row[NH*HD + h*HD + 2*i], x1 = row[NH*HD + h*HD + 2*i + 1];
        float c = f[2*i], sn = f[2*i+1];
        float* dst = kt + (((size_t)(b*NKV + h) * SS + s) * HD);
        dst[2*i]   = x0*c - x1*sn;
        dst[2*i+1] = x1*c + x0*sn;
    }
    for (int p = tid; p < NKV * HD; p += 256) {
        int h = p >> 7, d = p & 127;
        vt[(((size_t)(b*NKV + h) * SS + s) * HD) + d] = row[(NH + NKV)*HD + p];
    }
}

// ---------------- Flash attention (fp32, causal, GQA 4:1) --------------------
// Writes attn output directly as bf16 hi/lo into g_ah/g_al.
#define FL_SMEM_FLOATS (128*68*2 + 64*128 + 64*68 + 192)
__global__ __launch_bounds__(256) void flash_kernel()
{
    extern __shared__ float sm[];
    float* Qts   = sm;
    float* Kts   = Qts + 128*68;
    float* Vs    = Kts + 128*68;
    float* Sts   = Vs + 64*128;
    float* row_m = Sts + 64*68;
    float* row_l = row_m + 64;
    float* row_sc= row_l + 64;

    int tid = threadIdx.x;
    int qb = blockIdx.x, hb = blockIdx.y, bb = blockIdx.z;
    const float scale = 0.02209708691207961f;

    const float* Qg    = g_qt + (((size_t)(bb*NH + hb) * SS + (size_t)qb*64) * HD);
    const float* Kbase = g_kt + (((size_t)(bb*NKV + (hb >> 2)) * SS) * HD);
    const float* Vbase = g_vt + (((size_t)(bb*NKV + (hb >> 2)) * SS) * HD);

    for (int i = tid; i < 64*32; i += 256) {
        int r = i >> 5, d4 = (i & 31) << 2;
        float4 q4 = *(const float4*)(Qg + r*HD + d4);
        Qts[(d4+0)*68 + r] = q4.x * scale;
        Qts[(d4+1)*68 + r] = q4.y * scale;
        Qts[(d4+2)*68 + r] = q4.z * scale;
        Qts[(d4+3)*68 + r] = q4.w * scale;
    }
    if (tid < 64) { row_m[tid] = -1e30f; row_l[tid] = 0.f; }

    int txq = tid & 15, tyk = tid >> 4;
    int txc = tid & 15, tyr = tid >> 4;
    float acc[4][8];
    #pragma unroll
    for (int i = 0; i < 4; i++)
        #pragma unroll
        for (int j = 0; j < 8; j++) acc[i][j] = 0.f;

    for (int kb = 0; kb <= qb; kb++) {
        __syncthreads();
        const float* Kg = Kbase + (size_t)kb * 64 * HD;
        const float* Vg = Vbase + (size_t)kb * 64 * HD;
        for (int i = tid; i < 64*32; i += 256) {
            int r = i >> 5, d4 = (i & 31) << 2;
            float4 k4 = *(const float4*)(Kg + r*HD + d4);
            Kts[(d4+0)*68 + r] = k4.x;
            Kts[(d4+1)*68 + r] = k4.y;
            Kts[(d4+2)*68 + r] = k4.z;
            Kts[(d4+3)*68 + r] = k4.w;
            *(float4*)&Vs[r*HD + d4] = *(const float4*)(Vg + r*HD + d4);
        }
        __syncthreads();
        float s[4][4];
        #pragma unroll
        for (int i = 0; i < 4; i++)
            #pragma unroll
            for (int j = 0; j < 4; j++) s[i][j] = 0.f;
        #pragma unroll 4
        for (int d = 0; d < 128; d++) {
            float qr[4], kr[4];
            *(float4*)qr = *(const float4*)&Qts[d*68 + txq*4];
            *(float4*)kr = *(const float4*)&Kts[d*68 + tyk*4];
            #pragma unroll
            for (int i = 0; i < 4; i++)
                #pragma unroll
                for (int j = 0; j < 4; j++)
                    s[i][j] += qr[i] * kr[j];
        }
        #pragma unroll
        for (int i = 0; i < 4; i++)
            #pragma unroll
            for (int j = 0; j < 4; j++)
                Sts[(tyk*4 + j)*68 + txq*4 + i] = s[i][j];
        __syncthreads();
        if (tid < 64) {
            int r = tid;
            int valid = (kb == qb) ? (r + 1) : 64;
            float mx = row_m[r];
            for (int kc = 0; kc < valid; kc++) mx = fmaxf(mx, Sts[kc*68 + r]);
            float fac = __expf(row_m[r] - mx);
            float l = row_l[r] * fac;
            for (int kc = 0; kc < 64; kc++) {
                float p = (kc < valid) ? __expf(Sts[kc*68 + r] - mx) : 0.f;
                Sts[kc*68 + r] = p;
                l += p;
            }
            row_m[r] = mx; row_l[r] = l; row_sc[r] = fac;
        }
        __syncthreads();
        float fc[4];
        #pragma unroll
        for (int i = 0; i < 4; i++) fc[i] = row_sc[tyr*4 + i];
        #pragma unroll
        for (int i = 0; i < 4; i++)
            #pragma unroll
            for (int j = 0; j < 8; j++) acc[i][j] *= fc[i];
        #pragma unroll 2
        for (int kk = 0; kk < 64; kk++) {
            float pr[4], vv[8];
            *(float4*)pr     = *(const float4*)&Sts[kk*68 + tyr*4];
            *(float4*)vv     = *(const float4*)&Vs[kk*128 + txc*8];
            *(float4*)(vv+4) = *(const float4*)&Vs[kk*128 + txc*8 + 4];
            #pragma unroll
            for (int i = 0; i < 4; i++)
                #pragma unroll
                for (int j = 0; j < 8; j++)
                    acc[i][j] += pr[i] * vv[j];
        }
    }
    #pragma unroll
    for (int i = 0; i < 4; i++) {
        float inv = 1.f / row_l[tyr*4 + i];
        size_t grow = (size_t)bb * SS + (size_t)qb*64 + tyr*4 + i;
        size_t base = grow * EMBED + hb*HD + txc*8;
        __nv_bfloat16 h[8], l[8];
        #pragma unroll
        for (int j = 0; j < 8; j++) split2(acc[i][j] * inv, h[j], l[j]);
        __nv_bfloat162 hp[4] = {{h[0],h[1]},{h[2],h[3]},{h[4],h[5]},{h[6],h[7]}};
        __nv_bfloat162 lp[4] = {{l[0],l[1]},{l[2],l[3]},{l[4],l[5]},{l[6],l[7]}};
        *(uint4*)(g_ah + base) = *(uint4*)hp;
        *(uint4*)(g_al + base) = *(uint4*)lp;
    }
}

// ---------------- SwiGLU -> bf16 hi/lo ---------------------------------------
__global__ __launch_bounds__(256) void silu_split_kernel(
    const float* __restrict__ u1, const float* __restrict__ u2,
    __nv_bfloat16* __restrict__ hi, __nv_bfloat16* __restrict__ lo, int n4)
{
    int i = blockIdx.x * 256 + threadIdx.x;
    if (i >= n4) return;
    float4 a = ((const float4*)u1)[i];
    float4 b = ((const float4*)u2)[i];
    float r0 = a.x / (1.f + __expf(-a.x)) * b.x;
    float r1 = a.y / (1.f + __expf(-a.y)) * b.y;
    float r2 = a.z / (1.f + __expf(-a.z)) * b.z;
    float r3 = a.w / (1.f + __expf(-a.w)) * b.w;
    __nv_bfloat16 h0, h1, h2, h3, l0, l1, l2, l3;
    split2(r0, h0, l0); split2(r1, h1, l1); split2(r2, h2, l2); split2(r3, h3, l3);
    __nv_bfloat162* H = (__nv_bfloat162*)hi;
    __nv_bfloat162* L = (__nv_bfloat162*)lo;
    H[2*i]   = __nv_bfloat162(h0, h1);
    H[2*i+1] = __nv_bfloat162(h2, h3);
    L[2*i]   = __nv_bfloat162(l0, l1);
    L[2*i+1] = __nv_bfloat162(l2, l3);
}

// ---------------- driver ------------------------------------------------------
static inline void split_launch(const float* src, __nv_bfloat16* hi, __nv_bfloat16* lo, size_t n)
{
    int n4 = (int)(n / 4);
    split_kernel<<<(n4 + 255)/256, 256>>>(src, hi, lo, n4);
}

extern "C" void kernel_launch(void* const* d_in, const int* in_sizes, int n_in,
                              void* d_out, int out_size)
{
    const float* x       = (const float*)d_in[0];
    const float* freqs   = (const float*)d_in[2];
    const float* w_qkv   = (const float*)d_in[4];
    const float* w_fc    = (const float*)d_in[5];
    const float* w1      = (const float*)d_in[6];
    const float* w2      = (const float*)d_in[7];
    const float* w3      = (const float*)d_in[8];
    const float* attn_nw = (const float*)d_in[9];
    const float* ff_nw   = (const float*)d_in[10];
    float* out = (float*)d_out;

    float *qkv, *qt, *kt, *vt, *h1, *u1, *u2;
    __nv_bfloat16 *ah, *al, *wh, *wl;
    cudaGetSymbolAddress((void**)&qkv,   g_qkv);
    cudaGetSymbolAddress((void**)&qt,    g_qt);
    cudaGetSymbolAddress((void**)&kt,    g_kt);
    cudaGetSymbolAddress((void**)&vt,    g_vt);
    cudaGetSymbolAddress((void**)&h1,    g_h1);
    cudaGetSymbolAddress((void**)&u1,    g_u1);
    cudaGetSymbolAddress((void**)&u2,    g_u2);
    cudaGetSymbolAddress((void**)&ah,    g_ah);
    cudaGetSymbolAddress((void**)&al,    g_al);
    cudaGetSymbolAddress((void**)&wh,    g_wh);
    cudaGetSymbolAddress((void**)&wl,    g_wl);

    cudaFuncSetAttribute(tc_gemm, cudaFuncAttributeMaxDynamicSharedMemorySize, GM_SMEM_BYTES);

    // 1. attn rmsnorm -> bf16 hi/lo directly
    rmsnorm_split_kernel<<<ROWS, 256>>>(x, attn_nw, ah, al);
    // 2. qkv projection
    split_launch(w_qkv, wh, wl, (size_t)QKV_N*EMBED);
    tc_gemm<<<dim3(QKV_N/256, ROWS/128), 256, GM_SMEM_BYTES>>>(
        ah, al, wh, wl, qkv, nullptr, ROWS, QKV_N, EMBED);
    // 3. rope + transpose
    rope_kernel<<<dim3(SS, BB), 256>>>(qkv, freqs, qt, kt, vt);
    // 4. flash attention -> writes attn hi/lo into g_ah/g_al
    const int fl_bytes = FL_SMEM_FLOATS * 4;
    cudaFuncSetAttribute(flash_kernel, cudaFuncAttributeMaxDynamicSharedMemorySize, fl_bytes);
    flash_kernel<<<dim3(SS/64, NH, BB), 256, fl_bytes>>>();
    // 5. output projection + residual
    split_launch(w_fc, wh, wl, (size_t)EMBED*EMBED);
    tc_gemm<<<dim3(EMBED/256, ROWS/128), 256, GM_SMEM_BYTES>>>(
        ah, al, wh, wl, h1, x, ROWS, EMBED, EMBED);
    // 6. ffn rmsnorm -> hi/lo
    rmsnorm_split_kernel<<<ROWS, 256>>>(h1, ff_nw, ah, al);
    // 7-8. gate / up projections
    split_launch(w1, wh, wl, (size_t)FF*EMBED);
    tc_gemm<<<dim3(FF/256, ROWS/128), 256, GM_SMEM_BYTES>>>(
        ah, al, wh, wl, u1, nullptr, ROWS, FF, EMBED);
    split_launch(w2, wh, wl, (size_t)FF*EMBED);
    tc_gemm<<<dim3(FF/256, ROWS/128), 256, GM_SMEM_BYTES>>>(
        ah, al, wh, wl, u2, nullptr, ROWS, FF, EMBED);
    // 9. swiglu -> hi/lo
    silu_split_kernel<<<(ROWS*FF/4 + 255)/256, 256>>>(u1, u2, ah, al, ROWS*FF/4);
    // 10. down projection + residual -> out
    split_launch(w3, wh, wl, (size_t)EMBED*FF);
    tc_gemm<<<dim3(EMBED/256, ROWS/128), 256, GM_SMEM_BYTES>>>(
        ah, al, wh, wl, out, h1, ROWS, EMBED, FF);
}

// round 5
// speedup vs baseline: 11.8636x; 2.1258x over previous
#include <cuda_runtime.h>
#include <cuda_bf16.h>
#include <cuda_fp16.h>
#include <math.h>
#include <stdint.h>

#define EMBED 2048
#define NH 16
#define NKV 4
#define HD 128
#define FF 5632
#define BB 2
#define SS 2048
#define ROWS (BB*SS)                 // 4096 tokens
#define QKV_N ((NH + 2*NKV)*HD)      // 3072

#if defined(__CUDA_ARCH_FEAT_SM103_ALL) || defined(__CUDA_ARCH_FEAT_SM100_ALL)
#define USE_TCGEN05 1
#else
#define USE_TCGEN05 0
#endif

// ---------------- scratch (device globals; no allocations allowed) ----------
__device__ float g_qkv [ROWS*QKV_N];
__device__ __half g_qh2[BB*NH *SS*HD];   // fp16 Q (scaled), [b,h,s,d]
__device__ __half g_kh2[BB*NKV*SS*HD];   // fp16 K, [b,kvh,s,d]
__device__ __half g_vh2[BB*NKV*HD*SS];   // fp16 V transposed, [b,kvh,d,s]
__device__ float g_h1  [ROWS*EMBED];
__device__ float g_u1  [ROWS*FF];
__device__ float g_u2  [ROWS*FF];
__device__ __nv_bfloat16 g_ah[ROWS*FF];
__device__ __nv_bfloat16 g_al[ROWS*FF];
__device__ __nv_bfloat16 g_wh[FF*EMBED];
__device__ __nv_bfloat16 g_wl[FF*EMBED];

#define GM_STAGE_BYTES 98304
#define GM_SMEM_BYTES (1024 + 2*GM_STAGE_BYTES)

__device__ __forceinline__ void split2(float f, __nv_bfloat16& h, __nv_bfloat16& l) {
    h = __float2bfloat16(f);
    l = __float2bfloat16(f - __bfloat162float(h));
}

// ---------- common helpers (legal on plain sm_103 PTX) ----------------------
__device__ __forceinline__ uint32_t smem_u32(const void* p) {
    uint32_t a;
    asm("{ .reg .u64 t; cvta.to.shared.u64 t, %1; cvt.u32.u64 %0, t; }" : "=r"(a) : "l"(p));
    return a;
}
#define CP_COMMIT() asm volatile("cp.async.commit_group;" ::: "memory")
#define CP_WAIT0()  asm volatile("cp.async.wait_group 0;" ::: "memory")
__device__ __forceinline__ void cpa16(uint32_t saddr, const void* g) {
    asm volatile("cp.async.cg.shared.global [%0], [%1], 16;" :: "r"(saddr), "l"(g) : "memory");
}
__device__ __forceinline__ void mma16816(float* c, const uint32_t* a, const uint32_t* b) {
    asm volatile("mma.sync.aligned.m16n8k16.row.col.f32.f16.f16.f32 "
        "{%0,%1,%2,%3}, {%4,%5,%6,%7}, {%8,%9}, {%0,%1,%2,%3};"
        : "+f"(c[0]), "+f"(c[1]), "+f"(c[2]), "+f"(c[3])
        : "r"(a[0]), "r"(a[1]), "r"(a[2]), "r"(a[3]), "r"(b[0]), "r"(b[1]));
}
__device__ __forceinline__ void mma16816bf(float* c, const uint32_t* a, const uint32_t* b) {
    asm volatile("mma.sync.aligned.m16n8k16.row.col.f32.bf16.bf16.f32 "
        "{%0,%1,%2,%3}, {%4,%5,%6,%7}, {%8,%9}, {%0,%1,%2,%3};"
        : "+f"(c[0]), "+f"(c[1]), "+f"(c[2]), "+f"(c[3])
        : "r"(a[0]), "r"(a[1]), "r"(a[2]), "r"(a[3]), "r"(b[0]), "r"(b[1]));
}

// ======================= split fp32 -> bf16 hi/lo (weights) ==================
__global__ __launch_bounds__(256) void split_kernel(
    const float* __restrict__ x, __nv_bfloat16* __restrict__ hi,
    __nv_bfloat16* __restrict__ lo, int n4)
{
    int i = blockIdx.x * 256 + threadIdx.x;
    if (i >= n4) return;
    float4 v = ((const float4*)x)[i];
    __nv_bfloat16 h0, h1, h2, h3, l0, l1, l2, l3;
    split2(v.x, h0, l0); split2(v.y, h1, l1);
    split2(v.z, h2, l2); split2(v.w, h3, l3);
    __nv_bfloat162* H = (__nv_bfloat162*)hi;
    __nv_bfloat162* L = (__nv_bfloat162*)lo;
    H[2*i]   = __nv_bfloat162(h0, h1);
    H[2*i+1] = __nv_bfloat162(h2, h3);
    L[2*i]   = __nv_bfloat162(l0, l1);
    L[2*i+1] = __nv_bfloat162(l2, l3);
}

#if USE_TCGEN05
// ======================= tcgen05 GEMM (sm_103a pass) =========================
__device__ __forceinline__ uint32_t elect_one_pred() {
    uint32_t pred;
    asm volatile(
        "{\n\t.reg .pred p;\n\telect.sync _|p, 0xFFFFFFFF;\n\tselp.b32 %0, 1, 0, p;\n\t}"
        : "=r"(pred));
    return pred;
}
#define MBAR_INIT(addr, cnt) \
    asm volatile("mbarrier.init.shared.b64 [%0], %1;" :: "r"(addr), "r"((uint32_t)(cnt)) : "memory")
#define MBAR_INVAL(addr) \
    asm volatile("mbarrier.inval.shared.b64 [%0];" :: "r"(addr) : "memory")
#define MBAR_WAIT(addr, parity) do { \
    uint32_t _m = (addr); uint32_t _p = (parity); uint32_t _d; \
    asm volatile("{\n\t.reg .pred p;\n\tmbarrier.try_wait.parity.acquire.cta.shared::cta.b64 p, [%1], %2;\n\tselp.b32 %0, 1, 0, p;\n\t}" \
        : "=r"(_d) : "r"(_m), "r"(_p) : "memory"); \
    if (!_d) { \
        asm volatile("{\n\t.reg .pred P1;\n\tWL_%=:\n\tmbarrier.try_wait.parity.acquire.cta.shared::cta.b64 P1, [%0], %1, 0x989680;\n\t@P1 bra.uni WD_%=;\n\tbra.uni WL_%=;\n\tWD_%=:\n\t}" \
            :: "r"(_m), "r"(_p) : "memory"); \
    } } while(0)
#define TC_ALLOC(smem_addr, n) \
    asm volatile("tcgen05.alloc.cta_group::1.sync.aligned.shared::cta.b32 [%0], %1;" \
        :: "r"((uint32_t)(smem_addr)), "r"((uint32_t)(n)) : "memory")
#define TC_DEALLOC(tmem_addr, n) \
    asm volatile("tcgen05.dealloc.cta_group::1.sync.aligned.b32 %0, %1;" :: "r"(tmem_addr), "r"((uint32_t)(n)))
#define TC_RELINQ() \
    asm volatile("tcgen05.relinquish_alloc_permit.cta_group::1.sync.aligned;")
#define TC_COMMIT(mbar) \
    asm volatile("tcgen05.commit.cta_group::1.mbarrier::arrive::one.shared::cluster.b64 [%0];" \
        :: "r"((uint32_t)(mbar)) : "memory")
#define TC_FENCE_AFTER() asm volatile("tcgen05.fence::after_thread_sync;" ::: "memory")
#define TC_FENCE_BEFORE() asm volatile("tcgen05.fence::before_thread_sync;" ::: "memory")
#define TC_WAIT_LD() asm volatile("tcgen05.wait::ld.sync.aligned;" ::: "memory")
#define FENCE_ASYNC_SHARED() asm volatile("fence.proxy.async.shared::cta;" ::: "memory")
#define TC_LD_X32(r, tmem_addr) \
    asm volatile("tcgen05.ld.sync.aligned.32x32b.x32.b32 " \
        "{%0, %1, %2, %3, %4, %5, %6, %7, %8, %9, %10, %11, %12, %13, %14, %15, " \
        " %16, %17, %18, %19, %20, %21, %22, %23, %24, %25, %26, %27, %28, %29, %30, %31}, [%32];" \
        : "=r"((r)[0]),  "=r"((r)[1]),  "=r"((r)[2]),  "=r"((r)[3]), \
          "=r"((r)[4]),  "=r"((r)[5]),  "=r"((r)[6]),  "=r"((r)[7]), \
          "=r"((r)[8]),  "=r"((r)[9]),  "=r"((r)[10]), "=r"((r)[11]), \
          "=r"((r)[12]), "=r"((r)[13]), "=r"((r)[14]), "=r"((r)[15]), \
          "=r"((r)[16]), "=r"((r)[17]), "=r"((r)[18]), "=r"((r)[19]), \
          "=r"((r)[20]), "=r"((r)[21]), "=r"((r)[22]), "=r"((r)[23]), \
          "=r"((r)[24]), "=r"((r)[25]), "=r"((r)[26]), "=r"((r)[27]), \
          "=r"((r)[28]), "=r"((r)[29]), "=r"((r)[30]), "=r"((r)[31]) \
        : "r"(tmem_addr))

__device__ __forceinline__ uint64_t mk_desc(uint32_t addr) {
    const uint64_t base = (2ull << 61) | (1ull << 46) | (64ull << 32) | (1ull << 16);
    return base | ((uint64_t)(addr >> 4) & 0x3FFF);
}
__device__ __forceinline__ void mma_f16_ss(uint32_t d, uint64_t da, uint64_t db,
                                           uint32_t idesc, uint32_t en) {
    asm volatile(
        "{\n\t.reg .pred p;\n\tsetp.ne.u32 p, %5, 0;\n\t"
        "tcgen05.mma.cta_group::1.kind::f16 [%0], %1, %2, %3, {%4,%4,%4,%4}, p;\n\t}"
        :: "r"(d), "l"(da), "l"(db), "r"(idesc), "r"(0u), "r"(en) : "memory");
}

#define GM_IDESC 0x8400490u              // F32 acc, bf16 a/b, M=128, N=256

__device__ __forceinline__ void gm_load_stage(
    uint32_t stb,
    const __nv_bfloat16* __restrict__ Ah, const __nv_bfloat16* __restrict__ Al,
    const __nv_bfloat16* __restrict__ Bh, const __nv_bfloat16* __restrict__ Bl,
    int bm, int bn, int K, int kc, int tid)
{
    #pragma unroll
    for (int it = 0; it < 4; it++) {
        int v = tid + it * 256;
        int r = v >> 3, cv = v & 7;
        uint32_t off = (uint32_t)(r*128 + cv*16);
        uint32_t sw = off ^ ((off >> 3) & 0x70);
        size_t go = (size_t)(bm + r) * K + kc + cv*8;
        cpa16(stb + sw,         Ah + go);
        cpa16(stb + 16384 + sw, Al + go);
    }
    #pragma unroll
    for (int it = 0; it < 8; it++) {
        int v = tid + it * 256;
        int r = v >> 3, cv = v & 7;
        uint32_t off = (uint32_t)(r*128 + cv*16);
        uint32_t sw = off ^ ((off >> 3) & 0x70);
        size_t go = (size_t)(bn + r) * K + kc + cv*8;
        cpa16(stb + 32768 + sw, Bh + go);
        cpa16(stb + 65536 + sw, Bl + go);
    }
    CP_COMMIT();
}

__global__ __launch_bounds__(256, 1) void tc_gemm(
    const __nv_bfloat16* __restrict__ Ah, const __nv_bfloat16* __restrict__ Al,
    const __nv_bfloat16* __restrict__ Bh, const __nv_bfloat16* __restrict__ Bl,
    float* __restrict__ C, const float* __restrict__ addend,
    int M, int N, int K)
{
    extern __shared__ char smem[];
    uint32_t sb = smem_u32(smem);
    int tid = threadIdx.x;
    int wid = tid >> 5, lane = tid & 31;
    int bn = blockIdx.x * 256, bm = blockIdx.y * 128;

    if (wid == 0) { TC_ALLOC(sb, 256); TC_RELINQ(); }
    if (tid == 0) { MBAR_INIT(sb + 8, 1); MBAR_INIT(sb + 16, 1); }
    __syncthreads();
    uint32_t tmem;
    asm volatile("ld.shared.b32 %0, [%1];" : "=r"(tmem) : "r"(sb));

    const int NC = K / 64;
    int ph0 = 0, ph1 = 0;

    gm_load_stage(sb + 1024, Ah, Al, Bh, Bl, bm, bn, K, 0, tid);

    for (int c = 0; c < NC; c++) {
        int s = c & 1;
        CP_WAIT0();
        __syncthreads();
        uint32_t stb = sb + 1024 + (uint32_t)s * GM_STAGE_BYTES;
        if (wid == 0 && elect_one_pred()) {
            FENCE_ASYNC_SHARED();
            uint64_t dAh = mk_desc(stb);
            uint64_t dAl = mk_desc(stb + 16384);
            uint64_t dBh = mk_desc(stb + 32768);
            uint64_t dBl = mk_desc(stb + 65536);
            #pragma unroll
            for (int k = 0; k < 4; k++)
                mma_f16_ss(tmem, dAh + k*2, dBh + k*2, GM_IDESC, (c > 0) || (k > 0));
            #pragma unroll
            for (int k = 0; k < 4; k++)
                mma_f16_ss(tmem, dAh + k*2, dBl + k*2, GM_IDESC, 1u);
            #pragma unroll
            for (int k = 0; k < 4; k++)
                mma_f16_ss(tmem, dAl + k*2, dBh + k*2, GM_IDESC, 1u);
            TC_COMMIT(sb + 8 + (uint32_t)s * 8);
        }
        if (c + 1 < NC) {
            int s2 = (c + 1) & 1;
            if (c >= 1) {
                if (s2 == 0) { MBAR_WAIT(sb + 8, ph0);  ph0 ^= 1; }
                else         { MBAR_WAIT(sb + 16, ph1); ph1 ^= 1; }
            }
            gm_load_stage(sb + 1024 + (uint32_t)s2 * GM_STAGE_BYTES,
                          Ah, Al, Bh, Bl, bm, bn, K, (c + 1) * 64, tid);
        }
    }
    int sl = (NC - 1) & 1;
    if (sl == 0) { MBAR_WAIT(sb + 8, ph0); } else { MBAR_WAIT(sb + 16, ph1); }
    TC_FENCE_AFTER();

    int wg = wid >> 2, ws = wid & 3;
    size_t row = (size_t)(bm + ws * 32 + lane);
    #pragma unroll
    for (int cb = 0; cb < 4; cb++) {
        uint32_t regs[32];
        TC_LD_X32(regs, tmem + (uint32_t)(wg * 128 + cb * 32));
        TC_WAIT_LD();
        int col = bn + wg * 128 + cb * 32;
        float* Cp = C + row * (size_t)N + col;
        if (addend) {
            const float* Ap = addend + row * (size_t)N + col;
            #pragma unroll
            for (int j = 0; j < 32; j += 4) {
                float4 a = *(const float4*)(Ap + j);
                float4 o = make_float4(__uint_as_float(regs[j])   + a.x,
                                       __uint_as_float(regs[j+1]) + a.y,
                                       __uint_as_float(regs[j+2]) + a.z,
                                       __uint_as_float(regs[j+3]) + a.w);
                *(float4*)(Cp + j) = o;
            }
        } else {
            #pragma unroll
            for (int j = 0; j < 32; j += 4) {
                float4 o = make_float4(__uint_as_float(regs[j]),
                                       __uint_as_float(regs[j+1]),
                                       __uint_as_float(regs[j+2]),
                                       __uint_as_float(regs[j+3]));
                *(float4*)(Cp + j) = o;
            }
        }
    }
    TC_FENCE_BEFORE();
    __syncthreads();
    if (tid == 0) { MBAR_INVAL(sb + 8); MBAR_INVAL(sb + 16); }
    if (wid == 0) { TC_DEALLOC(tmem, 256); }
}

#else
// ======================= mma.sync GEMM fallback ==============================
#define FB_LD 40

__global__ __launch_bounds__(256, 1) void tc_gemm(
    const __nv_bfloat16* __restrict__ Ah, const __nv_bfloat16* __restrict__ Al,
    const __nv_bfloat16* __restrict__ Bh, const __nv_bfloat16* __restrict__ Bl,
    float* __restrict__ C, const float* __restrict__ addend,
    int M, int N, int K)
{
    extern __shared__ char smem[];
    __nv_bfloat16* sAh = (__nv_bfloat16*)smem;
    __nv_bfloat16* sAl = sAh + 128*FB_LD;
    __nv_bfloat16* sBh = sAl + 128*FB_LD;
    __nv_bfloat16* sBl = sBh + 256*FB_LD;
    int tid = threadIdx.x, lane = tid & 31, wid = tid >> 5;
    int bn = blockIdx.x * 256, bm = blockIdx.y * 128;
    int wm = wid >> 2, wn = wid & 3;
    int g = lane >> 2, tig = lane & 3;

    float acc[4][8][4];
    #pragma unroll
    for (int mt = 0; mt < 4; mt++)
        #pragma unroll
        for (int nt = 0; nt < 8; nt++)
            #pragma unroll
            for (int q = 0; q < 4; q++) acc[mt][nt][q] = 0.f;

    for (int k0 = 0; k0 < K; k0 += 32) {
        __syncthreads();
        for (int v = tid; v < 512; v += 256) {
            int r = v >> 2, q = v & 3;
            *(uint4*)&sAh[r*FB_LD + q*8] = *(const uint4*)(Ah + (size_t)(bm+r)*K + k0 + q*8);
            *(uint4*)&sAl[r*FB_LD + q*8] = *(const uint4*)(Al + (size_t)(bm+r)*K + k0 + q*8);
        }
        for (int v = tid; v < 1024; v += 256) {
            int r = v >> 2, q = v & 3;
            *(uint4*)&sBh[r*FB_LD + q*8] = *(const uint4*)(Bh + (size_t)(bn+r)*K + k0 + q*8);
            *(uint4*)&sBl[r*FB_LD + q*8] = *(const uint4*)(Bl + (size_t)(bn+r)*K + k0 + q*8);
        }
        __syncthreads();
        #pragma unroll
        for (int ks = 0; ks < 2; ks++) {
            int kk = ks * 16 + tig * 2;
            uint32_t ah[4][4], al[4][4], bh[8][2], bl[8][2];
            #pragma unroll
            for (int mt = 0; mt < 4; mt++) {
                int mr = (wm*64 + mt*16 + g)*FB_LD + kk;
                ah[mt][0] = *(const uint32_t*)&sAh[mr];
                ah[mt][1] = *(const uint32_t*)&sAh[mr + 8*FB_LD];
                ah[mt][2] = *(const uint32_t*)&sAh[mr + 8];
                ah[mt][3] = *(const uint32_t*)&sAh[mr + 8*FB_LD + 8];
                al[mt][0] = *(const uint32_t*)&sAl[mr];
                al[mt][1] = *(const uint32_t*)&sAl[mr + 8*FB_LD];
                al[mt][2] = *(const uint32_t*)&sAl[mr + 8];
                al[mt][3] = *(const uint32_t*)&sAl[mr + 8*FB_LD + 8];
            }
            #pragma unroll
            for (int nt = 0; nt < 8; nt++) {
                int nr = (wn*64 + nt*8 + g)*FB_LD + kk;
                bh[nt][0] = *(const uint32_t*)&sBh[nr];
                bh[nt][1] = *(const uint32_t*)&sBh[nr + 8];
                bl[nt][0] = *(const uint32_t*)&sBl[nr];
                bl[nt][1] = *(const uint32_t*)&sBl[nr + 8];
            }
            #pragma unroll
            for (int mt = 0; mt < 4; mt++)
                #pragma unroll
                for (int nt = 0; nt < 8; nt++) {
                    mma16816bf(acc[mt][nt], ah[mt], bh[nt]);
                    mma16816bf(acc[mt][nt], ah[mt], bl[nt]);
                    mma16816bf(acc[mt][nt], al[mt], bh[nt]);
                }
        }
    }
    #pragma unroll
    for (int mt = 0; mt < 4; mt++) {
        #pragma unroll
        for (int nt = 0; nt < 8; nt++) {
            size_t r0 = (size_t)(bm + wm*64 + mt*16 + g);
            int col = bn + wn*64 + nt*8 + tig*2;
            float2 v0 = make_float2(acc[mt][nt][0], acc[mt][nt][1]);
            float2 v1 = make_float2(acc[mt][nt][2], acc[mt][nt][3]);
            if (addend) {
                float2 a0 = *(const float2*)(addend + r0*N + col);
                float2 a1 = *(const float2*)(addend + (r0+8)*N + col);
                v0.x += a0.x; v0.y += a0.y; v1.x += a1.x; v1.y += a1.y;
            }
            *(float2*)(C + r0*N + col)     = v0;
            *(float2*)(C + (r0+8)*N + col) = v1;
        }
    }
}
#endif  // USE_TCGEN05

// ---------------- RMSNorm -> bf16 hi/lo --------------------------------------
__global__ __launch_bounds__(256) void rmsnorm_split_kernel(
    const float* __restrict__ x, const float* __restrict__ w,
    __nv_bfloat16* __restrict__ hi, __nv_bfloat16* __restrict__ lo)
{
    __shared__ float red[8];
    int row = blockIdx.x;
    int tid = threadIdx.x;
    const float4* xr = (const float4*)(x + (size_t)row * EMBED);
    const float4* w4 = (const float4*)w;
    float4 v0 = xr[tid];
    float4 v1 = xr[tid + 256];
    float ss = v0.x*v0.x + v0.y*v0.y + v0.z*v0.z + v0.w*v0.w
             + v1.x*v1.x + v1.y*v1.y + v1.z*v1.z + v1.w*v1.w;
    #pragma unroll
    for (int o = 16; o > 0; o >>= 1) ss += __shfl_xor_sync(0xffffffffu, ss, o);
    if ((tid & 31) == 0) red[tid >> 5] = ss;
    __syncthreads();
    float tot = red[0] + red[1] + red[2] + red[3] + red[4] + red[5] + red[6] + red[7];
    float inv = rsqrtf(tot * (1.0f / EMBED) + 1e-5f);
    float4 wa = w4[tid], wb = w4[tid + 256];
    float o0[4] = {v0.x*inv*wa.x, v0.y*inv*wa.y, v0.z*inv*wa.z, v0.w*inv*wa.w};
    float o1[4] = {v1.x*inv*wb.x, v1.y*inv*wb.y, v1.z*inv*wb.z, v1.w*inv*wb.w};
    __nv_bfloat16 h[4], l[4];
    __nv_bfloat162* H = (__nv_bfloat162*)(hi + (size_t)row * EMBED);
    __nv_bfloat162* L = (__nv_bfloat162*)(lo + (size_t)row * EMBED);
    #pragma unroll
    for (int j = 0; j < 4; j++) split2(o0[j], h[j], l[j]);
    H[2*tid]   = __nv_bfloat162(h[0], h[1]);  H[2*tid+1] = __nv_bfloat162(h[2], h[3]);
    L[2*tid]   = __nv_bfloat162(l[0], l[1]);  L[2*tid+1] = __nv_bfloat162(l[2], l[3]);
    #pragma unroll
    for (int j = 0; j < 4; j++) split2(o1[j], h[j], l[j]);
    H[2*(tid+256)]   = __nv_bfloat162(h[0], h[1]);  H[2*(tid+256)+1] = __nv_bfloat162(h[2], h[3]);
    L[2*(tid+256)]   = __nv_bfloat162(l[0], l[1]);  L[2*(tid+256)+1] = __nv_bfloat162(l[2], l[3]);
}

// ---------------- RoPE + head transpose -> fp16 ------------------------------
__global__ __launch_bounds__(256) void rope_kernel(
    const float* __restrict__ qkv, const float* __restrict__ freqs,
    __half* __restrict__ qh, __half* __restrict__ kh, __half* __restrict__ vh)
{
    int s = blockIdx.x, b = blockIdx.y, tid = threadIdx.x;
    const float* row = qkv + ((size_t)b * SS + s) * QKV_N;
    const float* f = freqs + (size_t)s * HD;
    const float scale = 0.02209708691207961f;   // 1/sqrt(2048), folded into Q

    for (int p = tid; p < NH * 64; p += 256) {
        int h = p >> 6, i = p & 63;
        float x0 = row[h*HD + 2*i], x1 = row[h*HD + 2*i + 1];
        float c = f[2*i], sn = f[2*i+1];
        __half2* dst = (__half2*)(qh + ((size_t)(b*NH + h) * SS + s) * HD + 2*i);
        *dst = __floats2half2_rn((x0*c - x1*sn) * scale, (x1*c + x0*sn) * scale);
    }
    for (int p = tid; p < NKV * 64; p += 256) {
        int h = p >> 6, i = p & 63;
        float x0 = row[NH*HD + h*HD + 2*i], x1 = row[NH*HD + h*HD + 2*i + 1];
        float c = f[2*i], sn = f[2*i+1];
        __half2* dst = (__half2*)(kh + ((size_t)(b*NKV + h) * SS + s) * HD + 2*i);
        *dst = __floats2half2_rn(x0*c - x1*sn, x1*c + x0*sn);
    }
    for (int p = tid; p < NKV * HD; p += 256) {
        int h = p >> 7, d = p & 127;
        vh[((size_t)(b*NKV + h) * HD + d) * SS + s] =
            __float2half_rn(row[(NH + NKV)*HD + p]);
    }
}

// ---------------- Tensor-core flash attention (fp16 mma, fp32 softmax) -------
// Block: 128 q-rows × HD=128; 64-key tiles; 8 warps × 16 rows each.
#define FLH_SMEM_BYTES ((128*136 + 64*136 + 128*72) * 2)
__global__ __launch_bounds__(256) void flash_tc_kernel(
    const __half* __restrict__ qh, const __half* __restrict__ kh,
    const __half* __restrict__ vh,
    __nv_bfloat16* __restrict__ oh, __nv_bfloat16* __restrict__ ol)
{
    extern __shared__ __half smh[];
    __half* Qs = smh;                  // [128][136]
    __half* Ks = Qs + 128*136;         // [64][136]
    __half* Vs = Ks + 64*136;          // [128][72]  (Vt: [d][kc])
    int tid = threadIdx.x, lane = tid & 31, wid = tid >> 5;
    int g = lane >> 2, tig = lane & 3;
    int qb = blockIdx.x, hb = blockIdx.y, bb = blockIdx.z;
    uint32_t ks_b = smem_u32(Ks), vs_b = smem_u32(Vs);

    const __half* Qg = qh + ((size_t)(bb*NH + hb) * SS + (size_t)qb*128) * HD;
    const __half* Kg = kh + (size_t)(bb*NKV + (hb >> 2)) * SS * HD;
    const __half* Vg = vh + (size_t)(bb*NKV + (hb >> 2)) * HD * SS;

    for (int i = tid; i < 128*16; i += 256) {
        int r = i >> 4, c = i & 15;
        *(uint4*)&Qs[r*136 + c*8] = *(const uint4*)(Qg + r*HD + c*8);
    }

    float accO[16][4];
    #pragma unroll
    for (int nd = 0; nd < 16; nd++)
        #pragma unroll
        for (int q = 0; q < 4; q++) accO[nd][q] = 0.f;
    float m0 = -1e30f, m1 = -1e30f, l0 = 0.f, l1 = 0.f;
    int r0 = qb*128 + wid*16 + g;
    int r1 = r0 + 8;

    int nkb = 2*(qb + 1);
    for (int kb = 0; kb < nkb; kb++) {
        __syncthreads();
        for (int i = tid; i < 64*16; i += 256) {       // K: 64 keys x 128 d
            int r = i >> 4, c = i & 15;
            cpa16(ks_b + (uint32_t)(r*136 + c*8)*2,
                  Kg + (size_t)(kb*64 + r)*HD + c*8);
        }
        for (int i = tid; i < 128*8; i += 256) {       // Vt: 128 d x 64 kc
            int r = i >> 3, c = i & 7;
            cpa16(vs_b + (uint32_t)(r*72 + c*8)*2,
                  Vg + (size_t)r*SS + kb*64 + c*8);
        }
        CP_COMMIT(); CP_WAIT0();
        __syncthreads();

        // S = Q*K^T  (128x64), warp: 16 rows
        float sacc[8][4];
        #pragma unroll
        for (int nt = 0; nt < 8; nt++)
            #pragma unroll
            for (int q = 0; q < 4; q++) sacc[nt][q] = 0.f;
        #pragma unroll
        for (int ks = 0; ks < 8; ks++) {
            uint32_t a[4];
            const __half* qr = &Qs[(wid*16 + g)*136 + ks*16 + 2*tig];
            a[0] = *(const uint32_t*)qr;
            a[1] = *(const uint32_t*)(qr + 8*136);
            a[2] = *(const uint32_t*)(qr + 8);
            a[3] = *(const uint32_t*)(qr + 8*136 + 8);
            #pragma unroll
            for (int nt = 0; nt < 8; nt++) {
                uint32_t b[2];
                const __half* kr = &Ks[(nt*8 + g)*136 + ks*16 + 2*tig];
                b[0] = *(const uint32_t*)kr;
                b[1] = *(const uint32_t*)(kr + 8);
                mma16816(sacc[nt], a, b);
            }
        }
        // causal mask (only diagonal-adjacent tiles can need it)
        if (kb >= 2*qb) {
            #pragma unroll
            for (int nt = 0; nt < 8; nt++) {
                int col = kb*64 + nt*8 + 2*tig;
                if (col     > r0) sacc[nt][0] = -1e30f;
                if (col + 1 > r0) sacc[nt][1] = -1e30f;
                if (col     > r1) sacc[nt][2] = -1e30f;
                if (col + 1 > r1) sacc[nt][3] = -1e30f;
            }
        }
        // online softmax (rows r0 via c0/c1, r1 via c2/c3; quad = 4 lanes)
        float mx0 = -1e30f, mx1 = -1e30f;
        #pragma unroll
        for (int nt = 0; nt < 8; nt++) {
            mx0 = fmaxf(mx0, fmaxf(sacc[nt][0], sacc[nt][1]));
            mx1 = fmaxf(mx1, fmaxf(sacc[nt][2], sacc[nt][3]));
        }
        mx0 = fmaxf(mx0, __shfl_xor_sync(0xffffffffu, mx0, 1));
        mx0 = fmaxf(mx0, __shfl_xor_sync(0xffffffffu, mx0, 2));
        mx1 = fmaxf(mx1, __shfl_xor_sync(0xffffffffu, mx1, 1));
        mx1 = fmaxf(mx1, __shfl_xor_sync(0xffffffffu, mx1, 2));
        float nm0 = fmaxf(m0, mx0), nm1 = fmaxf(m1, mx1);
        float f0 = __expf(m0 - nm0), f1 = __expf(m1 - nm1);
        m0 = nm0; m1 = nm1;
        float s0 = 0.f, s1 = 0.f;
        #pragma unroll
        for (int nt = 0; nt < 8; nt++) {
            float p0 = __expf(sacc[nt][0] - m0);
            float p1 = __expf(sacc[nt][1] - m0);
            float p2 = __expf(sacc[nt][2] - m1);
            float p3 = __expf(sacc[nt][3] - m1);
            sacc[nt][0] = p0; sacc[nt][1] = p1; sacc[nt][2] = p2; sacc[nt][3] = p3;
            s0 += p0 + p1; s1 += p2 + p3;
        }
        s0 += __shfl_xor_sync(0xffffffffu, s0, 1);
        s0 += __shfl_xor_sync(0xffffffffu, s0, 2);
        s1 += __shfl_xor_sync(0xffffffffu, s1, 1);
        s1 += __shfl_xor_sync(0xffffffffu, s1, 2);
        l0 = l0*f0 + s0; l1 = l1*f1 + s1;
        #pragma unroll
        for (int nd = 0; nd < 16; nd++) {
            accO[nd][0] *= f0; accO[nd][1] *= f0;
            accO[nd][2] *= f1; accO[nd][3] *= f1;
        }
        // O += P*V ; P fragments come straight from sacc
        #pragma unroll
        for (int j = 0; j < 4; j++) {
            uint32_t a[4];
            __half2 t;
            t = __floats2half2_rn(sacc[2*j][0],   sacc[2*j][1]);   a[0] = *(uint32_t*)&t;
            t = __floats2half2_rn(sacc[2*j][2],   sacc[2*j][3]);   a[1] = *(uint32_t*)&t;
            t = __floats2half2_rn(sacc[2*j+1][0], sacc[2*j+1][1]); a[2] = *(uint32_t*)&t;
            t = __floats2half2_rn(sacc[2*j+1][2], sacc[2*j+1][3]); a[3] = *(uint32_t*)&t;
            #pragma unroll
            for (int nd = 0; nd < 16; nd++) {
                uint32_t b[2];
                const __half* vr = &Vs[(nd*8 + g)*72 + j*16 + 2*tig];
                b[0] = *(const uint32_t*)vr;
                b[1] = *(const uint32_t*)(vr + 8);
                mma16816(accO[nd], a, b);
            }
        }
    }
    // epilogue: O /= l, hi/lo bf16 via smem staging (stride 136 for 16B align)
    float inv0 = 1.f / l0, inv1 = 1.f / l1;
    __nv_bfloat16* st = (__nv_bfloat16*)smh;   // [128][136]
    int lr = wid*16 + g;
    size_t obase = ((size_t)bb*SS + (size_t)qb*128) * EMBED + hb*HD;
    // pass 1: hi
    __syncthreads();
    #pragma unroll
    for (int nd = 0; nd < 16; nd++) {
        int col = nd*8 + 2*tig;
        *(__nv_bfloat162*)&st[lr*136 + col] = __nv_bfloat162(
            __float2bfloat16(accO[nd][0]*inv0), __float2bfloat16(accO[nd][1]*inv0));
        *(__nv_bfloat162*)&st[(lr+8)*136 + col] = __nv_bfloat162(
            __float2bfloat16(accO[nd][2]*inv1), __float2bfloat16(accO[nd][3]*inv1));
    }
    __syncthreads();
    for (int i = tid; i < 128*16; i += 256) {
        int r = i >> 4, c = i & 15;
        *(uint4*)(oh + obase + (size_t)r*EMBED + c*8) = *(uint4*)&st[r*136 + c*8];
    }
    __syncthreads();
    // pass 2: lo = v - float(hi)
    #pragma unroll
    for (int nd = 0; nd < 16; nd++) {
        int col = nd*8 + 2*tig;
        float v0 = accO[nd][0]*inv0, v1 = accO[nd][1]*inv0;
        float v2 = accO[nd][2]*inv1, v3 = accO[nd][3]*inv1;
        *(__nv_bfloat162*)&st[lr*136 + col] = __nv_bfloat162(
            __float2bfloat16(v0 - __bfloat162float(__float2bfloat16(v0))),
            __float2bfloat16(v1 - __bfloat162float(__float2bfloat16(v1))));
        *(__nv_bfloat162*)&st[(lr+8)*136 + col] = __nv_bfloat162(
            __float2bfloat16(v2 - __bfloat162float(__float2bfloat16(v2))),
            __float2bfloat16(v3 - __bfloat162float(__float2bfloat16(v3))));
    }
    __syncthreads();
    for (int i = tid; i < 128*16; i += 256) {
        int r = i >> 4, c = i & 15;
        *(uint4*)(ol + obase + (size_t)r*EMBED + c*8) = *(uint4*)&st[r*136 + c*8];
    }
}

// ---------------- SwiGLU -> bf16 hi/lo ---------------------------------------
__global__ __launch_bounds__(256) void silu_split_kernel(
    const float* __restrict__ u1, const float* __restrict__ u2,
    __nv_bfloat16* __restrict__ hi, __nv_bfloat16* __restrict__ lo, int n4)
{
    int i = blockIdx.x * 256 + threadIdx.x;
    if (i >= n4) return;
    float4 a = ((const float4*)u1)[i];
    float4 b = ((const float4*)u2)[i];
    float r0 = a.x / (1.f + __expf(-a.x)) * b.x;
    float r1 = a.y / (1.f + __expf(-a.y)) * b.y;
    float r2 = a.z / (1.f + __expf(-a.z)) * b.z;
    float r3 = a.w / (1.f + __expf(-a.w)) * b.w;
    __nv_bfloat16 h0, h1, h2, h3, l0, l1, l2, l3;
    split2(r0, h0, l0); split2(r1, h1, l1); split2(r2, h2, l2); split2(r3, h3, l3);
    __nv_bfloat162* H = (__nv_bfloat162*)hi;
    __nv_bfloat162* L = (__nv_bfloat162*)lo;
    H[2*i]   = __nv_bfloat162(h0, h1);
    H[2*i+1] = __nv_bfloat162(h2, h3);
    L[2*i]   = __nv_bfloat162(l0, l1);
    L[2*i+1] = __nv_bfloat162(l2, l3);
}

// ---------------- driver ------------------------------------------------------
static inline void split_launch(const float* src, __nv_bfloat16* hi, __nv_bfloat16* lo, size_t n)
{
    int n4 = (int)(n / 4);
    split_kernel<<<(n4 + 255)/256, 256>>>(src, hi, lo, n4);
}

extern "C" void kernel_launch(void* const* d_in, const int* in_sizes, int n_in,
                              void* d_out, int out_size)
{
    const float* x       = (const float*)d_in[0];
    const float* freqs   = (const float*)d_in[2];
    const float* w_qkv   = (const float*)d_in[4];
    const float* w_fc    = (const float*)d_in[5];
    const float* w1      = (const float*)d_in[6];
    const float* w2      = (const float*)d_in[7];
    const float* w3      = (const float*)d_in[8];
    const float* attn_nw = (const float*)d_in[9];
    const float* ff_nw   = (const float*)d_in[10];
    float* out = (float*)d_out;

    float *qkv, *h1, *u1, *u2;
    __half *qh, *kh, *vh;
    __nv_bfloat16 *ah, *al, *wh, *wl;
    cudaGetSymbolAddress((void**)&qkv, g_qkv);
    cudaGetSymbolAddress((void**)&qh,  g_qh2);
    cudaGetSymbolAddress((void**)&kh,  g_kh2);
    cudaGetSymbolAddress((void**)&vh,  g_vh2);
    cudaGetSymbolAddress((void**)&h1,  g_h1);
    cudaGetSymbolAddress((void**)&u1,  g_u1);
    cudaGetSymbolAddress((void**)&u2,  g_u2);
    cudaGetSymbolAddress((void**)&ah,  g_ah);
    cudaGetSymbolAddress((void**)&al,  g_al);
    cudaGetSymbolAddress((void**)&wh,  g_wh);
    cudaGetSymbolAddress((void**)&wl,  g_wl);

    cudaFuncSetAttribute(tc_gemm, cudaFuncAttributeMaxDynamicSharedMemorySize, GM_SMEM_BYTES);
    cudaFuncSetAttribute(flash_tc_kernel, cudaFuncAttributeMaxDynamicSharedMemorySize, FLH_SMEM_BYTES);

    // 1. attn rmsnorm -> bf16 hi/lo
    rmsnorm_split_kernel<<<ROWS, 256>>>(x, attn_nw, ah, al);
    // 2. qkv projection
    split_launch(w_qkv, wh, wl, (size_t)QKV_N*EMBED);
    tc_gemm<<<dim3(QKV_N/256, ROWS/128), 256, GM_SMEM_BYTES>>>(
        ah, al, wh, wl, qkv, nullptr, ROWS, QKV_N, EMBED);
    // 3. rope + transpose -> fp16
    rope_kernel<<<dim3(SS, BB), 256>>>(qkv, freqs, qh, kh, vh);
    // 4. tensor-core flash attention -> attn hi/lo into g_ah/g_al
    flash_tc_kernel<<<dim3(SS/128, NH, BB), 256, FLH_SMEM_BYTES>>>(qh, kh, vh, ah, al);
    // 5. output projection + residual
    split_launch(w_fc, wh, wl, (size_t)EMBED*EMBED);
    tc_gemm<<<dim3(EMBED/256, ROWS/128), 256, GM_SMEM_BYTES>>>(
        ah, al, wh, wl, h1, x, ROWS, EMBED, EMBED);
    // 6. ffn rmsnorm -> hi/lo
    rmsnorm_split_kernel<<<ROWS, 256>>>(h1, ff_nw, ah, al);
    // 7-8. gate / up projections
    split_launch(w1, wh, wl, (size_t)FF*EMBED);
    tc_gemm<<<dim3(FF/256, ROWS/128), 256, GM_SMEM_BYTES>>>(
        ah, al, wh, wl, u1, nullptr, ROWS, FF, EMBED);
    split_launch(w2, wh, wl, (size_t)FF*EMBED);
    tc_gemm<<<dim3(FF/256, ROWS/128), 256, GM_SMEM_BYTES>>>(
        ah, al, wh, wl, u2, nullptr, ROWS, FF, EMBED);
    // 9. swiglu -> hi/lo
    silu_split_kernel<<<(ROWS*FF/4 + 255)/256, 256>>>(u1, u2, ah, al, ROWS*FF/4);
    // 10. down projection + residual -> out
    split_launch(w3, wh, wl, (size_t)EMBED*FF);
    tc_gemm<<<dim3(EMBED/256, ROWS/128), 256, GM_SMEM_BYTES>>>(
        ah, al, wh, wl, out, h1, ROWS, EMBED, FF);
}

// round 6
// speedup vs baseline: 18.4043x; 1.5513x over previous
#include <cuda_runtime.h>
#include <cuda_bf16.h>
#include <cuda_fp16.h>
#include <math.h>
#include <stdint.h>

#define EMBED 2048
#define NH 16
#define NKV 4
#define HD 128
#define FF 5632
#define BB 2
#define SS 2048
#define ROWS (BB*SS)                 // 4096 tokens
#define QKV_N ((NH + 2*NKV)*HD)      // 3072

#if defined(__CUDA_ARCH_FEAT_SM103_ALL) || defined(__CUDA_ARCH_FEAT_SM100_ALL)
#define USE_TCGEN05 1
#else
#define USE_TCGEN05 0
#endif

// ---------------- scratch (device globals; no allocations allowed) ----------
__device__ float g_qkv [ROWS*QKV_N];
__device__ __half g_qh2[BB*NH *SS*HD];   // fp16 Q (scaled), [b,h,s,d]
__device__ __half g_kh2[BB*NKV*SS*HD];   // fp16 K, [b,kvh,s,d]
__device__ __half g_vh2[BB*NKV*HD*SS];   // fp16 V transposed, [b,kvh,d,s]
__device__ float g_h1  [ROWS*EMBED];
__device__ float g_u1  [ROWS*FF];
__device__ float g_u2  [ROWS*FF];
__device__ __half g_ah[ROWS*FF];         // fp16 activations (gemm A operand)
__device__ __half g_wh[FF*EMBED];        // fp16 weights     (gemm B operand)

#define GM_STAGE_BYTES 65536             // A0 16K + A1 16K + B 32K
#define GM_SMEM_BYTES (1024 + 2*GM_STAGE_BYTES)

// ---------- common helpers (legal on plain sm_103 PTX) ----------------------
__device__ __forceinline__ uint32_t smem_u32(const void* p) {
    uint32_t a;
    asm("{ .reg .u64 t; cvta.to.shared.u64 t, %1; cvt.u32.u64 %0, t; }" : "=r"(a) : "l"(p));
    return a;
}
#define CP_COMMIT() asm volatile("cp.async.commit_group;" ::: "memory")
#define CP_WAIT0()  asm volatile("cp.async.wait_group 0;" ::: "memory")
__device__ __forceinline__ void cpa16(uint32_t saddr, const void* g) {
    asm volatile("cp.async.cg.shared.global [%0], [%1], 16;" :: "r"(saddr), "l"(g) : "memory");
}
__device__ __forceinline__ void mma16816(float* c, const uint32_t* a, const uint32_t* b) {
    asm volatile("mma.sync.aligned.m16n8k16.row.col.f32.f16.f16.f32 "
        "{%0,%1,%2,%3}, {%4,%5,%6,%7}, {%8,%9}, {%0,%1,%2,%3};"
        : "+f"(c[0]), "+f"(c[1]), "+f"(c[2]), "+f"(c[3])
        : "r"(a[0]), "r"(a[1]), "r"(a[2]), "r"(a[3]), "r"(b[0]), "r"(b[1]));
}

// ======================= fp32 -> fp16 convert (weights) ======================
__global__ __launch_bounds__(256) void conv_kernel(
    const float* __restrict__ x, __half* __restrict__ y, int n4)
{
    int i = blockIdx.x * 256 + threadIdx.x;
    if (i >= n4) return;
    float4 v = ((const float4*)x)[i];
    __half2* Y = (__half2*)y;
    Y[2*i]   = __floats2half2_rn(v.x, v.y);
    Y[2*i+1] = __floats2half2_rn(v.z, v.w);
}

#if USE_TCGEN05
// ======================= tcgen05 GEMM (sm_103a pass) =========================
// C[M,N] = A[M,K] * B[N,K]^T (+addend); fp16 operands, fp32 TMEM accum.
// Tile: BM=256 (two M=128 halves sharing B), BN=256, BK=64.
__device__ __forceinline__ uint32_t elect_one_pred() {
    uint32_t pred;
    asm volatile(
        "{\n\t.reg .pred p;\n\telect.sync _|p, 0xFFFFFFFF;\n\tselp.b32 %0, 1, 0, p;\n\t}"
        : "=r"(pred));
    return pred;
}
#define MBAR_INIT(addr, cnt) \
    asm volatile("mbarrier.init.shared.b64 [%0], %1;" :: "r"(addr), "r"((uint32_t)(cnt)) : "memory")
#define MBAR_INVAL(addr) \
    asm volatile("mbarrier.inval.shared.b64 [%0];" :: "r"(addr) : "memory")
#define MBAR_WAIT(addr, parity) do { \
    uint32_t _m = (addr); uint32_t _p = (parity); uint32_t _d; \
    asm volatile("{\n\t.reg .pred p;\n\tmbarrier.try_wait.parity.acquire.cta.shared::cta.b64 p, [%1], %2;\n\tselp.b32 %0, 1, 0, p;\n\t}" \
        : "=r"(_d) : "r"(_m), "r"(_p) : "memory"); \
    if (!_d) { \
        asm volatile("{\n\t.reg .pred P1;\n\tWL_%=:\n\tmbarrier.try_wait.parity.acquire.cta.shared::cta.b64 P1, [%0], %1, 0x989680;\n\t@P1 bra.uni WD_%=;\n\tbra.uni WL_%=;\n\tWD_%=:\n\t}" \
            :: "r"(_m), "r"(_p) : "memory"); \
    } } while(0)
#define TC_ALLOC(smem_addr, n) \
    asm volatile("tcgen05.alloc.cta_group::1.sync.aligned.shared::cta.b32 [%0], %1;" \
        :: "r"((uint32_t)(smem_addr)), "r"((uint32_t)(n)) : "memory")
#define TC_DEALLOC(tmem_addr, n) \
    asm volatile("tcgen05.dealloc.cta_group::1.sync.aligned.b32 %0, %1;" :: "r"(tmem_addr), "r"((uint32_t)(n)))
#define TC_RELINQ() \
    asm volatile("tcgen05.relinquish_alloc_permit.cta_group::1.sync.aligned;")
#define TC_COMMIT(mbar) \
    asm volatile("tcgen05.commit.cta_group::1.mbarrier::arrive::one.shared::cluster.b64 [%0];" \
        :: "r"((uint32_t)(mbar)) : "memory")
#define TC_FENCE_AFTER() asm volatile("tcgen05.fence::after_thread_sync;" ::: "memory")
#define TC_FENCE_BEFORE() asm volatile("tcgen05.fence::before_thread_sync;" ::: "memory")
#define TC_WAIT_LD() asm volatile("tcgen05.wait::ld.sync.aligned;" ::: "memory")
#define FENCE_ASYNC_SHARED() asm volatile("fence.proxy.async.shared::cta;" ::: "memory")
#define TC_LD_X32(r, tmem_addr) \
    asm volatile("tcgen05.ld.sync.aligned.32x32b.x32.b32 " \
        "{%0, %1, %2, %3, %4, %5, %6, %7, %8, %9, %10, %11, %12, %13, %14, %15, " \
        " %16, %17, %18, %19, %20, %21, %22, %23, %24, %25, %26, %27, %28, %29, %30, %31}, [%32];" \
        : "=r"((r)[0]),  "=r"((r)[1]),  "=r"((r)[2]),  "=r"((r)[3]), \
          "=r"((r)[4]),  "=r"((r)[5]),  "=r"((r)[6]),  "=r"((r)[7]), \
          "=r"((r)[8]),  "=r"((r)[9]),  "=r"((r)[10]), "=r"((r)[11]), \
          "=r"((r)[12]), "=r"((r)[13]), "=r"((r)[14]), "=r"((r)[15]), \
          "=r"((r)[16]), "=r"((r)[17]), "=r"((r)[18]), "=r"((r)[19]), \
          "=r"((r)[20]), "=r"((r)[21]), "=r"((r)[22]), "=r"((r)[23]), \
          "=r"((r)[24]), "=r"((r)[25]), "=r"((r)[26]), "=r"((r)[27]), \
          "=r"((r)[28]), "=r"((r)[29]), "=r"((r)[30]), "=r"((r)[31]) \
        : "r"(tmem_addr))

__device__ __forceinline__ uint64_t mk_desc(uint32_t addr) {
    const uint64_t base = (2ull << 61) | (1ull << 46) | (64ull << 32) | (1ull << 16);
    return base | ((uint64_t)(addr >> 4) & 0x3FFF);
}
__device__ __forceinline__ void mma_f16_ss(uint32_t d, uint64_t da, uint64_t db,
                                           uint32_t idesc, uint32_t en) {
    asm volatile(
        "{\n\t.reg .pred p;\n\tsetp.ne.u32 p, %5, 0;\n\t"
        "tcgen05.mma.cta_group::1.kind::f16 [%0], %1, %2, %3, {%4,%4,%4,%4}, p;\n\t}"
        :: "r"(d), "l"(da), "l"(db), "r"(idesc), "r"(0u), "r"(en) : "memory");
}

#define GM_IDESC 0x8400010u              // F32 acc, fp16 a/b, M=128, N=256

__device__ __forceinline__ void gm_load_stage(
    uint32_t stb,
    const __half* __restrict__ A, const __half* __restrict__ B,
    int bm, int bn, int K, int kc, int tid)
{
    #pragma unroll
    for (int it = 0; it < 8; it++) {                 // A: 256 rows x 8 vec8
        int v = tid + it * 256;
        int r = v >> 3, cv = v & 7;
        uint32_t off = (uint32_t)((r & 127)*128 + cv*16);
        uint32_t sw = off ^ ((off >> 3) & 0x70);
        cpa16(stb + (uint32_t)(r >> 7)*16384 + sw,
              A + (size_t)(bm + r) * K + kc + cv*8);
    }
    #pragma unroll
    for (int it = 0; it < 8; it++) {                 // B: 256 rows x 8 vec8
        int v = tid + it * 256;
        int r = v >> 3, cv = v & 7;
        uint32_t off = (uint32_t)(r*128 + cv*16);
        uint32_t sw = off ^ ((off >> 3) & 0x70);
        cpa16(stb + 32768 + sw, B + (size_t)(bn + r) * K + kc + cv*8);
    }
    CP_COMMIT();
}

__global__ __launch_bounds__(256, 1) void tc_gemm(
    const __half* __restrict__ A, const __half* __restrict__ B,
    float* __restrict__ C, const float* __restrict__ addend,
    int M, int N, int K)
{
    extern __shared__ char smem[];
    uint32_t sb = smem_u32(smem);
    int tid = threadIdx.x;
    int wid = tid >> 5, lane = tid & 31;
    int bn = blockIdx.x * 256, bm = blockIdx.y * 256;

    if (wid == 0) { TC_ALLOC(sb, 512); TC_RELINQ(); }
    if (tid == 0) { MBAR_INIT(sb + 8, 1); MBAR_INIT(sb + 16, 1); }
    __syncthreads();
    uint32_t tmem;
    asm volatile("ld.shared.b32 %0, [%1];" : "=r"(tmem) : "r"(sb));

    const int NC = K / 64;
    int ph0 = 0, ph1 = 0;

    gm_load_stage(sb + 1024, A, B, bm, bn, K, 0, tid);

    for (int c = 0; c < NC; c++) {
        int s = c & 1;
        CP_WAIT0();
        __syncthreads();
        uint32_t stb = sb + 1024 + (uint32_t)s * GM_STAGE_BYTES;
        if (wid == 0 && elect_one_pred()) {
            FENCE_ASYNC_SHARED();
            uint64_t dA0 = mk_desc(stb);
            uint64_t dA1 = mk_desc(stb + 16384);
            uint64_t dB  = mk_desc(stb + 32768);
            #pragma unroll
            for (int k = 0; k < 4; k++) {
                uint32_t en = (c > 0) || (k > 0);
                mma_f16_ss(tmem,       dA0 + k*2, dB + k*2, GM_IDESC, en);
                mma_f16_ss(tmem + 256, dA1 + k*2, dB + k*2, GM_IDESC, en);
            }
            TC_COMMIT(sb + 8 + (uint32_t)s * 8);
        }
        if (c + 1 < NC) {
            int s2 = (c + 1) & 1;
            if (c >= 1) {
                if (s2 == 0) { MBAR_WAIT(sb + 8, ph0);  ph0 ^= 1; }
                else         { MBAR_WAIT(sb + 16, ph1); ph1 ^= 1; }
            }
            gm_load_stage(sb + 1024 + (uint32_t)s2 * GM_STAGE_BYTES,
                          A, B, bm, bn, K, (c + 1) * 64, tid);
        }
    }
    int sl = (NC - 1) & 1;
    if (sl == 0) { MBAR_WAIT(sb + 8, ph0); } else { MBAR_WAIT(sb + 16, ph1); }
    TC_FENCE_AFTER();

    // epilogue: 2 M-halves; 8 warps each (wg = col half, ws = row group)
    int wg = wid >> 2, ws = wid & 3;
    #pragma unroll
    for (int h = 0; h < 2; h++) {
        size_t row = (size_t)(bm + h*128 + ws * 32 + lane);
        #pragma unroll
        for (int cb = 0; cb < 4; cb++) {
            uint32_t regs[32];
            TC_LD_X32(regs, tmem + (uint32_t)(h*256 + wg * 128 + cb * 32));
            TC_WAIT_LD();
            int col = bn + wg * 128 + cb * 32;
            float* Cp = C + row * (size_t)N + col;
            if (addend) {
                const float* Ap = addend + row * (size_t)N + col;
                #pragma unroll
                for (int j = 0; j < 32; j += 4) {
                    float4 a = *(const float4*)(Ap + j);
                    float4 o = make_float4(__uint_as_float(regs[j])   + a.x,
                                           __uint_as_float(regs[j+1]) + a.y,
                                           __uint_as_float(regs[j+2]) + a.z,
                                           __uint_as_float(regs[j+3]) + a.w);
                    *(float4*)(Cp + j) = o;
                }
            } else {
                #pragma unroll
                for (int j = 0; j < 32; j += 4) {
                    float4 o = make_float4(__uint_as_float(regs[j]),
                                           __uint_as_float(regs[j+1]),
                                           __uint_as_float(regs[j+2]),
                                           __uint_as_float(regs[j+3]));
                    *(float4*)(Cp + j) = o;
                }
            }
        }
    }
    TC_FENCE_BEFORE();
    __syncthreads();
    if (tid == 0) { MBAR_INVAL(sb + 8); MBAR_INVAL(sb + 16); }
    if (wid == 0) { TC_DEALLOC(tmem, 512); }
}

#else
// ======================= mma.sync GEMM fallback ==============================
#define FB_LD 40

__global__ __launch_bounds__(256, 1) void tc_gemm(
    const __half* __restrict__ A, const __half* __restrict__ B,
    float* __restrict__ C, const float* __restrict__ addend,
    int M, int N, int K)
{
    extern __shared__ char smem[];
    __half* sA = (__half*)smem;               // [128][40]
    __half* sB = sA + 128*FB_LD;              // [256][40]
    int tid = threadIdx.x, lane = tid & 31, wid = tid >> 5;
    int bn = blockIdx.x * 256;
    int wm = wid >> 2, wn = wid & 3;
    int g = lane >> 2, tig = lane & 3;

    for (int half = 0; half < 2; half++) {
        int bm = blockIdx.y * 256 + half * 128;
        float acc[4][8][4];
        #pragma unroll
        for (int mt = 0; mt < 4; mt++)
            #pragma unroll
            for (int nt = 0; nt < 8; nt++)
                #pragma unroll
                for (int q = 0; q < 4; q++) acc[mt][nt][q] = 0.f;

        for (int k0 = 0; k0 < K; k0 += 32) {
            __syncthreads();
            for (int v = tid; v < 512; v += 256) {
                int r = v >> 2, q = v & 3;
                *(uint4*)&sA[r*FB_LD + q*8] = *(const uint4*)(A + (size_t)(bm+r)*K + k0 + q*8);
            }
            for (int v = tid; v < 1024; v += 256) {
                int r = v >> 2, q = v & 3;
                *(uint4*)&sB[r*FB_LD + q*8] = *(const uint4*)(B + (size_t)(bn+r)*K + k0 + q*8);
            }
            __syncthreads();
            #pragma unroll
            for (int ks = 0; ks < 2; ks++) {
                int kk = ks * 16 + tig * 2;
                uint32_t a[4][4], b[8][2];
                #pragma unroll
                for (int mt = 0; mt < 4; mt++) {
                    int mr = (wm*64 + mt*16 + g)*FB_LD + kk;
                    a[mt][0] = *(const uint32_t*)&sA[mr];
                    a[mt][1] = *(const uint32_t*)&sA[mr + 8*FB_LD];
                    a[mt][2] = *(const uint32_t*)&sA[mr + 8];
                    a[mt][3] = *(const uint32_t*)&sA[mr + 8*FB_LD + 8];
                }
                #pragma unroll
                for (int nt = 0; nt < 8; nt++) {
                    int nr = (wn*64 + nt*8 + g)*FB_LD + kk;
                    b[nt][0] = *(const uint32_t*)&sB[nr];
                    b[nt][1] = *(const uint32_t*)&sB[nr + 8];
                }
                #pragma unroll
                for (int mt = 0; mt < 4; mt++)
                    #pragma unroll
                    for (int nt = 0; nt < 8; nt++)
                        mma16816(acc[mt][nt], a[mt], b[nt]);
            }
        }
        #pragma unroll
        for (int mt = 0; mt < 4; mt++) {
            #pragma unroll
            for (int nt = 0; nt < 8; nt++) {
                size_t r0 = (size_t)(bm + wm*64 + mt*16 + g);
                int col = bn + wn*64 + nt*8 + tig*2;
                float2 v0 = make_float2(acc[mt][nt][0], acc[mt][nt][1]);
                float2 v1 = make_float2(acc[mt][nt][2], acc[mt][nt][3]);
                if (addend) {
                    float2 a0 = *(const float2*)(addend + r0*N + col);
                    float2 a1 = *(const float2*)(addend + (r0+8)*N + col);
                    v0.x += a0.x; v0.y += a0.y; v1.x += a1.x; v1.y += a1.y;
                }
                *(float2*)(C + r0*N + col)     = v0;
                *(float2*)(C + (r0+8)*N + col) = v1;
            }
        }
        __syncthreads();
    }
}
#endif  // USE_TCGEN05

// ---------------- RMSNorm -> fp16 --------------------------------------------
__global__ __launch_bounds__(256) void rmsnorm_h_kernel(
    const float* __restrict__ x, const float* __restrict__ w,
    __half* __restrict__ out)
{
    __shared__ float red[8];
    int row = blockIdx.x;
    int tid = threadIdx.x;
    const float4* xr = (const float4*)(x + (size_t)row * EMBED);
    const float4* w4 = (const float4*)w;
    float4 v0 = xr[tid];
    float4 v1 = xr[tid + 256];
    float ss = v0.x*v0.x + v0.y*v0.y + v0.z*v0.z + v0.w*v0.w
             + v1.x*v1.x + v1.y*v1.y + v1.z*v1.z + v1.w*v1.w;
    #pragma unroll
    for (int o = 16; o > 0; o >>= 1) ss += __shfl_xor_sync(0xffffffffu, ss, o);
    if ((tid & 31) == 0) red[tid >> 5] = ss;
    __syncthreads();
    float tot = red[0] + red[1] + red[2] + red[3] + red[4] + red[5] + red[6] + red[7];
    float inv = rsqrtf(tot * (1.0f / EMBED) + 1e-5f);
    float4 wa = w4[tid], wb = w4[tid + 256];
    __half2* O = (__half2*)(out + (size_t)row * EMBED);
    O[2*tid]         = __floats2half2_rn(v0.x*inv*wa.x, v0.y*inv*wa.y);
    O[2*tid+1]       = __floats2half2_rn(v0.z*inv*wa.z, v0.w*inv*wa.w);
    O[2*(tid+256)]   = __floats2half2_rn(v1.x*inv*wb.x, v1.y*inv*wb.y);
    O[2*(tid+256)+1] = __floats2half2_rn(v1.z*inv*wb.z, v1.w*inv*wb.w);
}

// ---------------- RoPE + head transpose -> fp16 ------------------------------
__global__ __launch_bounds__(256) void rope_kernel(
    const float* __restrict__ qkv, const float* __restrict__ freqs,
    __half* __restrict__ qh, __half* __restrict__ kh, __half* __restrict__ vh)
{
    int s = blockIdx.x, b = blockIdx.y, tid = threadIdx.x;
    const float* row = qkv + ((size_t)b * SS + s) * QKV_N;
    const float* f = freqs + (size_t)s * HD;
    const float scale = 0.02209708691207961f;   // 1/sqrt(2048), folded into Q

    for (int p = tid; p < NH * 64; p += 256) {
        int h = p >> 6, i = p & 63;
        float x0 = row[h*HD + 2*i], x1 = row[h*HD + 2*i + 1];
        float c = f[2*i], sn = f[2*i+1];
        __half2* dst = (__half2*)(qh + ((size_t)(b*NH + h) * SS + s) * HD + 2*i);
        *dst = __floats2half2_rn((x0*c - x1*sn) * scale, (x1*c + x0*sn) * scale);
    }
    for (int p = tid; p < NKV * 64; p += 256) {
        int h = p >> 6, i = p & 63;
        float x0 = row[NH*HD + h*HD + 2*i], x1 = row[NH*HD + h*HD + 2*i + 1];
        float c = f[2*i], sn = f[2*i+1];
        __half2* dst = (__half2*)(kh + ((size_t)(b*NKV + h) * SS + s) * HD + 2*i);
        *dst = __floats2half2_rn(x0*c - x1*sn, x1*c + x0*sn);
    }
    for (int p = tid; p < NKV * HD; p += 256) {
        int h = p >> 7, d = p & 127;
        vh[((size_t)(b*NKV + h) * HD + d) * SS + s] =
            __float2half_rn(row[(NH + NKV)*HD + p]);
    }
}

// ---------------- Tensor-core flash attention (fp16 mma, fp32 softmax) -------
#define FLH_SMEM_BYTES ((128*136 + 64*136 + 128*72) * 2)
__global__ __launch_bounds__(256) void flash_tc_kernel(
    const __half* __restrict__ qh, const __half* __restrict__ kh,
    const __half* __restrict__ vh, __half* __restrict__ oh)
{
    extern __shared__ __half smh[];
    __half* Qs = smh;                  // [128][136]
    __half* Ks = Qs + 128*136;         // [64][136]
    __half* Vs = Ks + 64*136;          // [128][72]  (Vt: [d][kc])
    int tid = threadIdx.x, lane = tid & 31, wid = tid >> 5;
    int g = lane >> 2, tig = lane & 3;
    int qb = blockIdx.x, hb = blockIdx.y, bb = blockIdx.z;
    uint32_t ks_b = smem_u32(Ks), vs_b = smem_u32(Vs);

    const __half* Qg = qh + ((size_t)(bb*NH + hb) * SS + (size_t)qb*128) * HD;
    const __half* Kg = kh + (size_t)(bb*NKV + (hb >> 2)) * SS * HD;
    const __half* Vg = vh + (size_t)(bb*NKV + (hb >> 2)) * HD * SS;

    for (int i = tid; i < 128*16; i += 256) {
        int r = i >> 4, c = i & 15;
        *(uint4*)&Qs[r*136 + c*8] = *(const uint4*)(Qg + r*HD + c*8);
    }

    float accO[16][4];
    #pragma unroll
    for (int nd = 0; nd < 16; nd++)
        #pragma unroll
        for (int q = 0; q < 4; q++) accO[nd][q] = 0.f;
    float m0 = -1e30f, m1 = -1e30f, l0 = 0.f, l1 = 0.f;
    int r0 = qb*128 + wid*16 + g;
    int r1 = r0 + 8;

    int nkb = 2*(qb + 1);
    for (int kb = 0; kb < nkb; kb++) {
        __syncthreads();
        for (int i = tid; i < 64*16; i += 256) {
            int r = i >> 4, c = i & 15;
            cpa16(ks_b + (uint32_t)(r*136 + c*8)*2,
                  Kg + (size_t)(kb*64 + r)*HD + c*8);
        }
        for (int i = tid; i < 128*8; i += 256) {
            int r = i >> 3, c = i & 7;
            cpa16(vs_b + (uint32_t)(r*72 + c*8)*2,
                  Vg + (size_t)r*SS + kb*64 + c*8);
        }
        CP_COMMIT(); CP_WAIT0();
        __syncthreads();

        float sacc[8][4];
        #pragma unroll
        for (int nt = 0; nt < 8; nt++)
            #pragma unroll
            for (int q = 0; q < 4; q++) sacc[nt][q] = 0.f;
        #pragma unroll
        for (int ks = 0; ks < 8; ks++) {
            uint32_t a[4];
            const __half* qr = &Qs[(wid*16 + g)*136 + ks*16 + 2*tig];
            a[0] = *(const uint32_t*)qr;
            a[1] = *(const uint32_t*)(qr + 8*136);
            a[2] = *(const uint32_t*)(qr + 8);
            a[3] = *(const uint32_t*)(qr + 8*136 + 8);
            #pragma unroll
            for (int nt = 0; nt < 8; nt++) {
                uint32_t b[2];
                const __half* kr = &Ks[(nt*8 + g)*136 + ks*16 + 2*tig];
                b[0] = *(const uint32_t*)kr;
                b[1] = *(const uint32_t*)(kr + 8);
                mma16816(sacc[nt], a, b);
            }
        }
        if (kb >= 2*qb) {
            #pragma unroll
            for (int nt = 0; nt < 8; nt++) {
                int col = kb*64 + nt*8 + 2*tig;
                if (col     > r0) sacc[nt][0] = -1e30f;
                if (col + 1 > r0) sacc[nt][1] = -1e30f;
                if (col     > r1) sacc[nt][2] = -1e30f;
                if (col + 1 > r1) sacc[nt][3] = -1e30f;
            }
        }
        float mx0 = -1e30f, mx1 = -1e30f;
        #pragma unroll
        for (int nt = 0; nt < 8; nt++) {
            mx0 = fmaxf(mx0, fmaxf(sacc[nt][0], sacc[nt][1]));
            mx1 = fmaxf(mx1, fmaxf(sacc[nt][2], sacc[nt][3]));
        }
        mx0 = fmaxf(mx0, __shfl_xor_sync(0xffffffffu, mx0, 1));
        mx0 = fmaxf(mx0, __shfl_xor_sync(0xffffffffu, mx0, 2));
        mx1 = fmaxf(mx1, __shfl_xor_sync(0xffffffffu, mx1, 1));
        mx1 = fmaxf(mx1, __shfl_xor_sync(0xffffffffu, mx1, 2));
        float nm0 = fmaxf(m0, mx0), nm1 = fmaxf(m1, mx1);
        float f0 = __expf(m0 - nm0), f1 = __expf(m1 - nm1);
        m0 = nm0; m1 = nm1;
        float s0 = 0.f, s1 = 0.f;
        #pragma unroll
        for (int nt = 0; nt < 8; nt++) {
            float p0 = __expf(sacc[nt][0] - m0);
            float p1 = __expf(sacc[nt][1] - m0);
            float p2 = __expf(sacc[nt][2] - m1);
            float p3 = __expf(sacc[nt][3] - m1);
            sacc[nt][0] = p0; sacc[nt][1] = p1; sacc[nt][2] = p2; sacc[nt][3] = p3;
            s0 += p0 + p1; s1 += p2 + p3;
        }
        s0 += __shfl_xor_sync(0xffffffffu, s0, 1);
        s0 += __shfl_xor_sync(0xffffffffu, s0, 2);
        s1 += __shfl_xor_sync(0xffffffffu, s1, 1);
        s1 += __shfl_xor_sync(0xffffffffu, s1, 2);
        l0 = l0*f0 + s0; l1 = l1*f1 + s1;
        #pragma unroll
        for (int nd = 0; nd < 16; nd++) {
            accO[nd][0] *= f0; accO[nd][1] *= f0;
            accO[nd][2] *= f1; accO[nd][3] *= f1;
        }
        #pragma unroll
        for (int j = 0; j < 4; j++) {
            uint32_t a[4];
            __half2 t;
            t = __floats2half2_rn(sacc[2*j][0],   sacc[2*j][1]);   a[0] = *(uint32_t*)&t;
            t = __floats2half2_rn(sacc[2*j][2],   sacc[2*j][3]);   a[1] = *(uint32_t*)&t;
            t = __floats2half2_rn(sacc[2*j+1][0], sacc[2*j+1][1]); a[2] = *(uint32_t*)&t;
            t = __floats2half2_rn(sacc[2*j+1][2], sacc[2*j+1][3]); a[3] = *(uint32_t*)&t;
            #pragma unroll
            for (int nd = 0; nd < 16; nd++) {
                uint32_t b[2];
                const __half* vr = &Vs[(nd*8 + g)*72 + j*16 + 2*tig];
                b[0] = *(const uint32_t*)vr;
                b[1] = *(const uint32_t*)(vr + 8);
                mma16816(accO[nd], a, b);
            }
        }
    }
    // epilogue: O /= l -> fp16 via smem staging
    float inv0 = 1.f / l0, inv1 = 1.f / l1;
    __half* st = smh;   // [128][136]
    int lr = wid*16 + g;
    size_t obase = ((size_t)bb*SS + (size_t)qb*128) * EMBED + hb*HD;
    __syncthreads();
    #pragma unroll
    for (int nd = 0; nd < 16; nd++) {
        int col = nd*8 + 2*tig;
        *(__half2*)&st[lr*136 + col] =
            __floats2half2_rn(accO[nd][0]*inv0, accO[nd][1]*inv0);
        *(__half2*)&st[(lr+8)*136 + col] =
            __floats2half2_rn(accO[nd][2]*inv1, accO[nd][3]*inv1);
    }
    __syncthreads();
    for (int i = tid; i < 128*16; i += 256) {
        int r = i >> 4, c = i & 15;
        *(uint4*)(oh + obase + (size_t)r*EMBED + c*8) = *(uint4*)&st[r*136 + c*8];
    }
}

// ---------------- SwiGLU -> fp16 ---------------------------------------------
__global__ __launch_bounds__(256) void silu_h_kernel(
    const float* __restrict__ u1, const float* __restrict__ u2,
    __half* __restrict__ out, int n4)
{
    int i = blockIdx.x * 256 + threadIdx.x;
    if (i >= n4) return;
    float4 a = ((const float4*)u1)[i];
    float4 b = ((const float4*)u2)[i];
    float r0 = a.x / (1.f + __expf(-a.x)) * b.x;
    float r1 = a.y / (1.f + __expf(-a.y)) * b.y;
    float r2 = a.z / (1.f + __expf(-a.z)) * b.z;
    float r3 = a.w / (1.f + __expf(-a.w)) * b.w;
    __half2* O = (__half2*)out;
    O[2*i]   = __floats2half2_rn(r0, r1);
    O[2*i+1] = __floats2half2_rn(r2, r3);
}

// ---------------- driver ------------------------------------------------------
static inline void conv_launch(const float* src, __half* dst, size_t n)
{
    int n4 = (int)(n / 4);
    conv_kernel<<<(n4 + 255)/256, 256>>>(src, dst, n4);
}

extern "C" void kernel_launch(void* const* d_in, const int* in_sizes, int n_in,
                              void* d_out, int out_size)
{
    const float* x       = (const float*)d_in[0];
    const float* freqs   = (const float*)d_in[2];
    const float* w_qkv   = (const float*)d_in[4];
    const float* w_fc    = (const float*)d_in[5];
    const float* w1      = (const float*)d_in[6];
    const float* w2      = (const float*)d_in[7];
    const float* w3      = (const float*)d_in[8];
    const float* attn_nw = (const float*)d_in[9];
    const float* ff_nw   = (const float*)d_in[10];
    float* out = (float*)d_out;

    float *qkv, *h1, *u1, *u2;
    __half *qh, *kh, *vh, *ah, *wh;
    cudaGetSymbolAddress((void**)&qkv, g_qkv);
    cudaGetSymbolAddress((void**)&qh,  g_qh2);
    cudaGetSymbolAddress((void**)&kh,  g_kh2);
    cudaGetSymbolAddress((void**)&vh,  g_vh2);
    cudaGetSymbolAddress((void**)&h1,  g_h1);
    cudaGetSymbolAddress((void**)&u1,  g_u1);
    cudaGetSymbolAddress((void**)&u2,  g_u2);
    cudaGetSymbolAddress((void**)&ah,  g_ah);
    cudaGetSymbolAddress((void**)&wh,  g_wh);

    cudaFuncSetAttribute(tc_gemm, cudaFuncAttributeMaxDynamicSharedMemorySize, GM_SMEM_BYTES);
    cudaFuncSetAttribute(flash_tc_kernel, cudaFuncAttributeMaxDynamicSharedMemorySize, FLH_SMEM_BYTES);

    // 1. attn rmsnorm -> fp16
    rmsnorm_h_kernel<<<ROWS, 256>>>(x, attn_nw, ah);
    // 2. qkv projection
    conv_launch(w_qkv, wh, (size_t)QKV_N*EMBED);
    tc_gemm<<<dim3(QKV_N/256, ROWS/256), 256, GM_SMEM_BYTES>>>(
        ah, wh, qkv, nullptr, ROWS, QKV_N, EMBED);
    // 3. rope + transpose -> fp16
    rope_kernel<<<dim3(SS, BB), 256>>>(qkv, freqs, qh, kh, vh);
    // 4. tensor-core flash attention -> fp16 attn into g_ah
    flash_tc_kernel<<<dim3(SS/128, NH, BB), 256, FLH_SMEM_BYTES>>>(qh, kh, vh, ah);
    // 5. output projection + residual
    conv_launch(w_fc, wh, (size_t)EMBED*EMBED);
    tc_gemm<<<dim3(EMBED/256, ROWS/256), 256, GM_SMEM_BYTES>>>(
        ah, wh, h1, x, ROWS, EMBED, EMBED);
    // 6. ffn rmsnorm -> fp16
    rmsnorm_h_kernel<<<ROWS, 256>>>(h1, ff_nw, ah);
    // 7-8. gate / up projections
    conv_launch(w1, wh, (size_t)FF*EMBED);
    tc_gemm<<<dim3(FF/256, ROWS/256), 256, GM_SMEM_BYTES>>>(
        ah, wh, u1, nullptr, ROWS, FF, EMBED);
    conv_launch(w2, wh, (size_t)FF*EMBED);
    tc_gemm<<<dim3(FF/256, ROWS/256), 256, GM_SMEM_BYTES>>>(
        ah, wh, u2, nullptr, ROWS, FF, EMBED);
    // 9. swiglu -> fp16
    silu_h_kernel<<<(ROWS*FF/4 + 255)/256, 256>>>(u1, u2, ah, ROWS*FF/4);
    // 10. down projection + residual -> out
    conv_launch(w3, wh, (size_t)EMBED*FF);
    tc_gemm<<<dim3(EMBED/256, ROWS/256), 256, GM_SMEM_BYTES>>>(
        ah, wh, out, h1, ROWS, EMBED, FF);
}

// round 8
// speedup vs baseline: 24.7320x; 1.3438x over previous
#include <cuda_runtime.h>
#include <cuda_bf16.h>
#include <cuda_fp16.h>
#include <math.h>
#include <stdint.h>

#define EMBED 2048
#define NH 16
#define NKV 4
#define HD 128
#define FF 5632
#define BB 2
#define SS 2048
#define ROWS (BB*SS)                 // 4096 tokens
#define QKV_N ((NH + 2*NKV)*HD)      // 3072

#if defined(__CUDA_ARCH_FEAT_SM103_ALL) || defined(__CUDA_ARCH_FEAT_SM100_ALL)
#define USE_TCGEN05 1
#else
#define USE_TCGEN05 0
#endif

// ---------------- scratch (device globals; no allocations allowed) ----------
__device__ __half g_qkvh[ROWS*QKV_N];     // fp16 qkv gemm output
__device__ __half g_qh2[BB*NH *SS*HD];    // fp16 Q (scaled), [b,h,s,d]
__device__ __half g_kh2[BB*NKV*SS*HD];    // fp16 K, [b,kvh,s,d]
__device__ __half g_vh2[BB*NKV*HD*SS];    // fp16 V transposed, [b,kvh,d,s]
__device__ float  g_h1 [ROWS*EMBED];
__device__ __half g_uh [ROWS*2*FF];       // fp16 combined gate|up
__device__ __half g_ah [ROWS*FF];         // fp16 activations (gemm A operand)
__device__ __half g_wh [2*FF*EMBED];      // fp16 weights     (gemm B operand)

#define GM_STAGE_BYTES 65536              // A0 16K + A1 16K + B 32K
#define GM_NSTAGE 3
#define GM_SMEM_BYTES (1024 + GM_NSTAGE*GM_STAGE_BYTES)

// ---------- common helpers (legal on plain sm_103 PTX) ----------------------
__device__ __forceinline__ uint32_t smem_u32(const void* p) {
    uint32_t a;
    asm("{ .reg .u64 t; cvta.to.shared.u64 t, %1; cvt.u32.u64 %0, t; }" : "=r"(a) : "l"(p));
    return a;
}
#define CP_COMMIT() asm volatile("cp.async.commit_group;" ::: "memory")
#define CP_WAIT0()  asm volatile("cp.async.wait_group 0;" ::: "memory")
#define CP_WAIT1()  asm volatile("cp.async.wait_group 1;" ::: "memory")
__device__ __forceinline__ void cpa16(uint32_t saddr, const void* g) {
    asm volatile("cp.async.cg.shared.global [%0], [%1], 16;" :: "r"(saddr), "l"(g) : "memory");
}
__device__ __forceinline__ void mma16816(float* c, const uint32_t* a, const uint32_t* b) {
    asm volatile("mma.sync.aligned.m16n8k16.row.col.f32.f16.f16.f32 "
        "{%0,%1,%2,%3}, {%4,%5,%6,%7}, {%8,%9}, {%0,%1,%2,%3};"
        : "+f"(c[0]), "+f"(c[1]), "+f"(c[2]), "+f"(c[3])
        : "r"(a[0]), "r"(a[1]), "r"(a[2]), "r"(a[3]), "r"(b[0]), "r"(b[1]));
}

// ======================= fp32 -> fp16 convert (weights) ======================
__global__ __launch_bounds__(256) void conv_kernel(
    const float* __restrict__ x, __half* __restrict__ y, int n4)
{
    int i = blockIdx.x * 256 + threadIdx.x;
    if (i >= n4) return;
    float4 v = ((const float4*)x)[i];
    __half2* Y = (__half2*)y;
    Y[2*i]   = __floats2half2_rn(v.x, v.y);
    Y[2*i+1] = __floats2half2_rn(v.z, v.w);
}

#if USE_TCGEN05
// ======================= tcgen05 GEMM (sm_103a pass) =========================
// C = A[M,K] * B[N,K]^T ; fp16 operands, fp32 TMEM accum.
// Output: Ch (fp16) if non-null, else Cf fp32 (+addend).
// Tile: BM=256 (two M=128 halves sharing B), BN=256, BK=64; 3-stage cp.async.
__device__ __forceinline__ uint32_t elect_one_pred() {
    uint32_t pred;
    asm volatile(
        "{\n\t.reg .pred p;\n\telect.sync _|p, 0xFFFFFFFF;\n\tselp.b32 %0, 1, 0, p;\n\t}"
        : "=r"(pred));
    return pred;
}
#define MBAR_INIT(addr, cnt) \
    asm volatile("mbarrier.init.shared.b64 [%0], %1;" :: "r"(addr), "r"((uint32_t)(cnt)) : "memory")
#define MBAR_INVAL(addr) \
    asm volatile("mbarrier.inval.shared.b64 [%0];" :: "r"(addr) : "memory")
#define MBAR_WAIT(addr, parity) do { \
    uint32_t _m = (addr); uint32_t _p = (parity); uint32_t _d; \
    asm volatile("{\n\t.reg .pred p;\n\tmbarrier.try_wait.parity.acquire.cta.shared::cta.b64 p, [%1], %2;\n\tselp.b32 %0, 1, 0, p;\n\t}" \
        : "=r"(_d) : "r"(_m), "r"(_p) : "memory"); \
    if (!_d) { \
        asm volatile("{\n\t.reg .pred P1;\n\tWL_%=:\n\tmbarrier.try_wait.parity.acquire.cta.shared::cta.b64 P1, [%0], %1, 0x989680;\n\t@P1 bra.uni WD_%=;\n\tbra.uni WL_%=;\n\tWD_%=:\n\t}" \
            :: "r"(_m), "r"(_p) : "memory"); \
    } } while(0)
#define TC_ALLOC(smem_addr, n) \
    asm volatile("tcgen05.alloc.cta_group::1.sync.aligned.shared::cta.b32 [%0], %1;" \
        :: "r"((uint32_t)(smem_addr)), "r"((uint32_t)(n)) : "memory")
#define TC_DEALLOC(tmem_addr, n) \
    asm volatile("tcgen05.dealloc.cta_group::1.sync.aligned.b32 %0, %1;" :: "r"(tmem_addr), "r"((uint32_t)(n)))
#define TC_RELINQ() \
    asm volatile("tcgen05.relinquish_alloc_permit.cta_group::1.sync.aligned;")
#define TC_COMMIT(mbar) \
    asm volatile("tcgen05.commit.cta_group::1.mbarrier::arrive::one.shared::cluster.b64 [%0];" \
        :: "r"((uint32_t)(mbar)) : "memory")
#define TC_FENCE_AFTER() asm volatile("tcgen05.fence::after_thread_sync;" ::: "memory")
#define TC_FENCE_BEFORE() asm volatile("tcgen05.fence::before_thread_sync;" ::: "memory")
#define TC_WAIT_LD() asm volatile("tcgen05.wait::ld.sync.aligned;" ::: "memory")
#define FENCE_ASYNC_SHARED() asm volatile("fence.proxy.async.shared::cta;" ::: "memory")
#define TC_LD_X32(r, tmem_addr) \
    asm volatile("tcgen05.ld.sync.aligned.32x32b.x32.b32 " \
        "{%0, %1, %2, %3, %4, %5, %6, %7, %8, %9, %10, %11, %12, %13, %14, %15, " \
        " %16, %17, %18, %19, %20, %21, %22, %23, %24, %25, %26, %27, %28, %29, %30, %31}, [%32];" \
        : "=r"((r)[0]),  "=r"((r)[1]),  "=r"((r)[2]),  "=r"((r)[3]), \
          "=r"((r)[4]),  "=r"((r)[5]),  "=r"((r)[6]),  "=r"((r)[7]), \
          "=r"((r)[8]),  "=r"((r)[9]),  "=r"((r)[10]), "=r"((r)[11]), \
          "=r"((r)[12]), "=r"((r)[13]), "=r"((r)[14]), "=r"((r)[15]), \
          "=r"((r)[16]), "=r"((r)[17]), "=r"((r)[18]), "=r"((r)[19]), \
          "=r"((r)[20]), "=r"((r)[21]), "=r"((r)[22]), "=r"((r)[23]), \
          "=r"((r)[24]), "=r"((r)[25]), "=r"((r)[26]), "=r"((r)[27]), \
          "=r"((r)[28]), "=r"((r)[29]), "=r"((r)[30]), "=r"((r)[31]) \
        : "r"(tmem_addr))

__device__ __forceinline__ uint64_t mk_desc(uint32_t addr) {
    const uint64_t base = (2ull << 61) | (1ull << 46) | (64ull << 32) | (1ull << 16);
    return base | ((uint64_t)(addr >> 4) & 0x3FFF);
}
__device__ __forceinline__ void mma_f16_ss(uint32_t d, uint64_t da, uint64_t db,
                                           uint32_t idesc, uint32_t en) {
    asm volatile(
        "{\n\t.reg .pred p;\n\tsetp.ne.u32 p, %5, 0;\n\t"
        "tcgen05.mma.cta_group::1.kind::f16 [%0], %1, %2, %3, {%4,%4,%4,%4}, p;\n\t}"
        :: "r"(d), "l"(da), "l"(db), "r"(idesc), "r"(0u), "r"(en) : "memory");
}

#define GM_IDESC 0x8400010u              // F32 acc, fp16 a/b, M=128, N=256

__device__ __forceinline__ void gm_load_stage(
    uint32_t stb,
    const __half* __restrict__ A, const __half* __restrict__ B,
    int bm, int bn, int K, int kc, int tid)
{
    #pragma unroll
    for (int it = 0; it < 8; it++) {                 // A: 256 rows x 8 vec8
        int v = tid + it * 256;
        int r = v >> 3, cv = v & 7;
        uint32_t off = (uint32_t)((r & 127)*128 + cv*16);
        uint32_t sw = off ^ ((off >> 3) & 0x70);
        cpa16(stb + (uint32_t)(r >> 7)*16384 + sw,
              A + (size_t)(bm + r) * K + kc + cv*8);
    }
    #pragma unroll
    for (int it = 0; it < 8; it++) {                 // B: 256 rows x 8 vec8
        int v = tid + it * 256;
        int r = v >> 3, cv = v & 7;
        uint32_t off = (uint32_t)(r*128 + cv*16);
        uint32_t sw = off ^ ((off >> 3) & 0x70);
        cpa16(stb + 32768 + sw, B + (size_t)(bn + r) * K + kc + cv*8);
    }
    CP_COMMIT();
}

__global__ __launch_bounds__(256, 1) void tc_gemm(
    const __half* __restrict__ A, const __half* __restrict__ B,
    float* __restrict__ Cf, __half* __restrict__ Ch,
    const float* __restrict__ addend,
    int M, int N, int K)
{
    extern __shared__ char smem[];
    uint32_t sb = smem_u32(smem);
    int tid = threadIdx.x;
    int wid = tid >> 5, lane = tid & 31;
    int bn = blockIdx.x * 256, bm = blockIdx.y * 256;

    if (wid == 0) { TC_ALLOC(sb, 512); TC_RELINQ(); }
    if (tid == 0) { MBAR_INIT(sb + 8, 1); MBAR_INIT(sb + 16, 1); MBAR_INIT(sb + 24, 1); }
    __syncthreads();
    uint32_t tmem;
    asm volatile("ld.shared.b32 %0, [%1];" : "=r"(tmem) : "r"(sb));

    const int NC = K / 64;
    int ph0 = 0, ph1 = 0;

    gm_load_stage(sb + 1024, A, B, bm, bn, K, 0, tid);
    gm_load_stage(sb + 1024 + GM_STAGE_BYTES, A, B, bm, bn, K, 64, tid);

    for (int c = 0; c < NC; c++) {
        int s = c % GM_NSTAGE;
        if (c + 1 < NC) { CP_WAIT1(); } else { CP_WAIT0(); }
        __syncthreads();
        uint32_t stb = sb + 1024 + (uint32_t)s * GM_STAGE_BYTES;
        if (wid == 0 && elect_one_pred()) {
            FENCE_ASYNC_SHARED();
            uint64_t dA0 = mk_desc(stb);
            uint64_t dA1 = mk_desc(stb + 16384);
            uint64_t dB  = mk_desc(stb + 32768);
            #pragma unroll
            for (int k = 0; k < 4; k++) {
                uint32_t en = (c > 0) || (k > 0);
                mma_f16_ss(tmem,       dA0 + k*2, dB + k*2, GM_IDESC, en);
                mma_f16_ss(tmem + 256, dA1 + k*2, dB + k*2, GM_IDESC, en);
            }
            TC_COMMIT(sb + 8 + (uint32_t)(c & 1) * 8);
            if (c == NC - 1) TC_COMMIT(sb + 24);   // dedicated final-completion mbar
        }
        if (c + 2 < NC) {
            // load of chunk c+2 reuses the stage consumed by MMA chunk c-1:
            // wait its commit (lockstep-safe: commit c+1 not yet issued here)
            if (c >= 1) {
                int m = (c - 1) & 1;
                if (m == 0) { MBAR_WAIT(sb + 8, ph0);  ph0 ^= 1; }
                else        { MBAR_WAIT(sb + 16, ph1); ph1 ^= 1; }
            }
            gm_load_stage(sb + 1024 + (uint32_t)((c + 2) % GM_NSTAGE) * GM_STAGE_BYTES,
                          A, B, bm, bn, K, (c + 2) * 64, tid);
        }
    }
    // all MMAs done when the dedicated final mbar fires (first & only wait: parity 0)
    MBAR_WAIT(sb + 24, 0);
    TC_FENCE_AFTER();

    // epilogue: 2 M-halves; 8 warps (wg = col half, ws = row group)
    int wg = wid >> 2, ws = wid & 3;
    #pragma unroll
    for (int h = 0; h < 2; h++) {
        size_t row = (size_t)(bm + h*128 + ws * 32 + lane);
        #pragma unroll
        for (int cb = 0; cb < 4; cb++) {
            uint32_t regs[32];
            TC_LD_X32(regs, tmem + (uint32_t)(h*256 + wg * 128 + cb * 32));
            TC_WAIT_LD();
            int col = bn + wg * 128 + cb * 32;
            if (Ch) {
                __half* Cp = Ch + row * (size_t)N + col;
                #pragma unroll
                for (int j = 0; j < 32; j += 8) {
                    __half2 o[4];
                    o[0] = __floats2half2_rn(__uint_as_float(regs[j]),   __uint_as_float(regs[j+1]));
                    o[1] = __floats2half2_rn(__uint_as_float(regs[j+2]), __uint_as_float(regs[j+3]));
                    o[2] = __floats2half2_rn(__uint_as_float(regs[j+4]), __uint_as_float(regs[j+5]));
                    o[3] = __floats2half2_rn(__uint_as_float(regs[j+6]), __uint_as_float(regs[j+7]));
                    *(uint4*)(Cp + j) = *(uint4*)o;
                }
            } else {
                float* Cp = Cf + row * (size_t)N + col;
                if (addend) {
                    const float* Ap = addend + row * (size_t)N + col;
                    #pragma unroll
                    for (int j = 0; j < 32; j += 4) {
                        float4 a = *(const float4*)(Ap + j);
                        float4 o = make_float4(__uint_as_float(regs[j])   + a.x,
                                               __uint_as_float(regs[j+1]) + a.y,
                                               __uint_as_float(regs[j+2]) + a.z,
                                               __uint_as_float(regs[j+3]) + a.w);
                        *(float4*)(Cp + j) = o;
                    }
                } else {
                    #pragma unroll
                    for (int j = 0; j < 32; j += 4) {
                        float4 o = make_float4(__uint_as_float(regs[j]),
                                               __uint_as_float(regs[j+1]),
                                               __uint_as_float(regs[j+2]),
                                               __uint_as_float(regs[j+3]));
                        *(float4*)(Cp + j) = o;
                    }
                }
            }
        }
    }
    TC_FENCE_BEFORE();
    __syncthreads();
    if (tid == 0) { MBAR_INVAL(sb + 8); MBAR_INVAL(sb + 16); MBAR_INVAL(sb + 24); }
    if (wid == 0) { TC_DEALLOC(tmem, 512); }
}

#else
// ======================= mma.sync GEMM fallback ==============================
#define FB_LD 40

__global__ __launch_bounds__(256, 1) void tc_gemm(
    const __half* __restrict__ A, const __half* __restrict__ B,
    float* __restrict__ Cf, __half* __restrict__ Ch,
    const float* __restrict__ addend,
    int M, int N, int K)
{
    extern __shared__ char smem[];
    __half* sA = (__half*)smem;               // [128][40]
    __half* sB = sA + 128*FB_LD;              // [256][40]
    int tid = threadIdx.x, lane = tid & 31, wid = tid >> 5;
    int bn = blockIdx.x * 256;
    int wm = wid >> 2, wn = wid & 3;
    int g = lane >> 2, tig = lane & 3;

    for (int half = 0; half < 2; half++) {
        int bm = blockIdx.y * 256 + half * 128;
        float acc[4][8][4];
        #pragma unroll
        for (int mt = 0; mt < 4; mt++)
            #pragma unroll
            for (int nt = 0; nt < 8; nt++)
                #pragma unroll
                for (int q = 0; q < 4; q++) acc[mt][nt][q] = 0.f;

        for (int k0 = 0; k0 < K; k0 += 32) {
            __syncthreads();
            for (int v = tid; v < 512; v += 256) {
                int r = v >> 2, q = v & 3;
                *(uint4*)&sA[r*FB_LD + q*8] = *(const uint4*)(A + (size_t)(bm+r)*K + k0 + q*8);
            }
            for (int v = tid; v < 1024; v += 256) {
                int r = v >> 2, q = v & 3;
                *(uint4*)&sB[r*FB_LD + q*8] = *(const uint4*)(B + (size_t)(bn+r)*K + k0 + q*8);
            }
            __syncthreads();
            #pragma unroll
            for (int ks = 0; ks < 2; ks++) {
                int kk = ks * 16 + tig * 2;
                uint32_t a[4][4], b[8][2];
                #pragma unroll
                for (int mt = 0; mt < 4; mt++) {
                    int mr = (wm*64 + mt*16 + g)*FB_LD + kk;
                    a[mt][0] = *(const uint32_t*)&sA[mr];
                    a[mt][1] = *(const uint32_t*)&sA[mr + 8*FB_LD];
                    a[mt][2] = *(const uint32_t*)&sA[mr + 8];
                    a[mt][3] = *(const uint32_t*)&sA[mr + 8*FB_LD + 8];
                }
                #pragma unroll
                for (int nt = 0; nt < 8; nt++) {
                    int nr = (wn*64 + nt*8 + g)*FB_LD + kk;
                    b[nt][0] = *(const uint32_t*)&sB[nr];
                    b[nt][1] = *(const uint32_t*)&sB[nr + 8];
                }
                #pragma unroll
                for (int mt = 0; mt < 4; mt++)
                    #pragma unroll
                    for (int nt = 0; nt < 8; nt++)
                        mma16816(acc[mt][nt], a[mt], b[nt]);
            }
        }
        #pragma unroll
        for (int mt = 0; mt < 4; mt++) {
            #pragma unroll
            for (int nt = 0; nt < 8; nt++) {
                size_t r0 = (size_t)(bm + wm*64 + mt*16 + g);
                int col = bn + wn*64 + nt*8 + tig*2;
                if (Ch) {
                    *(__half2*)(Ch + r0*N + col)     = __floats2half2_rn(acc[mt][nt][0], acc[mt][nt][1]);
                    *(__half2*)(Ch + (r0+8)*N + col) = __floats2half2_rn(acc[mt][nt][2], acc[mt][nt][3]);
                } else {
                    float2 v0 = make_float2(acc[mt][nt][0], acc[mt][nt][1]);
                    float2 v1 = make_float2(acc[mt][nt][2], acc[mt][nt][3]);
                    if (addend) {
                        float2 a0 = *(const float2*)(addend + r0*N + col);
                        float2 a1 = *(const float2*)(addend + (r0+8)*N + col);
                        v0.x += a0.x; v0.y += a0.y; v1.x += a1.x; v1.y += a1.y;
                    }
                    *(float2*)(Cf + r0*N + col)     = v0;
                    *(float2*)(Cf + (r0+8)*N + col) = v1;
                }
            }
        }
        __syncthreads();
    }
}
#endif  // USE_TCGEN05

// ---------------- RMSNorm -> fp16 --------------------------------------------
__global__ __launch_bounds__(256) void rmsnorm_h_kernel(
    const float* __restrict__ x, const float* __restrict__ w,
    __half* __restrict__ out)
{
    __shared__ float red[8];
    int row = blockIdx.x;
    int tid = threadIdx.x;
    const float4* xr = (const float4*)(x + (size_t)row * EMBED);
    const float4* w4 = (const float4*)w;
    float4 v0 = xr[tid];
    float4 v1 = xr[tid + 256];
    float ss = v0.x*v0.x + v0.y*v0.y + v0.z*v0.z + v0.w*v0.w
             + v1.x*v1.x + v1.y*v1.y + v1.z*v1.z + v1.w*v1.w;
    #pragma unroll
    for (int o = 16; o > 0; o >>= 1) ss += __shfl_xor_sync(0xffffffffu, ss, o);
    if ((tid & 31) == 0) red[tid >> 5] = ss;
    __syncthreads();
    float tot = red[0] + red[1] + red[2] + red[3] + red[4] + red[5] + red[6] + red[7];
    float inv = rsqrtf(tot * (1.0f / EMBED) + 1e-5f);
    float4 wa = w4[tid], wb = w4[tid + 256];
    __half2* O = (__half2*)(out + (size_t)row * EMBED);
    O[2*tid]         = __floats2half2_rn(v0.x*inv*wa.x, v0.y*inv*wa.y);
    O[2*tid+1]       = __floats2half2_rn(v0.z*inv*wa.z, v0.w*inv*wa.w);
    O[2*(tid+256)]   = __floats2half2_rn(v1.x*inv*wb.x, v1.y*inv*wb.y);
    O[2*(tid+256)+1] = __floats2half2_rn(v1.z*inv*wb.z, v1.w*inv*wb.w);
}

// ---------------- RoPE + head transpose (fp16 in -> fp16 out) ----------------
__global__ __launch_bounds__(256) void rope_kernel(
    const __half* __restrict__ qkv, const float* __restrict__ freqs,
    __half* __restrict__ qh, __half* __restrict__ kh, __half* __restrict__ vh)
{
    int s = blockIdx.x, b = blockIdx.y, tid = threadIdx.x;
    const __half* row = qkv + ((size_t)b * SS + s) * QKV_N;
    const float* f = freqs + (size_t)s * HD;
    const float scale = 0.02209708691207961f;   // 1/sqrt(2048), folded into Q

    for (int p = tid; p < NH * 64; p += 256) {
        int h = p >> 6, i = p & 63;
        __half2 xv = *(const __half2*)(row + h*HD + 2*i);
        float x0 = __half2float(__low2half(xv)), x1 = __half2float(__high2half(xv));
        float c = f[2*i], sn = f[2*i+1];
        __half2* dst = (__half2*)(qh + ((size_t)(b*NH + h) * SS + s) * HD + 2*i);
        *dst = __floats2half2_rn((x0*c - x1*sn) * scale, (x1*c + x0*sn) * scale);
    }
    for (int p = tid; p < NKV * 64; p += 256) {
        int h = p >> 6, i = p & 63;
        __half2 xv = *(const __half2*)(row + NH*HD + h*HD + 2*i);
        float x0 = __half2float(__low2half(xv)), x1 = __half2float(__high2half(xv));
        float c = f[2*i], sn = f[2*i+1];
        __half2* dst = (__half2*)(kh + ((size_t)(b*NKV + h) * SS + s) * HD + 2*i);
        *dst = __floats2half2_rn(x0*c - x1*sn, x1*c + x0*sn);
    }
    for (int p = tid; p < NKV * HD; p += 256) {
        int h = p >> 7, d = p & 127;
        vh[((size_t)(b*NKV + h) * HD + d) * SS + s] = row[(NH + NKV)*HD + p];
    }
}

// ---------------- Tensor-core flash attention (fp16 mma, fp32 softmax) -------
#define FLH_SMEM_BYTES ((128*136 + 64*136 + 128*72) * 2)
__global__ __launch_bounds__(256) void flash_tc_kernel(
    const __half* __restrict__ qh, const __half* __restrict__ kh,
    const __half* __restrict__ vh, __half* __restrict__ oh)
{
    extern __shared__ __half smh[];
    __half* Qs = smh;                  // [128][136]
    __half* Ks = Qs + 128*136;         // [64][136]
    __half* Vs = Ks + 64*136;          // [128][72]  (Vt: [d][kc])
    int tid = threadIdx.x, lane = tid & 31, wid = tid >> 5;
    int g = lane >> 2, tig = lane & 3;
    int qb = blockIdx.x, hb = blockIdx.y, bb = blockIdx.z;
    uint32_t ks_b = smem_u32(Ks), vs_b = smem_u32(Vs);

    const __half* Qg = qh + ((size_t)(bb*NH + hb) * SS + (size_t)qb*128) * HD;
    const __half* Kg = kh + (size_t)(bb*NKV + (hb >> 2)) * SS * HD;
    const __half* Vg = vh + (size_t)(bb*NKV + (hb >> 2)) * HD * SS;

    for (int i = tid; i < 128*16; i += 256) {
        int r = i >> 4, c = i & 15;
        *(uint4*)&Qs[r*136 + c*8] = *(const uint4*)(Qg + r*HD + c*8);
    }

    float accO[16][4];
    #pragma unroll
    for (int nd = 0; nd < 16; nd++)
        #pragma unroll
        for (int q = 0; q < 4; q++) accO[nd][q] = 0.f;
    float m0 = -1e30f, m1 = -1e30f, l0 = 0.f, l1 = 0.f;
    int r0 = qb*128 + wid*16 + g;
    int r1 = r0 + 8;

    int nkb = 2*(qb + 1);
    for (int kb = 0; kb < nkb; kb++) {
        __syncthreads();
        for (int i = tid; i < 64*16; i += 256) {
            int r = i >> 4, c = i & 15;
            cpa16(ks_b + (uint32_t)(r*136 + c*8)*2,
                  Kg + (size_t)(kb*64 + r)*HD + c*8);
        }
        for (int i = tid; i < 128*8; i += 256) {
            int r = i >> 3, c = i & 7;
            cpa16(vs_b + (uint32_t)(r*72 + c*8)*2,
                  Vg + (size_t)r*SS + kb*64 + c*8);
        }
        CP_COMMIT(); CP_WAIT0();
        __syncthreads();

        float sacc[8][4];
        #pragma unroll
        for (int nt = 0; nt < 8; nt++)
            #pragma unroll
            for (int q = 0; q < 4; q++) sacc[nt][q] = 0.f;
        #pragma unroll
        for (int ks = 0; ks < 8; ks++) {
            uint32_t a[4];
            const __half* qr = &Qs[(wid*16 + g)*136 + ks*16 + 2*tig];
            a[0] = *(const uint32_t*)qr;
            a[1] = *(const uint32_t*)(qr + 8*136);
            a[2] = *(const uint32_t*)(qr + 8);
            a[3] = *(const uint32_t*)(qr + 8*136 + 8);
            #pragma unroll
            for (int nt = 0; nt < 8; nt++) {
                uint32_t b[2];
                const __half* kr = &Ks[(nt*8 + g)*136 + ks*16 + 2*tig];
                b[0] = *(const uint32_t*)kr;
                b[1] = *(const uint32_t*)(kr + 8);
                mma16816(sacc[nt], a, b);
            }
        }
        if (kb >= 2*qb) {
            #pragma unroll
            for (int nt = 0; nt < 8; nt++) {
                int col = kb*64 + nt*8 + 2*tig;
                if (col     > r0) sacc[nt][0] = -1e30f;
                if (col + 1 > r0) sacc[nt][1] = -1e30f;
                if (col     > r1) sacc[nt][2] = -1e30f;
                if (col + 1 > r1) sacc[nt][3] = -1e30f;
            }
        }
        float mx0 = -1e30f, mx1 = -1e30f;
        #pragma unroll
        for (int nt = 0; nt < 8; nt++) {
            mx0 = fmaxf(mx0, fmaxf(sacc[nt][0], sacc[nt][1]));
            mx1 = fmaxf(mx1, fmaxf(sacc[nt][2], sacc[nt][3]));
        }
        mx0 = fmaxf(mx0, __shfl_xor_sync(0xffffffffu, mx0, 1));
        mx0 = fmaxf(mx0, __shfl_xor_sync(0xffffffffu, mx0, 2));
        mx1 = fmaxf(mx1, __shfl_xor_sync(0xffffffffu, mx1, 1));
        mx1 = fmaxf(mx1, __shfl_xor_sync(0xffffffffu, mx1, 2));
        float nm0 = fmaxf(m0, mx0), nm1 = fmaxf(m1, mx1);
        float f0 = __expf(m0 - nm0), f1 = __expf(m1 - nm1);
        m0 = nm0; m1 = nm1;
        float s0 = 0.f, s1 = 0.f;
        #pragma unroll
        for (int nt = 0; nt < 8; nt++) {
            float p0 = __expf(sacc[nt][0] - m0);
            float p1 = __expf(sacc[nt][1] - m0);
            float p2 = __expf(sacc[nt][2] - m1);
            float p3 = __expf(sacc[nt][3] - m1);
            sacc[nt][0] = p0; sacc[nt][1] = p1; sacc[nt][2] = p2; sacc[nt][3] = p3;
            s0 += p0 + p1; s1 += p2 + p3;
        }
        s0 += __shfl_xor_sync(0xffffffffu, s0, 1);
        s0 += __shfl_xor_sync(0xffffffffu, s0, 2);
        s1 += __shfl_xor_sync(0xffffffffu, s1, 1);
        s1 += __shfl_xor_sync(0xffffffffu, s1, 2);
        l0 = l0*f0 + s0; l1 = l1*f1 + s1;
        #pragma unroll
        for (int nd = 0; nd < 16; nd++) {
            accO[nd][0] *= f0; accO[nd][1] *= f0;
            accO[nd][2] *= f1; accO[nd][3] *= f1;
        }
        #pragma unroll
        for (int j = 0; j < 4; j++) {
            uint32_t a[4];
            __half2 t;
            t = __floats2half2_rn(sacc[2*j][0],   sacc[2*j][1]);   a[0] = *(uint32_t*)&t;
            t = __floats2half2_rn(sacc[2*j][2],   sacc[2*j][3]);   a[1] = *(uint32_t*)&t;
            t = __floats2half2_rn(sacc[2*j+1][0], sacc[2*j+1][1]); a[2] = *(uint32_t*)&t;
            t = __floats2half2_rn(sacc[2*j+1][2], sacc[2*j+1][3]); a[3] = *(uint32_t*)&t;
            #pragma unroll
            for (int nd = 0; nd < 16; nd++) {
                uint32_t b[2];
                const __half* vr = &Vs[(nd*8 + g)*72 + j*16 + 2*tig];
                b[0] = *(const uint32_t*)vr;
                b[1] = *(const uint32_t*)(vr + 8);
                mma16816(accO[nd], a, b);
            }
        }
    }
    // epilogue: O /= l -> fp16 via smem staging
    float inv0 = 1.f / l0, inv1 = 1.f / l1;
    __half* st = smh;   // [128][136]
    int lr = wid*16 + g;
    size_t obase = ((size_t)bb*SS + (size_t)qb*128) * EMBED + hb*HD;
    __syncthreads();
    #pragma unroll
    for (int nd = 0; nd < 16; nd++) {
        int col = nd*8 + 2*tig;
        *(__half2*)&st[lr*136 + col] =
            __floats2half2_rn(accO[nd][0]*inv0, accO[nd][1]*inv0);
        *(__half2*)&st[(lr+8)*136 + col] =
            __floats2half2_rn(accO[nd][2]*inv1, accO[nd][3]*inv1);
    }
    __syncthreads();
    for (int i = tid; i < 128*16; i += 256) {
        int r = i >> 4, c = i & 15;
        *(uint4*)(oh + obase + (size_t)r*EMBED + c*8) = *(uint4*)&st[r*136 + c*8];
    }
}

// ---------------- SwiGLU (fp16 combined gate|up -> fp16) ---------------------
__global__ __launch_bounds__(256) void silu_h_kernel(
    const __half* __restrict__ u, __half* __restrict__ out, int n8)
{
    int i = blockIdx.x * 256 + threadIdx.x;
    if (i >= n8) return;
    int row = i / (FF/8), c8 = i % (FF/8);
    const __half* gp = u + (size_t)row * 2*FF + c8*8;
    uint4 gv = *(const uint4*)gp;
    uint4 uv = *(const uint4*)(gp + FF);
    __half2* gh = (__half2*)&gv;
    __half2* uh = (__half2*)&uv;
    __half2 o[4];
    #pragma unroll
    for (int q = 0; q < 4; q++) {
        float a0 = __half2float(__low2half(gh[q])), a1 = __half2float(__high2half(gh[q]));
        float b0 = __half2float(__low2half(uh[q])), b1 = __half2float(__high2half(uh[q]));
        o[q] = __floats2half2_rn(a0 / (1.f + __expf(-a0)) * b0,
                                 a1 / (1.f + __expf(-a1)) * b1);
    }
    *(uint4*)(out + (size_t)row * FF + c8*8) = *(uint4*)o;
}

// ---------------- driver ------------------------------------------------------
static inline void conv_launch(const float* src, __half* dst, size_t n)
{
    int n4 = (int)(n / 4);
    conv_kernel<<<(n4 + 255)/256, 256>>>(src, dst, n4);
}

extern "C" void kernel_launch(void* const* d_in, const int* in_sizes, int n_in,
                              void* d_out, int out_size)
{
    const float* x       = (const float*)d_in[0];
    const float* freqs   = (const float*)d_in[2];
    const float* w_qkv   = (const float*)d_in[4];
    const float* w_fc    = (const float*)d_in[5];
    const float* w1      = (const float*)d_in[6];
    const float* w2      = (const float*)d_in[7];
    const float* w3      = (const float*)d_in[8];
    const float* attn_nw = (const float*)d_in[9];
    const float* ff_nw   = (const float*)d_in[10];
    float* out = (float*)d_out;

    float *h1;
    __half *qkvh, *qh, *kh, *vh, *uh, *ah, *wh;
    cudaGetSymbolAddress((void**)&qkvh, g_qkvh);
    cudaGetSymbolAddress((void**)&qh,  g_qh2);
    cudaGetSymbolAddress((void**)&kh,  g_kh2);
    cudaGetSymbolAddress((void**)&vh,  g_vh2);
    cudaGetSymbolAddress((void**)&h1,  g_h1);
    cudaGetSymbolAddress((void**)&uh,  g_uh);
    cudaGetSymbolAddress((void**)&ah,  g_ah);
    cudaGetSymbolAddress((void**)&wh,  g_wh);

    cudaFuncSetAttribute(tc_gemm, cudaFuncAttributeMaxDynamicSharedMemorySize, GM_SMEM_BYTES);
    cudaFuncSetAttribute(flash_tc_kernel, cudaFuncAttributeMaxDynamicSharedMemorySize, FLH_SMEM_BYTES);

    // 1. attn rmsnorm -> fp16
    rmsnorm_h_kernel<<<ROWS, 256>>>(x, attn_nw, ah);
    // 2. qkv projection -> fp16 qkvh
    conv_launch(w_qkv, wh, (size_t)QKV_N*EMBED);
    tc_gemm<<<dim3(QKV_N/256, ROWS/256), 256, GM_SMEM_BYTES>>>(
        ah, wh, nullptr, qkvh, nullptr, ROWS, QKV_N, EMBED);
    // 3. rope + transpose -> fp16
    rope_kernel<<<dim3(SS, BB), 256>>>(qkvh, freqs, qh, kh, vh);
    // 4. tensor-core flash attention -> fp16 attn into g_ah
    flash_tc_kernel<<<dim3(SS/128, NH, BB), 256, FLH_SMEM_BYTES>>>(qh, kh, vh, ah);
    // 5. output projection + residual -> fp32 h1
    conv_launch(w_fc, wh, (size_t)EMBED*EMBED);
    tc_gemm<<<dim3(EMBED/256, ROWS/256), 256, GM_SMEM_BYTES>>>(
        ah, wh, h1, nullptr, x, ROWS, EMBED, EMBED);
    // 6. ffn rmsnorm -> fp16
    rmsnorm_h_kernel<<<ROWS, 256>>>(h1, ff_nw, ah);
    // 7. combined gate|up projection -> fp16 uh  (w1 then w2 in one B buffer)
    conv_launch(w1, wh, (size_t)FF*EMBED);
    conv_launch(w2, wh + (size_t)FF*EMBED, (size_t)FF*EMBED);
    tc_gemm<<<dim3(2*FF/256, ROWS/256), 256, GM_SMEM_BYTES>>>(
        ah, wh, nullptr, uh, nullptr, ROWS, 2*FF, EMBED);
    // 8. swiglu -> fp16 ah
    silu_h_kernel<<<(ROWS*FF/8 + 255)/256, 256>>>(uh, ah, ROWS*FF/8);
    // 9. down projection + residual -> out
    conv_launch(w3, wh, (size_t)EMBED*FF);
    tc_gemm<<<dim3(EMBED/256, ROWS/256), 256, GM_SMEM_BYTES>>>(
        ah, wh, out, nullptr, h1, ROWS, EMBED, FF);
}

// round 9
// speedup vs baseline: 27.1008x; 1.0958x over previous
#include <cuda_runtime.h>
#include <cuda_bf16.h>
#include <cuda_fp16.h>
#include <math.h>
#include <stdint.h>

#define EMBED 2048
#define NH 16
#define NKV 4
#define HD 128
#define FF 5632
#define BB 2
#define SS 2048
#define ROWS (BB*SS)                 // 4096 tokens
#define QKV_N ((NH + 2*NKV)*HD)      // 3072

#if defined(__CUDA_ARCH_FEAT_SM103_ALL) || defined(__CUDA_ARCH_FEAT_SM100_ALL)
#define USE_TCGEN05 1
#else
#define USE_TCGEN05 0
#endif

// ---------------- scratch (device globals; no allocations allowed) ----------
__device__ __half g_qkvh[ROWS*QKV_N];     // fp16 qkv gemm output
__device__ __half g_qh2[BB*NH *SS*HD];    // fp16 Q (scaled by 1/sqrt(E)*log2e), [b,h,s,d]
__device__ __half g_kh2[BB*NKV*SS*HD];    // fp16 K, [b,kvh,s,d]
__device__ __half g_vh2[BB*NKV*HD*SS];    // fp16 V transposed, [b,kvh,d,s]
__device__ float  g_h1 [ROWS*EMBED];
__device__ __half g_uh [ROWS*2*FF];       // fp16 combined gate|up
__device__ __half g_ah [ROWS*FF];         // fp16 activations (gemm A operand)
__device__ __half g_wh [2*FF*EMBED];      // fp16 weights     (gemm B operand)

#define GM_STAGE_BYTES 65536              // A0 16K + A1 16K + B 32K
#define GM_NSTAGE 3
#define GM_SMEM_BYTES (1024 + GM_NSTAGE*GM_STAGE_BYTES)

// ---------- common helpers (legal on plain sm_103 PTX) ----------------------
__device__ __forceinline__ uint32_t smem_u32(const void* p) {
    uint32_t a;
    asm("{ .reg .u64 t; cvta.to.shared.u64 t, %1; cvt.u32.u64 %0, t; }" : "=r"(a) : "l"(p));
    return a;
}
#define CP_COMMIT() asm volatile("cp.async.commit_group;" ::: "memory")
#define CP_WAIT0()  asm volatile("cp.async.wait_group 0;" ::: "memory")
#define CP_WAIT1()  asm volatile("cp.async.wait_group 1;" ::: "memory")
__device__ __forceinline__ void cpa16(uint32_t saddr, const void* g) {
    asm volatile("cp.async.cg.shared.global [%0], [%1], 16;" :: "r"(saddr), "l"(g) : "memory");
}
__device__ __forceinline__ void mma16816(float* c, const uint32_t* a, const uint32_t* b) {
    asm volatile("mma.sync.aligned.m16n8k16.row.col.f32.f16.f16.f32 "
        "{%0,%1,%2,%3}, {%4,%5,%6,%7}, {%8,%9}, {%0,%1,%2,%3};"
        : "+f"(c[0]), "+f"(c[1]), "+f"(c[2]), "+f"(c[3])
        : "r"(a[0]), "r"(a[1]), "r"(a[2]), "r"(a[3]), "r"(b[0]), "r"(b[1]));
}
__device__ __forceinline__ float ex2f(float x) {
    float y; asm("ex2.approx.f32 %0, %1;" : "=f"(y) : "f"(x)); return y;
}

// ======================= fp32 -> fp16 convert (weights) ======================
__global__ __launch_bounds__(256) void conv_kernel(
    const float* __restrict__ x, __half* __restrict__ y, int n4)
{
    int i = blockIdx.x * 256 + threadIdx.x;
    if (i >= n4) return;
    float4 v = ((const float4*)x)[i];
    __half2* Y = (__half2*)y;
    Y[2*i]   = __floats2half2_rn(v.x, v.y);
    Y[2*i+1] = __floats2half2_rn(v.z, v.w);
}

#if USE_TCGEN05
// ======================= tcgen05 GEMM (sm_103a pass) =========================
__device__ __forceinline__ uint32_t elect_one_pred() {
    uint32_t pred;
    asm volatile(
        "{\n\t.reg .pred p;\n\telect.sync _|p, 0xFFFFFFFF;\n\tselp.b32 %0, 1, 0, p;\n\t}"
        : "=r"(pred));
    return pred;
}
#define MBAR_INIT(addr, cnt) \
    asm volatile("mbarrier.init.shared.b64 [%0], %1;" :: "r"(addr), "r"((uint32_t)(cnt)) : "memory")
#define MBAR_INVAL(addr) \
    asm volatile("mbarrier.inval.shared.b64 [%0];" :: "r"(addr) : "memory")
#define MBAR_WAIT(addr, parity) do { \
    uint32_t _m = (addr); uint32_t _p = (parity); uint32_t _d; \
    asm volatile("{\n\t.reg .pred p;\n\tmbarrier.try_wait.parity.acquire.cta.shared::cta.b64 p, [%1], %2;\n\tselp.b32 %0, 1, 0, p;\n\t}" \
        : "=r"(_d) : "r"(_m), "r"(_p) : "memory"); \
    if (!_d) { \
        asm volatile("{\n\t.reg .pred P1;\n\tWL_%=:\n\tmbarrier.try_wait.parity.acquire.cta.shared::cta.b64 P1, [%0], %1, 0x989680;\n\t@P1 bra.uni WD_%=;\n\tbra.uni WL_%=;\n\tWD_%=:\n\t}" \
            :: "r"(_m), "r"(_p) : "memory"); \
    } } while(0)
#define TC_ALLOC(smem_addr, n) \
    asm volatile("tcgen05.alloc.cta_group::1.sync.aligned.shared::cta.b32 [%0], %1;" \
        :: "r"((uint32_t)(smem_addr)), "r"((uint32_t)(n)) : "memory")
#define TC_DEALLOC(tmem_addr, n) \
    asm volatile("tcgen05.dealloc.cta_group::1.sync.aligned.b32 %0, %1;" :: "r"(tmem_addr), "r"((uint32_t)(n)))
#define TC_RELINQ() \
    asm volatile("tcgen05.relinquish_alloc_permit.cta_group::1.sync.aligned;")
#define TC_COMMIT(mbar) \
    asm volatile("tcgen05.commit.cta_group::1.mbarrier::arrive::one.shared::cluster.b64 [%0];" \
        :: "r"((uint32_t)(mbar)) : "memory")
#define TC_FENCE_AFTER() asm volatile("tcgen05.fence::after_thread_sync;" ::: "memory")
#define TC_FENCE_BEFORE() asm volatile("tcgen05.fence::before_thread_sync;" ::: "memory")
#define TC_WAIT_LD() asm volatile("tcgen05.wait::ld.sync.aligned;" ::: "memory")
#define FENCE_ASYNC_SHARED() asm volatile("fence.proxy.async.shared::cta;" ::: "memory")
#define TC_LD_X32(r, tmem_addr) \
    asm volatile("tcgen05.ld.sync.aligned.32x32b.x32.b32 " \
        "{%0, %1, %2, %3, %4, %5, %6, %7, %8, %9, %10, %11, %12, %13, %14, %15, " \
        " %16, %17, %18, %19, %20, %21, %22, %23, %24, %25, %26, %27, %28, %29, %30, %31}, [%32];" \
        : "=r"((r)[0]),  "=r"((r)[1]),  "=r"((r)[2]),  "=r"((r)[3]), \
          "=r"((r)[4]),  "=r"((r)[5]),  "=r"((r)[6]),  "=r"((r)[7]), \
          "=r"((r)[8]),  "=r"((r)[9]),  "=r"((r)[10]), "=r"((r)[11]), \
          "=r"((r)[12]), "=r"((r)[13]), "=r"((r)[14]), "=r"((r)[15]), \
          "=r"((r)[16]), "=r"((r)[17]), "=r"((r)[18]), "=r"((r)[19]), \
          "=r"((r)[20]), "=r"((r)[21]), "=r"((r)[22]), "=r"((r)[23]), \
          "=r"((r)[24]), "=r"((r)[25]), "=r"((r)[26]), "=r"((r)[27]), \
          "=r"((r)[28]), "=r"((r)[29]), "=r"((r)[30]), "=r"((r)[31]) \
        : "r"(tmem_addr))

__device__ __forceinline__ uint64_t mk_desc(uint32_t addr) {
    const uint64_t base = (2ull << 61) | (1ull << 46) | (64ull << 32) | (1ull << 16);
    return base | ((uint64_t)(addr >> 4) & 0x3FFF);
}
__device__ __forceinline__ void mma_f16_ss(uint32_t d, uint64_t da, uint64_t db,
                                           uint32_t idesc, uint32_t en) {
    asm volatile(
        "{\n\t.reg .pred p;\n\tsetp.ne.u32 p, %5, 0;\n\t"
        "tcgen05.mma.cta_group::1.kind::f16 [%0], %1, %2, %3, {%4,%4,%4,%4}, p;\n\t}"
        :: "r"(d), "l"(da), "l"(db), "r"(idesc), "r"(0u), "r"(en) : "memory");
}

#define GM_IDESC 0x8400010u              // F32 acc, fp16 a/b, M=128, N=256

__device__ __forceinline__ void gm_load_stage(
    uint32_t stb,
    const __half* __restrict__ A, const __half* __restrict__ B,
    int bm, int bn, int K, int kc, int tid)
{
    #pragma unroll
    for (int it = 0; it < 8; it++) {                 // A: 256 rows x 8 vec8
        int v = tid + it * 256;
        int r = v >> 3, cv = v & 7;
        uint32_t off = (uint32_t)((r & 127)*128 + cv*16);
        uint32_t sw = off ^ ((off >> 3) & 0x70);
        cpa16(stb + (uint32_t)(r >> 7)*16384 + sw,
              A + (size_t)(bm + r) * K + kc + cv*8);
    }
    #pragma unroll
    for (int it = 0; it < 8; it++) {                 // B: 256 rows x 8 vec8
        int v = tid + it * 256;
        int r = v >> 3, cv = v & 7;
        uint32_t off = (uint32_t)(r*128 + cv*16);
        uint32_t sw = off ^ ((off >> 3) & 0x70);
        cpa16(stb + 32768 + sw, B + (size_t)(bn + r) * K + kc + cv*8);
    }
    CP_COMMIT();
}

__global__ __launch_bounds__(256, 1) void tc_gemm(
    const __half* __restrict__ A, const __half* __restrict__ B,
    float* __restrict__ Cf, __half* __restrict__ Ch,
    const float* __restrict__ addend,
    int M, int N, int K)
{
    extern __shared__ char smem[];
    uint32_t sb = smem_u32(smem);
    int tid = threadIdx.x;
    int wid = tid >> 5, lane = tid & 31;
    int bn = blockIdx.x * 256, bm = blockIdx.y * 256;

    if (wid == 0) { TC_ALLOC(sb, 512); TC_RELINQ(); }
    if (tid == 0) { MBAR_INIT(sb + 8, 1); MBAR_INIT(sb + 16, 1); MBAR_INIT(sb + 24, 1); }
    __syncthreads();
    uint32_t tmem;
    asm volatile("ld.shared.b32 %0, [%1];" : "=r"(tmem) : "r"(sb));

    const int NC = K / 64;
    int ph0 = 0, ph1 = 0;

    gm_load_stage(sb + 1024, A, B, bm, bn, K, 0, tid);
    gm_load_stage(sb + 1024 + GM_STAGE_BYTES, A, B, bm, bn, K, 64, tid);

    for (int c = 0; c < NC; c++) {
        int s = c % GM_NSTAGE;
        if (c + 1 < NC) { CP_WAIT1(); } else { CP_WAIT0(); }
        __syncthreads();
        uint32_t stb = sb + 1024 + (uint32_t)s * GM_STAGE_BYTES;
        if (wid == 0 && elect_one_pred()) {
            FENCE_ASYNC_SHARED();
            uint64_t dA0 = mk_desc(stb);
            uint64_t dA1 = mk_desc(stb + 16384);
            uint64_t dB  = mk_desc(stb + 32768);
            #pragma unroll
            for (int k = 0; k < 4; k++) {
                uint32_t en = (c > 0) || (k > 0);
                mma_f16_ss(tmem,       dA0 + k*2, dB + k*2, GM_IDESC, en);
                mma_f16_ss(tmem + 256, dA1 + k*2, dB + k*2, GM_IDESC, en);
            }
            TC_COMMIT(sb + 8 + (uint32_t)(c & 1) * 8);
            if (c == NC - 1) TC_COMMIT(sb + 24);   // dedicated final-completion mbar
        }
        if (c + 2 < NC) {
            if (c >= 1) {
                int m = (c - 1) & 1;
                if (m == 0) { MBAR_WAIT(sb + 8, ph0);  ph0 ^= 1; }
                else        { MBAR_WAIT(sb + 16, ph1); ph1 ^= 1; }
            }
            gm_load_stage(sb + 1024 + (uint32_t)((c + 2) % GM_NSTAGE) * GM_STAGE_BYTES,
                          A, B, bm, bn, K, (c + 2) * 64, tid);
        }
    }
    MBAR_WAIT(sb + 24, 0);
    TC_FENCE_AFTER();

    int wg = wid >> 2, ws = wid & 3;
    #pragma unroll
    for (int h = 0; h < 2; h++) {
        size_t row = (size_t)(bm + h*128 + ws * 32 + lane);
        #pragma unroll
        for (int cb = 0; cb < 4; cb++) {
            uint32_t regs[32];
            TC_LD_X32(regs, tmem + (uint32_t)(h*256 + wg * 128 + cb * 32));
            TC_WAIT_LD();
            int col = bn + wg * 128 + cb * 32;
            if (Ch) {
                __half* Cp = Ch + row * (size_t)N + col;
                #pragma unroll
                for (int j = 0; j < 32; j += 8) {
                    __half2 o[4];
                    o[0] = __floats2half2_rn(__uint_as_float(regs[j]),   __uint_as_float(regs[j+1]));
                    o[1] = __floats2half2_rn(__uint_as_float(regs[j+2]), __uint_as_float(regs[j+3]));
                    o[2] = __floats2half2_rn(__uint_as_float(regs[j+4]), __uint_as_float(regs[j+5]));
                    o[3] = __floats2half2_rn(__uint_as_float(regs[j+6]), __uint_as_float(regs[j+7]));
                    *(uint4*)(Cp + j) = *(uint4*)o;
                }
            } else {
                float* Cp = Cf + row * (size_t)N + col;
                if (addend) {
                    const float* Ap = addend + row * (size_t)N + col;
                    #pragma unroll
                    for (int j = 0; j < 32; j += 4) {
                        float4 a = *(const float4*)(Ap + j);
                        float4 o = make_float4(__uint_as_float(regs[j])   + a.x,
                                               __uint_as_float(regs[j+1]) + a.y,
                                               __uint_as_float(regs[j+2]) + a.z,
                                               __uint_as_float(regs[j+3]) + a.w);
                        *(float4*)(Cp + j) = o;
                    }
                } else {
                    #pragma unroll
                    for (int j = 0; j < 32; j += 4) {
                        float4 o = make_float4(__uint_as_float(regs[j]),
                                               __uint_as_float(regs[j+1]),
                                               __uint_as_float(regs[j+2]),
                                               __uint_as_float(regs[j+3]));
                        *(float4*)(Cp + j) = o;
                    }
                }
            }
        }
    }
    TC_FENCE_BEFORE();
    __syncthreads();
    if (tid == 0) { MBAR_INVAL(sb + 8); MBAR_INVAL(sb + 16); MBAR_INVAL(sb + 24); }
    if (wid == 0) { TC_DEALLOC(tmem, 512); }
}

#else
// ======================= mma.sync GEMM fallback ==============================
#define FB_LD 40

__global__ __launch_bounds__(256, 1) void tc_gemm(
    const __half* __restrict__ A, const __half* __restrict__ B,
    float* __restrict__ Cf, __half* __restrict__ Ch,
    const float* __restrict__ addend,
    int M, int N, int K)
{
    extern __shared__ char smem[];
    __half* sA = (__half*)smem;               // [128][40]
    __half* sB = sA + 128*FB_LD;              // [256][40]
    int tid = threadIdx.x, lane = tid & 31, wid = tid >> 5;
    int bn = blockIdx.x * 256;
    int wm = wid >> 2, wn = wid & 3;
    int g = lane >> 2, tig = lane & 3;

    for (int half = 0; half < 2; half++) {
        int bm = blockIdx.y * 256 + half * 128;
        float acc[4][8][4];
        #pragma unroll
        for (int mt = 0; mt < 4; mt++)
            #pragma unroll
            for (int nt = 0; nt < 8; nt++)
                #pragma unroll
                for (int q = 0; q < 4; q++) acc[mt][nt][q] = 0.f;

        for (int k0 = 0; k0 < K; k0 += 32) {
            __syncthreads();
            for (int v = tid; v < 512; v += 256) {
                int r = v >> 2, q = v & 3;
                *(uint4*)&sA[r*FB_LD + q*8] = *(const uint4*)(A + (size_t)(bm+r)*K + k0 + q*8);
            }
            for (int v = tid; v < 1024; v += 256) {
                int r = v >> 2, q = v & 3;
                *(uint4*)&sB[r*FB_LD + q*8] = *(const uint4*)(B + (size_t)(bn+r)*K + k0 + q*8);
            }
            __syncthreads();
            #pragma unroll
            for (int ks = 0; ks < 2; ks++) {
                int kk = ks * 16 + tig * 2;
                uint32_t a[4][4], b[8][2];
                #pragma unroll
                for (int mt = 0; mt < 4; mt++) {
                    int mr = (wm*64 + mt*16 + g)*FB_LD + kk;
                    a[mt][0] = *(const uint32_t*)&sA[mr];
                    a[mt][1] = *(const uint32_t*)&sA[mr + 8*FB_LD];
                    a[mt][2] = *(const uint32_t*)&sA[mr + 8];
                    a[mt][3] = *(const uint32_t*)&sA[mr + 8*FB_LD + 8];
                }
                #pragma unroll
                for (int nt = 0; nt < 8; nt++) {
                    int nr = (wn*64 + nt*8 + g)*FB_LD + kk;
                    b[nt][0] = *(const uint32_t*)&sB[nr];
                    b[nt][1] = *(const uint32_t*)&sB[nr + 8];
                }
                #pragma unroll
                for (int mt = 0; mt < 4; mt++)
                    #pragma unroll
                    for (int nt = 0; nt < 8; nt++)
                        mma16816(acc[mt][nt], a[mt], b[nt]);
            }
        }
        #pragma unroll
        for (int mt = 0; mt < 4; mt++) {
            #pragma unroll
            for (int nt = 0; nt < 8; nt++) {
                size_t r0 = (size_t)(bm + wm*64 + mt*16 + g);
                int col = bn + wn*64 + nt*8 + tig*2;
                if (Ch) {
                    *(__half2*)(Ch + r0*N + col)     = __floats2half2_rn(acc[mt][nt][0], acc[mt][nt][1]);
                    *(__half2*)(Ch + (r0+8)*N + col) = __floats2half2_rn(acc[mt][nt][2], acc[mt][nt][3]);
                } else {
                    float2 v0 = make_float2(acc[mt][nt][0], acc[mt][nt][1]);
                    float2 v1 = make_float2(acc[mt][nt][2], acc[mt][nt][3]);
                    if (addend) {
                        float2 a0 = *(const float2*)(addend + r0*N + col);
                        float2 a1 = *(const float2*)(addend + (r0+8)*N + col);
                        v0.x += a0.x; v0.y += a0.y; v1.x += a1.x; v1.y += a1.y;
                    }
                    *(float2*)(Cf + r0*N + col)     = v0;
                    *(float2*)(Cf + (r0+8)*N + col) = v1;
                }
            }
        }
        __syncthreads();
    }
}
#endif  // USE_TCGEN05

// ---------------- RMSNorm -> fp16 --------------------------------------------
__global__ __launch_bounds__(256) void rmsnorm_h_kernel(
    const float* __restrict__ x, const float* __restrict__ w,
    __half* __restrict__ out)
{
    __shared__ float red[8];
    int row = blockIdx.x;
    int tid = threadIdx.x;
    const float4* xr = (const float4*)(x + (size_t)row * EMBED);
    const float4* w4 = (const float4*)w;
    float4 v0 = xr[tid];
    float4 v1 = xr[tid + 256];
    float ss = v0.x*v0.x + v0.y*v0.y + v0.z*v0.z + v0.w*v0.w
             + v1.x*v1.x + v1.y*v1.y + v1.z*v1.z + v1.w*v1.w;
    #pragma unroll
    for (int o = 16; o > 0; o >>= 1) ss += __shfl_xor_sync(0xffffffffu, ss, o);
    if ((tid & 31) == 0) red[tid >> 5] = ss;
    __syncthreads();
    float tot = red[0] + red[1] + red[2] + red[3] + red[4] + red[5] + red[6] + red[7];
    float inv = rsqrtf(tot * (1.0f / EMBED) + 1e-5f);
    float4 wa = w4[tid], wb = w4[tid + 256];
    __half2* O = (__half2*)(out + (size_t)row * EMBED);
    O[2*tid]         = __floats2half2_rn(v0.x*inv*wa.x, v0.y*inv*wa.y);
    O[2*tid+1]       = __floats2half2_rn(v0.z*inv*wa.z, v0.w*inv*wa.w);
    O[2*(tid+256)]   = __floats2half2_rn(v1.x*inv*wb.x, v1.y*inv*wb.y);
    O[2*(tid+256)+1] = __floats2half2_rn(v1.z*inv*wb.z, v1.w*inv*wb.w);
}

// ---------------- RoPE (q,k only; fp16 in -> fp16 out) -----------------------
__global__ __launch_bounds__(256) void rope_kernel(
    const __half* __restrict__ qkv, const float* __restrict__ freqs,
    __half* __restrict__ qh, __half* __restrict__ kh)
{
    int s = blockIdx.x, b = blockIdx.y, tid = threadIdx.x;
    const __half* row = qkv + ((size_t)b * SS + s) * QKV_N;
    const float* f = freqs + (size_t)s * HD;
    // 1/sqrt(EMBED) * log2(e): softmax done in exp2 domain
    const float scale = 0.02209708691207961f * 1.4426950408889634f;

    for (int p = tid; p < NH * 64; p += 256) {
        int h = p >> 6, i = p & 63;
        __half2 xv = *(const __half2*)(row + h*HD + 2*i);
        float x0 = __half2float(__low2half(xv)), x1 = __half2float(__high2half(xv));
        float c = f[2*i], sn = f[2*i+1];
        __half2* dst = (__half2*)(qh + ((size_t)(b*NH + h) * SS + s) * HD + 2*i);
        *dst = __floats2half2_rn((x0*c - x1*sn) * scale, (x1*c + x0*sn) * scale);
    }
    for (int p = tid; p < NKV * 64; p += 256) {
        int h = p >> 6, i = p & 63;
        __half2 xv = *(const __half2*)(row + NH*HD + h*HD + 2*i);
        float x0 = __half2float(__low2half(xv)), x1 = __half2float(__high2half(xv));
        float c = f[2*i], sn = f[2*i+1];
        __half2* dst = (__half2*)(kh + ((size_t)(b*NKV + h) * SS + s) * HD + 2*i);
        *dst = __floats2half2_rn(x0*c - x1*sn, x1*c + x0*sn);
    }
}

// ---------------- Coalesced V transpose: [b,s,(kvh,d)] -> [b,kvh,d,s] --------
__global__ __launch_bounds__(256) void vtrans_kernel(
    const __half* __restrict__ qkv, __half* __restrict__ vh)
{
    __shared__ __half t[64*136];   // [64 s][128 d] padded
    int s0 = blockIdx.x * 64, h = blockIdx.y, b = blockIdx.z;
    int tid = threadIdx.x;
    const __half* src = qkv + ((size_t)b * SS + s0) * QKV_N + (size_t)(NH + NKV)*HD + h*HD;
    for (int i = tid; i < 64*16; i += 256) {
        int r = i >> 4, c = i & 15;
        *(uint4*)&t[r*136 + c*8] = *(const uint4*)(src + (size_t)r * QKV_N + c*8);
    }
    __syncthreads();
    __half* dst = vh + ((size_t)(b*NKV + h) * HD) * SS + s0;
    for (int i = tid; i < 128*8; i += 256) {
        int d = i >> 3, c = i & 7;
        __half v[8];
        #pragma unroll
        for (int j = 0; j < 8; j++) v[j] = t[(c*8 + j)*136 + d];
        *(uint4*)(dst + (size_t)d * SS + c*8) = *(uint4*)v;
    }
}

// ---------------- Tensor-core flash attention (fp16 mma, exp2 softmax) -------
// Double-buffered K/V via cp.async; no running max (scores provably small).
#define FLH_SMEM_BYTES ((128*136 + 2*64*136 + 2*128*72) * 2)
__global__ __launch_bounds__(256) void flash_tc_kernel(
    const __half* __restrict__ qh, const __half* __restrict__ kh,
    const __half* __restrict__ vh, __half* __restrict__ oh)
{
    extern __shared__ __half smh[];
    __half* Qs  = smh;                      // [128][136]
    __half* Ks0 = Qs + 128*136;             // [64][136] x2
    __half* Ks1 = Ks0 + 64*136;
    __half* Vs0 = Ks1 + 64*136;             // [128][72] x2 (Vt: [d][kc])
    __half* Vs1 = Vs0 + 128*72;
    int tid = threadIdx.x, lane = tid & 31, wid = tid >> 5;
    int g = lane >> 2, tig = lane & 3;
    int qb = gridDim.x - 1 - blockIdx.x;    // biggest workload first
    int hb = blockIdx.y, bb = blockIdx.z;
    uint32_t ksb[2] = {smem_u32(Ks0), smem_u32(Ks1)};
    uint32_t vsb[2] = {smem_u32(Vs0), smem_u32(Vs1)};
    uint32_t qsb = smem_u32(Qs);

    const __half* Qg = qh + ((size_t)(bb*NH + hb) * SS + (size_t)qb*128) * HD;
    const __half* Kg = kh + (size_t)(bb*NKV + (hb >> 2)) * SS * HD;
    const __half* Vg = vh + (size_t)(bb*NKV + (hb >> 2)) * HD * SS;

    // prologue: Q + K/V stage 0 in one cp.async group
    for (int i = tid; i < 128*16; i += 256) {
        int r = i >> 4, c = i & 15;
        cpa16(qsb + (uint32_t)(r*136 + c*8)*2, Qg + r*HD + c*8);
    }
    {   // stage 0
        for (int i = tid; i < 64*16; i += 256) {
            int r = i >> 4, c = i & 15;
            cpa16(ksb[0] + (uint32_t)(r*136 + c*8)*2, Kg + (size_t)r*HD + c*8);
        }
        for (int i = tid; i < 128*8; i += 256) {
            int r = i >> 3, c = i & 7;
            cpa16(vsb[0] + (uint32_t)(r*72 + c*8)*2, Vg + (size_t)r*SS + c*8);
        }
        CP_COMMIT();
    }

    float accO[16][4];
    #pragma unroll
    for (int nd = 0; nd < 16; nd++)
        #pragma unroll
        for (int q = 0; q < 4; q++) accO[nd][q] = 0.f;
    float l0 = 0.f, l1 = 0.f;
    int r0 = qb*128 + wid*16 + g;
    int r1 = r0 + 8;

    int nkb = 2*(qb + 1);
    for (int kb = 0; kb < nkb; kb++) {
        int st = kb & 1;
        if (kb + 1 < nkb) {
            int st2 = st ^ 1;
            for (int i = tid; i < 64*16; i += 256) {
                int r = i >> 4, c = i & 15;
                cpa16(ksb[st2] + (uint32_t)(r*136 + c*8)*2,
                      Kg + (size_t)((kb+1)*64 + r)*HD + c*8);
            }
            for (int i = tid; i < 128*8; i += 256) {
                int r = i >> 3, c = i & 7;
                cpa16(vsb[st2] + (uint32_t)(r*72 + c*8)*2,
                      Vg + (size_t)r*SS + (kb+1)*64 + c*8);
            }
            CP_COMMIT(); CP_WAIT1();
        } else {
            CP_WAIT0();
        }
        __syncthreads();
        const __half* Ks = (st == 0) ? Ks0 : Ks1;
        const __half* Vs = (st == 0) ? Vs0 : Vs1;

        // S = Q*K^T  (128x64), warp: 16 rows
        float sacc[8][4];
        #pragma unroll
        for (int nt = 0; nt < 8; nt++)
            #pragma unroll
            for (int q = 0; q < 4; q++) sacc[nt][q] = 0.f;
        #pragma unroll
        for (int ks = 0; ks < 8; ks++) {
            uint32_t a[4];
            const __half* qr = &Qs[(wid*16 + g)*136 + ks*16 + 2*tig];
            a[0] = *(const uint32_t*)qr;
            a[1] = *(const uint32_t*)(qr + 8*136);
            a[2] = *(const uint32_t*)(qr + 8);
            a[3] = *(const uint32_t*)(qr + 8*136 + 8);
            #pragma unroll
            for (int nt = 0; nt < 8; nt++) {
                uint32_t b[2];
                const __half* kr = &Ks[(nt*8 + g)*136 + ks*16 + 2*tig];
                b[0] = *(const uint32_t*)kr;
                b[1] = *(const uint32_t*)(kr + 8);
                mma16816(sacc[nt], a, b);
            }
        }
        if (kb >= 2*qb) {   // causal mask on diagonal tiles
            #pragma unroll
            for (int nt = 0; nt < 8; nt++) {
                int col = kb*64 + nt*8 + 2*tig;
                if (col     > r0) sacc[nt][0] = -10000.f;
                if (col + 1 > r0) sacc[nt][1] = -10000.f;
                if (col     > r1) sacc[nt][2] = -10000.f;
                if (col + 1 > r1) sacc[nt][3] = -10000.f;
            }
        }
        // softmax numerator: p = exp2(S)  (log2e folded into Q scale; no max)
        float s0 = 0.f, s1 = 0.f;
        #pragma unroll
        for (int nt = 0; nt < 8; nt++) {
            float p0 = ex2f(sacc[nt][0]);
            float p1 = ex2f(sacc[nt][1]);
            float p2 = ex2f(sacc[nt][2]);
            float p3 = ex2f(sacc[nt][3]);
            sacc[nt][0] = p0; sacc[nt][1] = p1; sacc[nt][2] = p2; sacc[nt][3] = p3;
            s0 += p0 + p1; s1 += p2 + p3;
        }
        s0 += __shfl_xor_sync(0xffffffffu, s0, 1);
        s0 += __shfl_xor_sync(0xffffffffu, s0, 2);
        s1 += __shfl_xor_sync(0xffffffffu, s1, 1);
        s1 += __shfl_xor_sync(0xffffffffu, s1, 2);
        l0 += s0; l1 += s1;
        // O += P*V
        #pragma unroll
        for (int j = 0; j < 4; j++) {
            uint32_t a[4];
            __half2 t;
            t = __floats2half2_rn(sacc[2*j][0],   sacc[2*j][1]);   a[0] = *(uint32_t*)&t;
            t = __floats2half2_rn(sacc[2*j][2],   sacc[2*j][3]);   a[1] = *(uint32_t*)&t;
            t = __floats2half2_rn(sacc[2*j+1][0], sacc[2*j+1][1]); a[2] = *(uint32_t*)&t;
            t = __floats2half2_rn(sacc[2*j+1][2], sacc[2*j+1][3]); a[3] = *(uint32_t*)&t;
            #pragma unroll
            for (int nd = 0; nd < 16; nd++) {
                uint32_t b[2];
                const __half* vr = &Vs[(nd*8 + g)*72 + j*16 + 2*tig];
                b[0] = *(const uint32_t*)vr;
                b[1] = *(const uint32_t*)(vr + 8);
                mma16816(accO[nd], a, b);
            }
        }
        __syncthreads();   // protect buffers before next iteration's loads
    }
    // epilogue: O /= l -> fp16 via smem staging (reuse Qs area)
    float inv0 = 1.f / l0, inv1 = 1.f / l1;
    __half* stg = smh;   // [128][136]
    int lr = wid*16 + g;
    size_t obase = ((size_t)bb*SS + (size_t)qb*128) * EMBED + hb*HD;
    #pragma unroll
    for (int nd = 0; nd < 16; nd++) {
        int col = nd*8 + 2*tig;
        *(__half2*)&stg[lr*136 + col] =
            __floats2half2_rn(accO[nd][0]*inv0, accO[nd][1]*inv0);
        *(__half2*)&stg[(lr+8)*136 + col] =
            __floats2half2_rn(accO[nd][2]*inv1, accO[nd][3]*inv1);
    }
    __syncthreads();
    for (int i = tid; i < 128*16; i += 256) {
        int r = i >> 4, c = i & 15;
        *(uint4*)(oh + obase + (size_t)r*EMBED + c*8) = *(uint4*)&stg[r*136 + c*8];
    }
}

// ---------------- SwiGLU (fp16 combined gate|up -> fp16) ---------------------
__global__ __launch_bounds__(256) void silu_h_kernel(
    const __half* __restrict__ u, __half* __restrict__ out, int n8)
{
    int i = blockIdx.x * 256 + threadIdx.x;
    if (i >= n8) return;
    int row = i / (FF/8), c8 = i % (FF/8);
    const __half* gp = u + (size_t)row * 2*FF + c8*8;
    uint4 gv = *(const uint4*)gp;
    uint4 uv = *(const uint4*)(gp + FF);
    __half2* gh = (__half2*)&gv;
    __half2* uh = (__half2*)&uv;
    __half2 o[4];
    #pragma unroll
    for (int q = 0; q < 4; q++) {
        float a0 = __half2float(__low2half(gh[q])), a1 = __half2float(__high2half(gh[q]));
        float b0 = __half2float(__low2half(uh[q])), b1 = __half2float(__high2half(uh[q]));
        o[q] = __floats2half2_rn(a0 / (1.f + __expf(-a0)) * b0,
                                 a1 / (1.f + __expf(-a1)) * b1);
    }
    *(uint4*)(out + (size_t)row * FF + c8*8) = *(uint4*)o;
}

// ---------------- driver ------------------------------------------------------
static inline void conv_launch(const float* src, __half* dst, size_t n)
{
    int n4 = (int)(n / 4);
    conv_kernel<<<(n4 + 255)/256, 256>>>(src, dst, n4);
}

extern "C" void kernel_launch(void* const* d_in, const int* in_sizes, int n_in,
                              void* d_out, int out_size)
{
    const float* x       = (const float*)d_in[0];
    const float* freqs   = (const float*)d_in[2];
    const float* w_qkv   = (const float*)d_in[4];
    const float* w_fc    = (const float*)d_in[5];
    const float* w1      = (const float*)d_in[6];
    const float* w2      = (const float*)d_in[7];
    const float* w3      = (const float*)d_in[8];
    const float* attn_nw = (const float*)d_in[9];
    const float* ff_nw   = (const float*)d_in[10];
    float* out = (float*)d_out;

    float *h1;
    __half *qkvh, *qh, *kh, *vh, *uh, *ah, *wh;
    cudaGetSymbolAddress((void**)&qkvh, g_qkvh);
    cudaGetSymbolAddress((void**)&qh,  g_qh2);
    cudaGetSymbolAddress((void**)&kh,  g_kh2);
    cudaGetSymbolAddress((void**)&vh,  g_vh2);
    cudaGetSymbolAddress((void**)&h1,  g_h1);
    cudaGetSymbolAddress((void**)&uh,  g_uh);
    cudaGetSymbolAddress((void**)&ah,  g_ah);
    cudaGetSymbolAddress((void**)&wh,  g_wh);

    cudaFuncSetAttribute(tc_gemm, cudaFuncAttributeMaxDynamicSharedMemorySize, GM_SMEM_BYTES);
    cudaFuncSetAttribute(flash_tc_kernel, cudaFuncAttributeMaxDynamicSharedMemorySize, FLH_SMEM_BYTES);

    // 1. attn rmsnorm -> fp16
    rmsnorm_h_kernel<<<ROWS, 256>>>(x, attn_nw, ah);
    // 2. qkv projection -> fp16 qkvh
    conv_launch(w_qkv, wh, (size_t)QKV_N*EMBED);
    tc_gemm<<<dim3(QKV_N/256, ROWS/256), 256, GM_SMEM_BYTES>>>(
        ah, wh, nullptr, qkvh, nullptr, ROWS, QKV_N, EMBED);
    // 3. rope (q,k) + coalesced V transpose
    rope_kernel<<<dim3(SS, BB), 256>>>(qkvh, freqs, qh, kh);
    vtrans_kernel<<<dim3(SS/64, NKV, BB), 256>>>(qkvh, vh);
    // 4. tensor-core flash attention -> fp16 attn into g_ah
    flash_tc_kernel<<<dim3(SS/128, NH, BB), 256, FLH_SMEM_BYTES>>>(qh, kh, vh, ah);
    // 5. output projection + residual -> fp32 h1
    conv_launch(w_fc, wh, (size_t)EMBED*EMBED);
    tc_gemm<<<dim3(EMBED/256, ROWS/256), 256, GM_SMEM_BYTES>>>(
        ah, wh, h1, nullptr, x, ROWS, EMBED, EMBED);
    // 6. ffn rmsnorm -> fp16
    rmsnorm_h_kernel<<<ROWS, 256>>>(h1, ff_nw, ah);
    // 7. combined gate|up projection -> fp16 uh
    conv_launch(w1, wh, (size_t)FF*EMBED);
    conv_launch(w2, wh + (size_t)FF*EMBED, (size_t)FF*EMBED);
    tc_gemm<<<dim3(2*FF/256, ROWS/256), 256, GM_SMEM_BYTES>>>(
        ah, wh, nullptr, uh, nullptr, ROWS, 2*FF, EMBED);
    // 8. swiglu -> fp16 ah
    silu_h_kernel<<<(ROWS*FF/8 + 255)/256, 256>>>(uh, ah, ROWS*FF/8);
    // 9. down projection + residual -> out
    conv_launch(w3, wh, (size_t)EMBED*FF);
    tc_gemm<<<dim3(EMBED/256, ROWS/256), 256, GM_SMEM_BYTES>>>(
        ah, wh, out, nullptr, h1, ROWS, EMBED, FF);
}

// round 10
// speedup vs baseline: 27.5737x; 1.0175x over previous
#include <cuda_runtime.h>
#include <cuda_bf16.h>
#include <cuda_fp16.h>
#include <math.h>
#include <stdint.h>

#define EMBED 2048
#define NH 16
#define NKV 4
#define HD 128
#define FF 5632
#define BB 2
#define SS 2048
#define ROWS (BB*SS)                 // 4096 tokens
#define QKV_N ((NH + 2*NKV)*HD)      // 3072

#if defined(__CUDA_ARCH_FEAT_SM103_ALL) || defined(__CUDA_ARCH_FEAT_SM100_ALL)
#define USE_TCGEN05 1
#else
#define USE_TCGEN05 0
#endif

// ---------------- scratch (device globals; no allocations allowed) ----------
__device__ __half g_qkvh[ROWS*QKV_N];     // fp16 qkv gemm output
__device__ __half g_qh2[BB*NH *SS*HD];    // fp16 Q (scaled by 1/sqrt(E)*log2e), [b,h,s,d]
__device__ __half g_kh2[BB*NKV*SS*HD];    // fp16 K, [b,kvh,s,d]
__device__ __half g_vh2[BB*NKV*HD*SS];    // fp16 V transposed, [b,kvh,d,s]
__device__ float  g_h1 [ROWS*EMBED];
__device__ __half g_uh [ROWS*2*FF];       // fp16 combined gate|up
__device__ __half g_ah [ROWS*FF];         // fp16 activations (gemm A operand)
__device__ __half g_wh [2*FF*EMBED];      // fp16 weights     (gemm B operand)

#define GM_STAGE_BYTES 65536              // A0 16K + A1 16K + B 32K
#define GM_NSTAGE 3
#define GM_SMEM_BYTES (1024 + GM_NSTAGE*GM_STAGE_BYTES)

// ---------- common helpers (legal on plain sm_103 PTX) ----------------------
__device__ __forceinline__ uint32_t smem_u32(const void* p) {
    uint32_t a;
    asm("{ .reg .u64 t; cvta.to.shared.u64 t, %1; cvt.u32.u64 %0, t; }" : "=r"(a) : "l"(p));
    return a;
}
#define CP_COMMIT() asm volatile("cp.async.commit_group;" ::: "memory")
#define CP_WAIT0()  asm volatile("cp.async.wait_group 0;" ::: "memory")
#define CP_WAIT1()  asm volatile("cp.async.wait_group 1;" ::: "memory")
__device__ __forceinline__ void cpa16(uint32_t saddr, const void* g) {
    asm volatile("cp.async.cg.shared.global [%0], [%1], 16;" :: "r"(saddr), "l"(g) : "memory");
}
__device__ __forceinline__ void mma16816(float* c, const uint32_t* a, const uint32_t* b) {
    asm volatile("mma.sync.aligned.m16n8k16.row.col.f32.f16.f16.f32 "
        "{%0,%1,%2,%3}, {%4,%5,%6,%7}, {%8,%9}, {%0,%1,%2,%3};"
        : "+f"(c[0]), "+f"(c[1]), "+f"(c[2]), "+f"(c[3])
        : "r"(a[0]), "r"(a[1]), "r"(a[2]), "r"(a[3]), "r"(b[0]), "r"(b[1]));
}
__device__ __forceinline__ uint32_t ex2h2(uint32_t x) {
    uint32_t y; asm("ex2.approx.f16x2 %0, %1;" : "=r"(y) : "r"(x)); return y;
}

// ======================= fp32 -> fp16 convert (weights) ======================
__global__ __launch_bounds__(256) void conv_kernel(
    const float* __restrict__ x, __half* __restrict__ y, int n4)
{
    int i = blockIdx.x * 256 + threadIdx.x;
    if (i >= n4) return;
    float4 v = ((const float4*)x)[i];
    __half2* Y = (__half2*)y;
    Y[2*i]   = __floats2half2_rn(v.x, v.y);
    Y[2*i+1] = __floats2half2_rn(v.z, v.w);
}

#if USE_TCGEN05
// ======================= tcgen05 GEMM (sm_103a pass) =========================
__device__ __forceinline__ uint32_t elect_one_pred() {
    uint32_t pred;
    asm volatile(
        "{\n\t.reg .pred p;\n\telect.sync _|p, 0xFFFFFFFF;\n\tselp.b32 %0, 1, 0, p;\n\t}"
        : "=r"(pred));
    return pred;
}
#define MBAR_INIT(addr, cnt) \
    asm volatile("mbarrier.init.shared.b64 [%0], %1;" :: "r"(addr), "r"((uint32_t)(cnt)) : "memory")
#define MBAR_INVAL(addr) \
    asm volatile("mbarrier.inval.shared.b64 [%0];" :: "r"(addr) : "memory")
#define MBAR_WAIT(addr, parity) do { \
    uint32_t _m = (addr); uint32_t _p = (parity); uint32_t _d; \
    asm volatile("{\n\t.reg .pred p;\n\tmbarrier.try_wait.parity.acquire.cta.shared::cta.b64 p, [%1], %2;\n\tselp.b32 %0, 1, 0, p;\n\t}" \
        : "=r"(_d) : "r"(_m), "r"(_p) : "memory"); \
    if (!_d) { \
        asm volatile("{\n\t.reg .pred P1;\n\tWL_%=:\n\tmbarrier.try_wait.parity.acquire.cta.shared::cta.b64 P1, [%0], %1, 0x989680;\n\t@P1 bra.uni WD_%=;\n\tbra.uni WL_%=;\n\tWD_%=:\n\t}" \
            :: "r"(_m), "r"(_p) : "memory"); \
    } } while(0)
#define TC_ALLOC(smem_addr, n) \
    asm volatile("tcgen05.alloc.cta_group::1.sync.aligned.shared::cta.b32 [%0], %1;" \
        :: "r"((uint32_t)(smem_addr)), "r"((uint32_t)(n)) : "memory")
#define TC_DEALLOC(tmem_addr, n) \
    asm volatile("tcgen05.dealloc.cta_group::1.sync.aligned.b32 %0, %1;" :: "r"(tmem_addr), "r"((uint32_t)(n)))
#define TC_RELINQ() \
    asm volatile("tcgen05.relinquish_alloc_permit.cta_group::1.sync.aligned;")
#define TC_COMMIT(mbar) \
    asm volatile("tcgen05.commit.cta_group::1.mbarrier::arrive::one.shared::cluster.b64 [%0];" \
        :: "r"((uint32_t)(mbar)) : "memory")
#define TC_FENCE_AFTER() asm volatile("tcgen05.fence::after_thread_sync;" ::: "memory")
#define TC_FENCE_BEFORE() asm volatile("tcgen05.fence::before_thread_sync;" ::: "memory")
#define TC_WAIT_LD() asm volatile("tcgen05.wait::ld.sync.aligned;" ::: "memory")
#define FENCE_ASYNC_SHARED() asm volatile("fence.proxy.async.shared::cta;" ::: "memory")
#define TC_LD_X32(r, tmem_addr) \
    asm volatile("tcgen05.ld.sync.aligned.32x32b.x32.b32 " \
        "{%0, %1, %2, %3, %4, %5, %6, %7, %8, %9, %10, %11, %12, %13, %14, %15, " \
        " %16, %17, %18, %19, %20, %21, %22, %23, %24, %25, %26, %27, %28, %29, %30, %31}, [%32];" \
        : "=r"((r)[0]),  "=r"((r)[1]),  "=r"((r)[2]),  "=r"((r)[3]), \
          "=r"((r)[4]),  "=r"((r)[5]),  "=r"((r)[6]),  "=r"((r)[7]), \
          "=r"((r)[8]),  "=r"((r)[9]),  "=r"((r)[10]), "=r"((r)[11]), \
          "=r"((r)[12]), "=r"((r)[13]), "=r"((r)[14]), "=r"((r)[15]), \
          "=r"((r)[16]), "=r"((r)[17]), "=r"((r)[18]), "=r"((r)[19]), \
          "=r"((r)[20]), "=r"((r)[21]), "=r"((r)[22]), "=r"((r)[23]), \
          "=r"((r)[24]), "=r"((r)[25]), "=r"((r)[26]), "=r"((r)[27]), \
          "=r"((r)[28]), "=r"((r)[29]), "=r"((r)[30]), "=r"((r)[31]) \
        : "r"(tmem_addr))

__device__ __forceinline__ uint64_t mk_desc(uint32_t addr) {
    const uint64_t base = (2ull << 61) | (1ull << 46) | (64ull << 32) | (1ull << 16);
    return base | ((uint64_t)(addr >> 4) & 0x3FFF);
}
__device__ __forceinline__ void mma_f16_ss(uint32_t d, uint64_t da, uint64_t db,
                                           uint32_t idesc, uint32_t en) {
    asm volatile(
        "{\n\t.reg .pred p;\n\tsetp.ne.u32 p, %5, 0;\n\t"
        "tcgen05.mma.cta_group::1.kind::f16 [%0], %1, %2, %3, {%4,%4,%4,%4}, p;\n\t}"
        :: "r"(d), "l"(da), "l"(db), "r"(idesc), "r"(0u), "r"(en) : "memory");
}

#define GM_IDESC 0x8400010u              // F32 acc, fp16 a/b, M=128, N=256

__device__ __forceinline__ void gm_load_stage(
    uint32_t stb,
    const __half* __restrict__ A, const __half* __restrict__ B,
    int bm, int bn, int K, int kc, int tid)
{
    #pragma unroll
    for (int it = 0; it < 8; it++) {                 // A: 256 rows x 8 vec8
        int v = tid + it * 256;
        int r = v >> 3, cv = v & 7;
        uint32_t off = (uint32_t)((r & 127)*128 + cv*16);
        uint32_t sw = off ^ ((off >> 3) & 0x70);
        cpa16(stb + (uint32_t)(r >> 7)*16384 + sw,
              A + (size_t)(bm + r) * K + kc + cv*8);
    }
    #pragma unroll
    for (int it = 0; it < 8; it++) {                 // B: 256 rows x 8 vec8
        int v = tid + it * 256;
        int r = v >> 3, cv = v & 7;
        uint32_t off = (uint32_t)(r*128 + cv*16);
        uint32_t sw = off ^ ((off >> 3) & 0x70);
        cpa16(stb + 32768 + sw, B + (size_t)(bn + r) * K + kc + cv*8);
    }
    CP_COMMIT();
}

__global__ __launch_bounds__(256, 1) void tc_gemm(
    const __half* __restrict__ A, const __half* __restrict__ B,
    float* __restrict__ Cf, __half* __restrict__ Ch,
    const float* __restrict__ addend,
    int M, int N, int K)
{
    extern __shared__ char smem[];
    uint32_t sb = smem_u32(smem);
    int tid = threadIdx.x;
    int wid = tid >> 5, lane = tid & 31;
    int bn = blockIdx.x * 256, bm = blockIdx.y * 256;

    if (wid == 0) { TC_ALLOC(sb, 512); TC_RELINQ(); }
    if (tid == 0) { MBAR_INIT(sb + 8, 1); MBAR_INIT(sb + 16, 1); MBAR_INIT(sb + 24, 1); }
    __syncthreads();
    uint32_t tmem;
    asm volatile("ld.shared.b32 %0, [%1];" : "=r"(tmem) : "r"(sb));

    const int NC = K / 64;
    int ph0 = 0, ph1 = 0;

    gm_load_stage(sb + 1024, A, B, bm, bn, K, 0, tid);
    gm_load_stage(sb + 1024 + GM_STAGE_BYTES, A, B, bm, bn, K, 64, tid);

    for (int c = 0; c < NC; c++) {
        int s = c % GM_NSTAGE;
        if (c + 1 < NC) { CP_WAIT1(); } else { CP_WAIT0(); }
        __syncthreads();
        uint32_t stb = sb + 1024 + (uint32_t)s * GM_STAGE_BYTES;
        if (wid == 0 && elect_one_pred()) {
            FENCE_ASYNC_SHARED();
            uint64_t dA0 = mk_desc(stb);
            uint64_t dA1 = mk_desc(stb + 16384);
            uint64_t dB  = mk_desc(stb + 32768);
            #pragma unroll
            for (int k = 0; k < 4; k++) {
                uint32_t en = (c > 0) || (k > 0);
                mma_f16_ss(tmem,       dA0 + k*2, dB + k*2, GM_IDESC, en);
                mma_f16_ss(tmem + 256, dA1 + k*2, dB + k*2, GM_IDESC, en);
            }
            TC_COMMIT(sb + 8 + (uint32_t)(c & 1) * 8);
            if (c == NC - 1) TC_COMMIT(sb + 24);   // dedicated final-completion mbar
        }
        if (c + 2 < NC) {
            if (c >= 1) {
                int m = (c - 1) & 1;
                if (m == 0) { MBAR_WAIT(sb + 8, ph0);  ph0 ^= 1; }
                else        { MBAR_WAIT(sb + 16, ph1); ph1 ^= 1; }
            }
            gm_load_stage(sb + 1024 + (uint32_t)((c + 2) % GM_NSTAGE) * GM_STAGE_BYTES,
                          A, B, bm, bn, K, (c + 2) * 64, tid);
        }
    }
    MBAR_WAIT(sb + 24, 0);
    TC_FENCE_AFTER();

    int wg = wid >> 2, ws = wid & 3;
    #pragma unroll
    for (int h = 0; h < 2; h++) {
        size_t row = (size_t)(bm + h*128 + ws * 32 + lane);
        #pragma unroll
        for (int cb = 0; cb < 4; cb++) {
            uint32_t regs[32];
            TC_LD_X32(regs, tmem + (uint32_t)(h*256 + wg * 128 + cb * 32));
            TC_WAIT_LD();
            int col = bn + wg * 128 + cb * 32;
            if (Ch) {
                __half* Cp = Ch + row * (size_t)N + col;
                #pragma unroll
                for (int j = 0; j < 32; j += 8) {
                    __half2 o[4];
                    o[0] = __floats2half2_rn(__uint_as_float(regs[j]),   __uint_as_float(regs[j+1]));
                    o[1] = __floats2half2_rn(__uint_as_float(regs[j+2]), __uint_as_float(regs[j+3]));
                    o[2] = __floats2half2_rn(__uint_as_float(regs[j+4]), __uint_as_float(regs[j+5]));
                    o[3] = __floats2half2_rn(__uint_as_float(regs[j+6]), __uint_as_float(regs[j+7]));
                    *(uint4*)(Cp + j) = *(uint4*)o;
                }
            } else {
                float* Cp = Cf + row * (size_t)N + col;
                if (addend) {
                    const float* Ap = addend + row * (size_t)N + col;
                    #pragma unroll
                    for (int j = 0; j < 32; j += 4) {
                        float4 a = *(const float4*)(Ap + j);
                        float4 o = make_float4(__uint_as_float(regs[j])   + a.x,
                                               __uint_as_float(regs[j+1]) + a.y,
                                               __uint_as_float(regs[j+2]) + a.z,
                                               __uint_as_float(regs[j+3]) + a.w);
                        *(float4*)(Cp + j) = o;
                    }
                } else {
                    #pragma unroll
                    for (int j = 0; j < 32; j += 4) {
                        float4 o = make_float4(__uint_as_float(regs[j]),
                                               __uint_as_float(regs[j+1]),
                                               __uint_as_float(regs[j+2]),
                                               __uint_as_float(regs[j+3]));
                        *(float4*)(Cp + j) = o;
                    }
                }
            }
        }
    }
    TC_FENCE_BEFORE();
    __syncthreads();
    if (tid == 0) { MBAR_INVAL(sb + 8); MBAR_INVAL(sb + 16); MBAR_INVAL(sb + 24); }
    if (wid == 0) { TC_DEALLOC(tmem, 512); }
}

#else
// ======================= mma.sync GEMM fallback ==============================
#define FB_LD 40

__global__ __launch_bounds__(256, 1) void tc_gemm(
    const __half* __restrict__ A, const __half* __restrict__ B,
    float* __restrict__ Cf, __half* __restrict__ Ch,
    const float* __restrict__ addend,
    int M, int N, int K)
{
    extern __shared__ char smem[];
    __half* sA = (__half*)smem;               // [128][40]
    __half* sB = sA + 128*FB_LD;              // [256][40]
    int tid = threadIdx.x, lane = tid & 31, wid = tid >> 5;
    int bn = blockIdx.x * 256;
    int wm = wid >> 2, wn = wid & 3;
    int g = lane >> 2, tig = lane & 3;

    for (int half = 0; half < 2; half++) {
        int bm = blockIdx.y * 256 + half * 128;
        float acc[4][8][4];
        #pragma unroll
        for (int mt = 0; mt < 4; mt++)
            #pragma unroll
            for (int nt = 0; nt < 8; nt++)
                #pragma unroll
                for (int q = 0; q < 4; q++) acc[mt][nt][q] = 0.f;

        for (int k0 = 0; k0 < K; k0 += 32) {
            __syncthreads();
            for (int v = tid; v < 512; v += 256) {
                int r = v >> 2, q = v & 3;
                *(uint4*)&sA[r*FB_LD + q*8] = *(const uint4*)(A + (size_t)(bm+r)*K + k0 + q*8);
            }
            for (int v = tid; v < 1024; v += 256) {
                int r = v >> 2, q = v & 3;
                *(uint4*)&sB[r*FB_LD + q*8] = *(const uint4*)(B + (size_t)(bn+r)*K + k0 + q*8);
            }
            __syncthreads();
            #pragma unroll
            for (int ks = 0; ks < 2; ks++) {
                int kk = ks * 16 + tig * 2;
                uint32_t a[4][4], b[8][2];
                #pragma unroll
                for (int mt = 0; mt < 4; mt++) {
                    int mr = (wm*64 + mt*16 + g)*FB_LD + kk;
                    a[mt][0] = *(const uint32_t*)&sA[mr];
                    a[mt][1] = *(const uint32_t*)&sA[mr + 8*FB_LD];
                    a[mt][2] = *(const uint32_t*)&sA[mr + 8];
                    a[mt][3] = *(const uint32_t*)&sA[mr + 8*FB_LD + 8];
                }
                #pragma unroll
                for (int nt = 0; nt < 8; nt++) {
                    int nr = (wn*64 + nt*8 + g)*FB_LD + kk;
                    b[nt][0] = *(const uint32_t*)&sB[nr];
                    b[nt][1] = *(const uint32_t*)&sB[nr + 8];
                }
                #pragma unroll
                for (int mt = 0; mt < 4; mt++)
                    #pragma unroll
                    for (int nt = 0; nt < 8; nt++)
                        mma16816(acc[mt][nt], a[mt], b[nt]);
            }
        }
        #pragma unroll
        for (int mt = 0; mt < 4; mt++) {
            #pragma unroll
            for (int nt = 0; nt < 8; nt++) {
                size_t r0 = (size_t)(bm + wm*64 + mt*16 + g);
                int col = bn + wn*64 + nt*8 + tig*2;
                if (Ch) {
                    *(__half2*)(Ch + r0*N + col)     = __floats2half2_rn(acc[mt][nt][0], acc[mt][nt][1]);
                    *(__half2*)(Ch + (r0+8)*N + col) = __floats2half2_rn(acc[mt][nt][2], acc[mt][nt][3]);
                } else {
                    float2 v0 = make_float2(acc[mt][nt][0], acc[mt][nt][1]);
                    float2 v1 = make_float2(acc[mt][nt][2], acc[mt][nt][3]);
                    if (addend) {
                        float2 a0 = *(const float2*)(addend + r0*N + col);
                        float2 a1 = *(const float2*)(addend + (r0+8)*N + col);
                        v0.x += a0.x; v0.y += a0.y; v1.x += a1.x; v1.y += a1.y;
                    }
                    *(float2*)(Cf + r0*N + col)     = v0;
                    *(float2*)(Cf + (r0+8)*N + col) = v1;
                }
            }
        }
        __syncthreads();
    }
}
#endif  // USE_TCGEN05

// ---------------- RMSNorm -> fp16 --------------------------------------------
__global__ __launch_bounds__(256) void rmsnorm_h_kernel(
    const float* __restrict__ x, const float* __restrict__ w,
    __half* __restrict__ out)
{
    __shared__ float red[8];
    int row = blockIdx.x;
    int tid = threadIdx.x;
    const float4* xr = (const float4*)(x + (size_t)row * EMBED);
    const float4* w4 = (const float4*)w;
    float4 v0 = xr[tid];
    float4 v1 = xr[tid + 256];
    float ss = v0.x*v0.x + v0.y*v0.y + v0.z*v0.z + v0.w*v0.w
             + v1.x*v1.x + v1.y*v1.y + v1.z*v1.z + v1.w*v1.w;
    #pragma unroll
    for (int o = 16; o > 0; o >>= 1) ss += __shfl_xor_sync(0xffffffffu, ss, o);
    if ((tid & 31) == 0) red[tid >> 5] = ss;
    __syncthreads();
    float tot = red[0] + red[1] + red[2] + red[3] + red[4] + red[5] + red[6] + red[7];
    float inv = rsqrtf(tot * (1.0f / EMBED) + 1e-5f);
    float4 wa = w4[tid], wb = w4[tid + 256];
    __half2* O = (__half2*)(out + (size_t)row * EMBED);
    O[2*tid]         = __floats2half2_rn(v0.x*inv*wa.x, v0.y*inv*wa.y);
    O[2*tid+1]       = __floats2half2_rn(v0.z*inv*wa.z, v0.w*inv*wa.w);
    O[2*(tid+256)]   = __floats2half2_rn(v1.x*inv*wb.x, v1.y*inv*wb.y);
    O[2*(tid+256)+1] = __floats2half2_rn(v1.z*inv*wb.z, v1.w*inv*wb.w);
}

// ---------------- RoPE (q,k only; fp16 in -> fp16 out) -----------------------
__global__ __launch_bounds__(256) void rope_kernel(
    const __half* __restrict__ qkv, const float* __restrict__ freqs,
    __half* __restrict__ qh, __half* __restrict__ kh)
{
    int s = blockIdx.x, b = blockIdx.y, tid = threadIdx.x;
    const __half* row = qkv + ((size_t)b * SS + s) * QKV_N;
    const float* f = freqs + (size_t)s * HD;
    // 1/sqrt(EMBED) * log2(e): softmax done in exp2 domain
    const float scale = 0.02209708691207961f * 1.4426950408889634f;

    for (int p = tid; p < NH * 64; p += 256) {
        int h = p >> 6, i = p & 63;
        __half2 xv = *(const __half2*)(row + h*HD + 2*i);
        float x0 = __half2float(__low2half(xv)), x1 = __half2float(__high2half(xv));
        float c = f[2*i], sn = f[2*i+1];
        __half2* dst = (__half2*)(qh + ((size_t)(b*NH + h) * SS + s) * HD + 2*i);
        *dst = __floats2half2_rn((x0*c - x1*sn) * scale, (x1*c + x0*sn) * scale);
    }
    for (int p = tid; p < NKV * 64; p += 256) {
        int h = p >> 6, i = p & 63;
        __half2 xv = *(const __half2*)(row + NH*HD + h*HD + 2*i);
        float x0 = __half2float(__low2half(xv)), x1 = __half2float(__high2half(xv));
        float c = f[2*i], sn = f[2*i+1];
        __half2* dst = (__half2*)(kh + ((size_t)(b*NKV + h) * SS + s) * HD + 2*i);
        *dst = __floats2half2_rn(x0*c - x1*sn, x1*c + x0*sn);
    }
}

// ---------------- Coalesced V transpose: [b,s,(kvh,d)] -> [b,kvh,d,s] --------
__global__ __launch_bounds__(256) void vtrans_kernel(
    const __half* __restrict__ qkv, __half* __restrict__ vh)
{
    __shared__ __half t[64*136];   // [64 s][128 d] padded
    int s0 = blockIdx.x * 64, h = blockIdx.y, b = blockIdx.z;
    int tid = threadIdx.x;
    const __half* src = qkv + ((size_t)b * SS + s0) * QKV_N + (size_t)(NH + NKV)*HD + h*HD;
    for (int i = tid; i < 64*16; i += 256) {
        int r = i >> 4, c = i & 15;
        *(uint4*)&t[r*136 + c*8] = *(const uint4*)(src + (size_t)r * QKV_N + c*8);
    }
    __syncthreads();
    __half* dst = vh + ((size_t)(b*NKV + h) * HD) * SS + s0;
    for (int i = tid; i < 128*8; i += 256) {
        int d = i >> 3, c = i & 7;
        __half v[8];
        #pragma unroll
        for (int j = 0; j < 8; j++) v[j] = t[(c*8 + j)*136 + d];
        *(uint4*)(dst + (size_t)d * SS + c*8) = *(uint4*)v;
    }
}

// ---------------- Tensor-core flash attention (fp16 mma, f16x2 exp2) ---------
// Double-buffered K/V; no running max; P = ex2.f16x2(S); l via ones-MMA.
#define FLH_SMEM_BYTES ((128*136 + 2*64*136 + 2*128*72) * 2)
__global__ __launch_bounds__(256) void flash_tc_kernel(
    const __half* __restrict__ qh, const __half* __restrict__ kh,
    const __half* __restrict__ vh, __half* __restrict__ oh)
{
    extern __shared__ __half smh[];
    __half* Qs  = smh;                      // [128][136]
    __half* Ks0 = Qs + 128*136;             // [64][136] x2
    __half* Ks1 = Ks0 + 64*136;
    __half* Vs0 = Ks1 + 64*136;             // [128][72] x2 (Vt: [d][kc])
    __half* Vs1 = Vs0 + 128*72;
    int tid = threadIdx.x, lane = tid & 31, wid = tid >> 5;
    int g = lane >> 2, tig = lane & 3;
    int qb = gridDim.x - 1 - blockIdx.x;    // biggest workload first
    int hb = blockIdx.y, bb = blockIdx.z;
    uint32_t ksb[2] = {smem_u32(Ks0), smem_u32(Ks1)};
    uint32_t vsb[2] = {smem_u32(Vs0), smem_u32(Vs1)};
    uint32_t qsb = smem_u32(Qs);

    const __half* Qg = qh + ((size_t)(bb*NH + hb) * SS + (size_t)qb*128) * HD;
    const __half* Kg = kh + (size_t)(bb*NKV + (hb >> 2)) * SS * HD;
    const __half* Vg = vh + (size_t)(bb*NKV + (hb >> 2)) * HD * SS;

    // prologue: Q + K/V stage 0 in one cp.async group
    for (int i = tid; i < 128*16; i += 256) {
        int r = i >> 4, c = i & 15;
        cpa16(qsb + (uint32_t)(r*136 + c*8)*2, Qg + r*HD + c*8);
    }
    {   // stage 0
        for (int i = tid; i < 64*16; i += 256) {
            int r = i >> 4, c = i & 15;
            cpa16(ksb[0] + (uint32_t)(r*136 + c*8)*2, Kg + (size_t)r*HD + c*8);
        }
        for (int i = tid; i < 128*8; i += 256) {
            int r = i >> 3, c = i & 7;
            cpa16(vsb[0] + (uint32_t)(r*72 + c*8)*2, Vg + (size_t)r*SS + c*8);
        }
        CP_COMMIT();
    }

    float accO[16][4];
    #pragma unroll
    for (int nd = 0; nd < 16; nd++)
        #pragma unroll
        for (int q = 0; q < 4; q++) accO[nd][q] = 0.f;
    float accL[4] = {0.f, 0.f, 0.f, 0.f};   // row sums via ones-MMA
    const uint32_t ONES2 = 0x3C003C00u;     // half2(1,1)
    uint32_t b_ones[2] = {ONES2, ONES2};
    int r0 = qb*128 + wid*16 + g;
    int r1 = r0 + 8;

    int nkb = 2*(qb + 1);
    for (int kb = 0; kb < nkb; kb++) {
        int st = kb & 1;
        if (kb + 1 < nkb) {
            int st2 = st ^ 1;
            for (int i = tid; i < 64*16; i += 256) {
                int r = i >> 4, c = i & 15;
                cpa16(ksb[st2] + (uint32_t)(r*136 + c*8)*2,
                      Kg + (size_t)((kb+1)*64 + r)*HD + c*8);
            }
            for (int i = tid; i < 128*8; i += 256) {
                int r = i >> 3, c = i & 7;
                cpa16(vsb[st2] + (uint32_t)(r*72 + c*8)*2,
                      Vg + (size_t)r*SS + (kb+1)*64 + c*8);
            }
            CP_COMMIT(); CP_WAIT1();
        } else {
            CP_WAIT0();
        }
        __syncthreads();
        const __half* Ks = (st == 0) ? Ks0 : Ks1;
        const __half* Vs = (st == 0) ? Vs0 : Vs1;

        // S = Q*K^T  (128x64), warp: 16 rows
        float sacc[8][4];
        #pragma unroll
        for (int nt = 0; nt < 8; nt++)
            #pragma unroll
            for (int q = 0; q < 4; q++) sacc[nt][q] = 0.f;
        #pragma unroll
        for (int ks = 0; ks < 8; ks++) {
            uint32_t a[4];
            const __half* qr = &Qs[(wid*16 + g)*136 + ks*16 + 2*tig];
            a[0] = *(const uint32_t*)qr;
            a[1] = *(const uint32_t*)(qr + 8*136);
            a[2] = *(const uint32_t*)(qr + 8);
            a[3] = *(const uint32_t*)(qr + 8*136 + 8);
            #pragma unroll
            for (int nt = 0; nt < 8; nt++) {
                uint32_t b[2];
                const __half* kr = &Ks[(nt*8 + g)*136 + ks*16 + 2*tig];
                b[0] = *(const uint32_t*)kr;
                b[1] = *(const uint32_t*)(kr + 8);
                mma16816(sacc[nt], a, b);
            }
        }
        if (kb >= 2*qb) {   // causal mask on diagonal tiles
            #pragma unroll
            for (int nt = 0; nt < 8; nt++) {
                int col = kb*64 + nt*8 + 2*tig;
                if (col     > r0) sacc[nt][0] = -10000.f;
                if (col + 1 > r0) sacc[nt][1] = -10000.f;
                if (col     > r1) sacc[nt][2] = -10000.f;
                if (col + 1 > r1) sacc[nt][3] = -10000.f;
            }
        }
        // P = exp2(S) computed in f16x2; l accumulated via ones-MMA.
        // O += P*V; fragments built directly from half2 exps.
        #pragma unroll
        for (int j = 0; j < 4; j++) {
            uint32_t a[4];
            __half2 t;
            t = __floats2half2_rn(sacc[2*j][0],   sacc[2*j][1]);   a[0] = ex2h2(*(uint32_t*)&t);
            t = __floats2half2_rn(sacc[2*j][2],   sacc[2*j][3]);   a[1] = ex2h2(*(uint32_t*)&t);
            t = __floats2half2_rn(sacc[2*j+1][0], sacc[2*j+1][1]); a[2] = ex2h2(*(uint32_t*)&t);
            t = __floats2half2_rn(sacc[2*j+1][2], sacc[2*j+1][3]); a[3] = ex2h2(*(uint32_t*)&t);
            mma16816(accL, a, b_ones);      // row sums (all 8 cols identical)
            #pragma unroll
            for (int nd = 0; nd < 16; nd++) {
                uint32_t b[2];
                const __half* vr = &Vs[(nd*8 + g)*72 + j*16 + 2*tig];
                b[0] = *(const uint32_t*)vr;
                b[1] = *(const uint32_t*)(vr + 8);
                mma16816(accO[nd], a, b);
            }
        }
        __syncthreads();   // protect buffers before next iteration's loads
    }
    // epilogue: O /= l -> fp16 via smem staging (reuse Qs area)
    float inv0 = 1.f / accL[0], inv1 = 1.f / accL[2];
    __half* stg = smh;   // [128][136]
    int lr = wid*16 + g;
    size_t obase = ((size_t)bb*SS + (size_t)qb*128) * EMBED + hb*HD;
    #pragma unroll
    for (int nd = 0; nd < 16; nd++) {
        int col = nd*8 + 2*tig;
        *(__half2*)&stg[lr*136 + col] =
            __floats2half2_rn(accO[nd][0]*inv0, accO[nd][1]*inv0);
        *(__half2*)&stg[(lr+8)*136 + col] =
            __floats2half2_rn(accO[nd][2]*inv1, accO[nd][3]*inv1);
    }
    __syncthreads();
    for (int i = tid; i < 128*16; i += 256) {
        int r = i >> 4, c = i & 15;
        *(uint4*)(oh + obase + (size_t)r*EMBED + c*8) = *(uint4*)&stg[r*136 + c*8];
    }
}

// ---------------- SwiGLU (fp16 combined gate|up -> fp16) ---------------------
__global__ __launch_bounds__(256) void silu_h_kernel(
    const __half* __restrict__ u, __half* __restrict__ out, int n8)
{
    int i = blockIdx.x * 256 + threadIdx.x;
    if (i >= n8) return;
    int row = i / (FF/8), c8 = i % (FF/8);
    const __half* gp = u + (size_t)row * 2*FF + c8*8;
    uint4 gv = *(const uint4*)gp;
    uint4 uv = *(const uint4*)(gp + FF);
    __half2* gh = (__half2*)&gv;
    __half2* uh = (__half2*)&uv;
    __half2 o[4];
    #pragma unroll
    for (int q = 0; q < 4; q++) {
        float a0 = __half2float(__low2half(gh[q])), a1 = __half2float(__high2half(gh[q]));
        float b0 = __half2float(__low2half(uh[q])), b1 = __half2float(__high2half(uh[q]));
        o[q] = __floats2half2_rn(a0 / (1.f + __expf(-a0)) * b0,
                                 a1 / (1.f + __expf(-a1)) * b1);
    }
    *(uint4*)(out + (size_t)row * FF + c8*8) = *(uint4*)o;
}

// ---------------- driver ------------------------------------------------------
static inline void conv_launch(const float* src, __half* dst, size_t n)
{
    int n4 = (int)(n / 4);
    conv_kernel<<<(n4 + 255)/256, 256>>>(src, dst, n4);
}

extern "C" void kernel_launch(void* const* d_in, const int* in_sizes, int n_in,
                              void* d_out, int out_size)
{
    const float* x       = (const float*)d_in[0];
    const float* freqs   = (const float*)d_in[2];
    const float* w_qkv   = (const float*)d_in[4];
    const float* w_fc    = (const float*)d_in[5];
    const float* w1      = (const float*)d_in[6];
    const float* w2      = (const float*)d_in[7];
    const float* w3      = (const float*)d_in[8];
    const float* attn_nw = (const float*)d_in[9];
    const float* ff_nw   = (const float*)d_in[10];
    float* out = (float*)d_out;

    float *h1;
    __half *qkvh, *qh, *kh, *vh, *uh, *ah, *wh;
    cudaGetSymbolAddress((void**)&qkvh, g_qkvh);
    cudaGetSymbolAddress((void**)&qh,  g_qh2);
    cudaGetSymbolAddress((void**)&kh,  g_kh2);
    cudaGetSymbolAddress((void**)&vh,  g_vh2);
    cudaGetSymbolAddress((void**)&h1,  g_h1);
    cudaGetSymbolAddress((void**)&uh,  g_uh);
    cudaGetSymbolAddress((void**)&ah,  g_ah);
    cudaGetSymbolAddress((void**)&wh,  g_wh);

    cudaFuncSetAttribute(tc_gemm, cudaFuncAttributeMaxDynamicSharedMemorySize, GM_SMEM_BYTES);
    cudaFuncSetAttribute(flash_tc_kernel, cudaFuncAttributeMaxDynamicSharedMemorySize, FLH_SMEM_BYTES);

    // 1. attn rmsnorm -> fp16
    rmsnorm_h_kernel<<<ROWS, 256>>>(x, attn_nw, ah);
    // 2. qkv projection -> fp16 qkvh
    conv_launch(w_qkv, wh, (size_t)QKV_N*EMBED);
    tc_gemm<<<dim3(QKV_N/256, ROWS/256), 256, GM_SMEM_BYTES>>>(
        ah, wh, nullptr, qkvh, nullptr, ROWS, QKV_N, EMBED);
    // 3. rope (q,k) + coalesced V transpose
    rope_kernel<<<dim3(SS, BB), 256>>>(qkvh, freqs, qh, kh);
    vtrans_kernel<<<dim3(SS/64, NKV, BB), 256>>>(qkvh, vh);
    // 4. tensor-core flash attention -> fp16 attn into g_ah
    flash_tc_kernel<<<dim3(SS/128, NH, BB), 256, FLH_SMEM_BYTES>>>(qh, kh, vh, ah);
    // 5. output projection + residual -> fp32 h1
    conv_launch(w_fc, wh, (size_t)EMBED*EMBED);
    tc_gemm<<<dim3(EMBED/256, ROWS/256), 256, GM_SMEM_BYTES>>>(
        ah, wh, h1, nullptr, x, ROWS, EMBED, EMBED);
    // 6. ffn rmsnorm -> fp16
    rmsnorm_h_kernel<<<ROWS, 256>>>(h1, ff_nw, ah);
    // 7. combined gate|up projection -> fp16 uh
    conv_launch(w1, wh, (size_t)FF*EMBED);
    conv_launch(w2, wh + (size_t)FF*EMBED, (size_t)FF*EMBED);
    tc_gemm<<<dim3(2*FF/256, ROWS/256), 256, GM_SMEM_BYTES>>>(
        ah, wh, nullptr, uh, nullptr, ROWS, 2*FF, EMBED);
    // 8. swiglu -> fp16 ah
    silu_h_kernel<<<(ROWS*FF/8 + 255)/256, 256>>>(uh, ah, ROWS*FF/8);
    // 9. down projection + residual -> out
    conv_launch(w3, wh, (size_t)EMBED*FF);
    tc_gemm<<<dim3(EMBED/256, ROWS/256), 256, GM_SMEM_BYTES>>>(
        ah, wh, out, nullptr, h1, ROWS, EMBED, FF);
}

// round 13
// speedup vs baseline: 28.2090x; 1.0230x over previous
#include <cuda_runtime.h>
#include <cuda_bf16.h>
#include <cuda_fp16.h>
#include <math.h>
#include <stdint.h>

#define EMBED 2048
#define NH 16
#define NKV 4
#define HD 128
#define FF 5632
#define BB 2
#define SS 2048
#define ROWS (BB*SS)                 // 4096 tokens
#define QKV_N ((NH + 2*NKV)*HD)      // 3072

#if defined(__CUDA_ARCH_FEAT_SM103_ALL) || defined(__CUDA_ARCH_FEAT_SM100_ALL)
#define USE_TCGEN05 1
#else
#define USE_TCGEN05 0
#endif

// ---------------- scratch (device globals; no allocations allowed) ----------
__device__ __half g_qkvh[ROWS*QKV_N];     // fp16 qkv gemm output
__device__ __half g_qh2[BB*NH *SS*HD];    // fp16 Q (scaled by 1/sqrt(E)*log2e), [b,h,s,d]
__device__ __half g_kh2[BB*NKV*SS*HD];    // fp16 K, [b,kvh,s,d]
__device__ __half g_vh2[BB*NKV*HD*SS];    // fp16 V transposed, [b,kvh,d,s]
__device__ float  g_h1 [ROWS*EMBED];
__device__ __half g_ah [ROWS*FF];         // fp16 activations (gemm A operand)
__device__ __half g_sw [ROWS*FF];         // fp16 fused-swiglu output (down-proj A)
__device__ __half g_wh [2*FF*EMBED];      // fp16 weights     (gemm B operand)

#define GM_STAGE_BYTES 65536              // A0 16K + A1 16K + B 32K
#define GM_NSTAGE 3
#define GM_SMEM_BYTES (1024 + GM_NSTAGE*GM_STAGE_BYTES)

// ---------- common helpers (legal on plain sm_103 PTX) ----------------------
__device__ __forceinline__ uint32_t smem_u32(const void* p) {
    uint32_t a;
    asm("{ .reg .u64 t; cvta.to.shared.u64 t, %1; cvt.u32.u64 %0, t; }" : "=r"(a) : "l"(p));
    return a;
}
#define CP_COMMIT() asm volatile("cp.async.commit_group;" ::: "memory")
#define CP_WAIT0()  asm volatile("cp.async.wait_group 0;" ::: "memory")
#define CP_WAIT1()  asm volatile("cp.async.wait_group 1;" ::: "memory")
__device__ __forceinline__ void cpa16(uint32_t saddr, const void* g) {
    asm volatile("cp.async.cg.shared.global [%0], [%1], 16;" :: "r"(saddr), "l"(g) : "memory");
}
__device__ __forceinline__ void mma16816(float* c, const uint32_t* a, const uint32_t* b) {
    asm volatile("mma.sync.aligned.m16n8k16.row.col.f32.f16.f16.f32 "
        "{%0,%1,%2,%3}, {%4,%5,%6,%7}, {%8,%9}, {%0,%1,%2,%3};"
        : "+f"(c[0]), "+f"(c[1]), "+f"(c[2]), "+f"(c[3])
        : "r"(a[0]), "r"(a[1]), "r"(a[2]), "r"(a[3]), "r"(b[0]), "r"(b[1]));
}
__device__ __forceinline__ uint32_t ex2h2(uint32_t x) {
    uint32_t y; asm("ex2.approx.f16x2 %0, %1;" : "=r"(y) : "r"(x)); return y;
}
__device__ __forceinline__ float siluf(float a) {
    return a / (1.f + __expf(-a));
}

// ======================= fp32 -> fp16 convert (weights) ======================
__global__ __launch_bounds__(256) void conv_kernel(
    const float* __restrict__ x, __half* __restrict__ y, int n4)
{
    int i = blockIdx.x * 256 + threadIdx.x;
    if (i >= n4) return;
    float4 v = ((const float4*)x)[i];
    __half2* Y = (__half2*)y;
    Y[2*i]   = __floats2half2_rn(v.x, v.y);
    Y[2*i+1] = __floats2half2_rn(v.z, v.w);
}

// interleave rows: w1 row j -> dst row 2j, w2 row j -> dst row 2j+1
__global__ __launch_bounds__(256) void conv_inter_kernel(
    const float* __restrict__ w1, const float* __restrict__ w2,
    __half* __restrict__ y, int n4)   // n4 = FF*EMBED/4
{
    int i = blockIdx.x * 256 + threadIdx.x;
    if (i >= n4) return;
    const int RQ = EMBED / 4;
    int row = i / RQ, q = i % RQ;
    float4 a = ((const float4*)w1)[i];
    float4 b = ((const float4*)w2)[i];
    __half2* Y1 = (__half2*)(y + ((size_t)(2*row)   * EMBED) + q*4);
    __half2* Y2 = (__half2*)(y + ((size_t)(2*row+1) * EMBED) + q*4);
    Y1[0] = __floats2half2_rn(a.x, a.y);
    Y1[1] = __floats2half2_rn(a.z, a.w);
    Y2[0] = __floats2half2_rn(b.x, b.y);
    Y2[1] = __floats2half2_rn(b.z, b.w);
}

#if USE_TCGEN05
// ======================= tcgen05 GEMM (sm_103a pass) =========================
__device__ __forceinline__ uint32_t elect_one_pred() {
    uint32_t pred;
    asm volatile(
        "{\n\t.reg .pred p;\n\telect.sync _|p, 0xFFFFFFFF;\n\tselp.b32 %0, 1, 0, p;\n\t}"
        : "=r"(pred));
    return pred;
}
#define MBAR_INIT(addr, cnt) \
    asm volatile("mbarrier.init.shared.b64 [%0], %1;" :: "r"(addr), "r"((uint32_t)(cnt)) : "memory")
#define MBAR_INVAL(addr) \
    asm volatile("mbarrier.inval.shared.b64 [%0];" :: "r"(addr) : "memory")
#define MBAR_WAIT(addr, parity) do { \
    uint32_t _m = (addr); uint32_t _p = (parity); uint32_t _d; \
    asm volatile("{\n\t.reg .pred p;\n\tmbarrier.try_wait.parity.acquire.cta.shared::cta.b64 p, [%1], %2;\n\tselp.b32 %0, 1, 0, p;\n\t}" \
        : "=r"(_d) : "r"(_m), "r"(_p) : "memory"); \
    if (!_d) { \
        asm volatile("{\n\t.reg .pred P1;\n\tWL_%=:\n\tmbarrier.try_wait.parity.acquire.cta.shared::cta.b64 P1, [%0], %1, 0x989680;\n\t@P1 bra.uni WD_%=;\n\tbra.uni WL_%=;\n\tWD_%=:\n\t}" \
            :: "r"(_m), "r"(_p) : "memory"); \
    } } while(0)
#define TC_ALLOC(smem_addr, n) \
    asm volatile("tcgen05.alloc.cta_group::1.sync.aligned.shared::cta.b32 [%0], %1;" \
        :: "r"((uint32_t)(smem_addr)), "r"((uint32_t)(n)) : "memory")
#define TC_DEALLOC(tmem_addr, n) \
    asm volatile("tcgen05.dealloc.cta_group::1.sync.aligned.b32 %0, %1;" :: "r"(tmem_addr), "r"((uint32_t)(n)))
#define TC_RELINQ() \
    asm volatile("tcgen05.relinquish_alloc_permit.cta_group::1.sync.aligned;")
#define TC_COMMIT(mbar) \
    asm volatile("tcgen05.commit.cta_group::1.mbarrier::arrive::one.shared::cluster.b64 [%0];" \
        :: "r"((uint32_t)(mbar)) : "memory")
#define TC_FENCE_AFTER() asm volatile("tcgen05.fence::after_thread_sync;" ::: "memory")
#define TC_FENCE_BEFORE() asm volatile("tcgen05.fence::before_thread_sync;" ::: "memory")
#define TC_WAIT_LD() asm volatile("tcgen05.wait::ld.sync.aligned;" ::: "memory")
#define FENCE_ASYNC_SHARED() asm volatile("fence.proxy.async.shared::cta;" ::: "memory")
#define TC_LD_X32(r, tmem_addr) \
    asm volatile("tcgen05.ld.sync.aligned.32x32b.x32.b32 " \
        "{%0, %1, %2, %3, %4, %5, %6, %7, %8, %9, %10, %11, %12, %13, %14, %15, " \
        " %16, %17, %18, %19, %20, %21, %22, %23, %24, %25, %26, %27, %28, %29, %30, %31}, [%32];" \
        : "=r"((r)[0]),  "=r"((r)[1]),  "=r"((r)[2]),  "=r"((r)[3]), \
          "=r"((r)[4]),  "=r"((r)[5]),  "=r"((r)[6]),  "=r"((r)[7]), \
          "=r"((r)[8]),  "=r"((r)[9]),  "=r"((r)[10]), "=r"((r)[11]), \
          "=r"((r)[12]), "=r"((r)[13]), "=r"((r)[14]), "=r"((r)[15]), \
          "=r"((r)[16]), "=r"((r)[17]), "=r"((r)[18]), "=r"((r)[19]), \
          "=r"((r)[20]), "=r"((r)[21]), "=r"((r)[22]), "=r"((r)[23]), \
          "=r"((r)[24]), "=r"((r)[25]), "=r"((r)[26]), "=r"((r)[27]), \
          "=r"((r)[28]), "=r"((r)[29]), "=r"((r)[30]), "=r"((r)[31]) \
        : "r"(tmem_addr))

__device__ __forceinline__ uint64_t mk_desc(uint32_t addr) {
    const uint64_t base = (2ull << 61) | (1ull << 46) | (64ull << 32) | (1ull << 16);
    return base | ((uint64_t)(addr >> 4) & 0x3FFF);
}
__device__ __forceinline__ void mma_f16_ss(uint32_t d, uint64_t da, uint64_t db,
                                           uint32_t idesc, uint32_t en) {
    asm volatile(
        "{\n\t.reg .pred p;\n\tsetp.ne.u32 p, %5, 0;\n\t"
        "tcgen05.mma.cta_group::1.kind::f16 [%0], %1, %2, %3, {%4,%4,%4,%4}, p;\n\t}"
        :: "r"(d), "l"(da), "l"(db), "r"(idesc), "r"(0u), "r"(en) : "memory");
}

#define GM_IDESC 0x8400010u              // F32 acc, fp16 a/b, M=128, N=256

__device__ __forceinline__ void gm_load_stage(
    uint32_t stb,
    const __half* __restrict__ A, const __half* __restrict__ B,
    int bm, int bn, int K, int kc, int tid)
{
    #pragma unroll
    for (int it = 0; it < 8; it++) {                 // A: 256 rows x 8 vec8
        int v = tid + it * 256;
        int r = v >> 3, cv = v & 7;
        uint32_t off = (uint32_t)((r & 127)*128 + cv*16);
        uint32_t sw = off ^ ((off >> 3) & 0x70);
        cpa16(stb + (uint32_t)(r >> 7)*16384 + sw,
              A + (size_t)(bm + r) * K + kc + cv*8);
    }
    #pragma unroll
    for (int it = 0; it < 8; it++) {                 // B: 256 rows x 8 vec8
        int v = tid + it * 256;
        int r = v >> 3, cv = v & 7;
        uint32_t off = (uint32_t)(r*128 + cv*16);
        uint32_t sw = off ^ ((off >> 3) & 0x70);
        cpa16(stb + 32768 + sw, B + (size_t)(bn + r) * K + kc + cv*8);
    }
    CP_COMMIT();
}

// mode: 0 = fp32 out (+optional addend), 1 = fp16 out, 2 = fused silu (pairs)
__global__ __launch_bounds__(256, 1) void tc_gemm(
    const __half* __restrict__ A, const __half* __restrict__ B,
    float* __restrict__ Cf, __half* __restrict__ Ch,
    const float* __restrict__ addend,
    int M, int N, int K, int mode)
{
    extern __shared__ char smem[];
    uint32_t sb = smem_u32(smem);
    int tid = threadIdx.x;
    int wid = tid >> 5, lane = tid & 31;
    int bn = blockIdx.x * 256, bm = blockIdx.y * 256;

    if (wid == 0) { TC_ALLOC(sb, 512); TC_RELINQ(); }
    if (tid == 0) { MBAR_INIT(sb + 8, 1); MBAR_INIT(sb + 16, 1); MBAR_INIT(sb + 24, 1); }
    __syncthreads();
    uint32_t tmem;
    asm volatile("ld.shared.b32 %0, [%1];" : "=r"(tmem) : "r"(sb));

    const int NC = K / 64;
    int ph0 = 0, ph1 = 0;

    gm_load_stage(sb + 1024, A, B, bm, bn, K, 0, tid);
    gm_load_stage(sb + 1024 + GM_STAGE_BYTES, A, B, bm, bn, K, 64, tid);

    for (int c = 0; c < NC; c++) {
        int s = c % GM_NSTAGE;
        if (c + 1 < NC) { CP_WAIT1(); } else { CP_WAIT0(); }
        __syncthreads();
        uint32_t stb = sb + 1024 + (uint32_t)s * GM_STAGE_BYTES;
        if (wid == 0 && elect_one_pred()) {
            FENCE_ASYNC_SHARED();
            uint64_t dA0 = mk_desc(stb);
            uint64_t dA1 = mk_desc(stb + 16384);
            uint64_t dB  = mk_desc(stb + 32768);
            #pragma unroll
            for (int k = 0; k < 4; k++) {
                uint32_t en = (c > 0) || (k > 0);
                mma_f16_ss(tmem,       dA0 + k*2, dB + k*2, GM_IDESC, en);
                mma_f16_ss(tmem + 256, dA1 + k*2, dB + k*2, GM_IDESC, en);
            }
            TC_COMMIT(sb + 8 + (uint32_t)(c & 1) * 8);
            if (c == NC - 1) TC_COMMIT(sb + 24);   // dedicated final-completion mbar
        }
        if (c + 2 < NC) {
            if (c >= 1) {
                int m = (c - 1) & 1;
                if (m == 0) { MBAR_WAIT(sb + 8, ph0);  ph0 ^= 1; }
                else        { MBAR_WAIT(sb + 16, ph1); ph1 ^= 1; }
            }
            gm_load_stage(sb + 1024 + (uint32_t)((c + 2) % GM_NSTAGE) * GM_STAGE_BYTES,
                          A, B, bm, bn, K, (c + 2) * 64, tid);
        }
    }
    MBAR_WAIT(sb + 24, 0);
    TC_FENCE_AFTER();

    int wg = wid >> 2, ws = wid & 3;
    #pragma unroll
    for (int h = 0; h < 2; h++) {
        size_t row = (size_t)(bm + h*128 + ws * 32 + lane);
        #pragma unroll
        for (int cb = 0; cb < 4; cb++) {
            uint32_t regs[32];
            TC_LD_X32(regs, tmem + (uint32_t)(h*256 + wg * 128 + cb * 32));
            TC_WAIT_LD();
            int col = bn + wg * 128 + cb * 32;
            if (mode == 2) {
                // fused swiglu: cols are (gate,up) pairs; out feature = col/2
                __half2 o[8];
                #pragma unroll
                for (int t = 0; t < 16; t += 2) {
                    float r0 = siluf(__uint_as_float(regs[2*t]))   * __uint_as_float(regs[2*t+1]);
                    float r1 = siluf(__uint_as_float(regs[2*t+2])) * __uint_as_float(regs[2*t+3]);
                    o[t >> 1] = __floats2half2_rn(r0, r1);
                }
                __half* Cp = Ch + row * (size_t)FF + (col >> 1);
                *(uint4*)(Cp)     = *(uint4*)&o[0];
                *(uint4*)(Cp + 8) = *(uint4*)&o[4];
            } else if (mode == 1) {
                __half* Cp = Ch + row * (size_t)N + col;
                #pragma unroll
                for (int j = 0; j < 32; j += 8) {
                    __half2 o[4];
                    o[0] = __floats2half2_rn(__uint_as_float(regs[j]),   __uint_as_float(regs[j+1]));
                    o[1] = __floats2half2_rn(__uint_as_float(regs[j+2]), __uint_as_float(regs[j+3]));
                    o[2] = __floats2half2_rn(__uint_as_float(regs[j+4]), __uint_as_float(regs[j+5]));
                    o[3] = __floats2half2_rn(__uint_as_float(regs[j+6]), __uint_as_float(regs[j+7]));
                    *(uint4*)(Cp + j) = *(uint4*)o;
                }
            } else {
                float* Cp = Cf + row * (size_t)N + col;
                if (addend) {
                    const float* Ap = addend + row * (size_t)N + col;
                    #pragma unroll
                    for (int j = 0; j < 32; j += 4) {
                        float4 a = *(const float4*)(Ap + j);
                        float4 o = make_float4(__uint_as_float(regs[j])   + a.x,
                                               __uint_as_float(regs[j+1]) + a.y,
                                               __uint_as_float(regs[j+2]) + a.z,
                                               __uint_as_float(regs[j+3]) + a.w);
                        *(float4*)(Cp + j) = o;
                    }
                } else {
                    #pragma unroll
                    for (int j = 0; j < 32; j += 4) {
                        float4 o = make_float4(__uint_as_float(regs[j]),
                                               __uint_as_float(regs[j+1]),
                                               __uint_as_float(regs[j+2]),
                                               __uint_as_float(regs[j+3]));
                        *(float4*)(Cp + j) = o;
                    }
                }
            }
        }
    }
    TC_FENCE_BEFORE();
    __syncthreads();
    if (tid == 0) { MBAR_INVAL(sb + 8); MBAR_INVAL(sb + 16); MBAR_INVAL(sb + 24); }
    if (wid == 0) { TC_DEALLOC(tmem, 512); }
}

#else
// ======================= mma.sync GEMM fallback ==============================
#define FB_LD 40

__global__ __launch_bounds__(256, 1) void tc_gemm(
    const __half* __restrict__ A, const __half* __restrict__ B,
    float* __restrict__ Cf, __half* __restrict__ Ch,
    const float* __restrict__ addend,
    int M, int N, int K, int mode)
{
    extern __shared__ char smem[];
    __half* sA = (__half*)smem;               // [128][40]
    __half* sB = sA + 128*FB_LD;              // [256][40]
    int tid = threadIdx.x, lane = tid & 31, wid = tid >> 5;
    int bn = blockIdx.x * 256;
    int wm = wid >> 2, wn = wid & 3;
    int g = lane >> 2, tig = lane & 3;

    for (int half = 0; half < 2; half++) {
        int bm = blockIdx.y * 256 + half * 128;
        float acc[4][8][4];
        #pragma unroll
        for (int mt = 0; mt < 4; mt++)
            #pragma unroll
            for (int nt = 0; nt < 8; nt++)
                #pragma unroll
                for (int q = 0; q < 4; q++) acc[mt][nt][q] = 0.f;

        for (int k0 = 0; k0 < K; k0 += 32) {
            __syncthreads();
            for (int v = tid; v < 512; v += 256) {
                int r = v >> 2, q = v & 3;
                *(uint4*)&sA[r*FB_LD + q*8] = *(const uint4*)(A + (size_t)(bm+r)*K + k0 + q*8);
            }
            for (int v = tid; v < 1024; v += 256) {
                int r = v >> 2, q = v & 3;
                *(uint4*)&sB[r*FB_LD + q*8] = *(const uint4*)(B + (size_t)(bn+r)*K + k0 + q*8);
            }
            __syncthreads();
            #pragma unroll
            for (int ks = 0; ks < 2; ks++) {
                int kk = ks * 16 + tig * 2;
                uint32_t a[4][4], b[8][2];
                #pragma unroll
                for (int mt = 0; mt < 4; mt++) {
                    int mr = (wm*64 + mt*16 + g)*FB_LD + kk;
                    a[mt][0] = *(const uint32_t*)&sA[mr];
                    a[mt][1] = *(const uint32_t*)&sA[mr + 8*FB_LD];
                    a[mt][2] = *(const uint32_t*)&sA[mr + 8];
                    a[mt][3] = *(const uint32_t*)&sA[mr + 8*FB_LD + 8];
                }
                #pragma unroll
                for (int nt = 0; nt < 8; nt++) {
                    int nr = (wn*64 + nt*8 + g)*FB_LD + kk;
                    b[nt][0] = *(const uint32_t*)&sB[nr];
                    b[nt][1] = *(const uint32_t*)&sB[nr + 8];
                }
                #pragma unroll
                for (int mt = 0; mt < 4; mt++)
                    #pragma unroll
                    for (int nt = 0; nt < 8; nt++)
                        mma16816(acc[mt][nt], a[mt], b[nt]);
            }
        }
        #pragma unroll
        for (int mt = 0; mt < 4; mt++) {
            #pragma unroll
            for (int nt = 0; nt < 8; nt++) {
                size_t r0 = (size_t)(bm + wm*64 + mt*16 + g);
                int col = bn + wn*64 + nt*8 + tig*2;
                if (mode == 2) {
                    float v0 = siluf(acc[mt][nt][0]) * acc[mt][nt][1];
                    float v1 = siluf(acc[mt][nt][2]) * acc[mt][nt][3];
                    Ch[r0*FF + (col>>1)]     = __float2half_rn(v0);
                    Ch[(r0+8)*FF + (col>>1)] = __float2half_rn(v1);
                } else if (mode == 1) {
                    *(__half2*)(Ch + r0*N + col)     = __floats2half2_rn(acc[mt][nt][0], acc[mt][nt][1]);
                    *(__half2*)(Ch + (r0+8)*N + col) = __floats2half2_rn(acc[mt][nt][2], acc[mt][nt][3]);
                } else {
                    float2 v0 = make_float2(acc[mt][nt][0], acc[mt][nt][1]);
                    float2 v1 = make_float2(acc[mt][nt][2], acc[mt][nt][3]);
                    if (addend) {
                        float2 a0 = *(const float2*)(addend + r0*N + col);
                        float2 a1 = *(const float2*)(addend + (r0+8)*N + col);
                        v0.x += a0.x; v0.y += a0.y; v1.x += a1.x; v1.y += a1.y;
                    }
                    *(float2*)(Cf + r0*N + col)     = v0;
                    *(float2*)(Cf + (r0+8)*N + col) = v1;
                }
            }
        }
        __syncthreads();
    }
}
#endif  // USE_TCGEN05

// ---------------- RMSNorm -> fp16 --------------------------------------------
__global__ __launch_bounds__(256) void rmsnorm_h_kernel(
    const float* __restrict__ x, const float* __restrict__ w,
    __half* __restrict__ out)
{
    __shared__ float red[8];
    int row = blockIdx.x;
    int tid = threadIdx.x;
    const float4* xr = (const float4*)(x + (size_t)row * EMBED);
    const float4* w4 = (const float4*)w;
    float4 v0 = xr[tid];
    float4 v1 = xr[tid + 256];
    float ss = v0.x*v0.x + v0.y*v0.y + v0.z*v0.z + v0.w*v0.w
             + v1.x*v1.x + v1.y*v1.y + v1.z*v1.z + v1.w*v1.w;
    #pragma unroll
    for (int o = 16; o > 0; o >>= 1) ss += __shfl_xor_sync(0xffffffffu, ss, o);
    if ((tid & 31) == 0) red[tid >> 5] = ss;
    __syncthreads();
    float tot = red[0] + red[1] + red[2] + red[3] + red[4] + red[5] + red[6] + red[7];
    float inv = rsqrtf(tot * (1.0f / EMBED) + 1e-5f);
    float4 wa = w4[tid], wb = w4[tid + 256];
    __half2* O = (__half2*)(out + (size_t)row * EMBED);
    O[2*tid]         = __floats2half2_rn(v0.x*inv*wa.x, v0.y*inv*wa.y);
    O[2*tid+1]       = __floats2half2_rn(v0.z*inv*wa.z, v0.w*inv*wa.w);
    O[2*(tid+256)]   = __floats2half2_rn(v1.x*inv*wb.x, v1.y*inv*wb.y);
    O[2*(tid+256)+1] = __floats2half2_rn(v1.z*inv*wb.z, v1.w*inv*wb.w);
}

// ---------------- RoPE (q,k only; fp16 in -> fp16 out) -----------------------
__global__ __launch_bounds__(256) void rope_kernel(
    const __half* __restrict__ qkv, const float* __restrict__ freqs,
    __half* __restrict__ qh, __half* __restrict__ kh)
{
    int s = blockIdx.x, b = blockIdx.y, tid = threadIdx.x;
    const __half* row = qkv + ((size_t)b * SS + s) * QKV_N;
    const float* f = freqs + (size_t)s * HD;
    // 1/sqrt(EMBED) * log2(e): softmax done in exp2 domain
    const float scale = 0.02209708691207961f * 1.4426950408889634f;

    for (int p = tid; p < NH * 64; p += 256) {
        int h = p >> 6, i = p & 63;
        __half2 xv = *(const __half2*)(row + h*HD + 2*i);
        float x0 = __half2float(__low2half(xv)), x1 = __half2float(__high2half(xv));
        float c = f[2*i], sn = f[2*i+1];
        __half2* dst = (__half2*)(qh + ((size_t)(b*NH + h) * SS + s) * HD + 2*i);
        *dst = __floats2half2_rn((x0*c - x1*sn) * scale, (x1*c + x0*sn) * scale);
    }
    for (int p = tid; p < NKV * 64; p += 256) {
        int h = p >> 6, i = p & 63;
        __half2 xv = *(const __half2*)(row + NH*HD + h*HD + 2*i);
        float x0 = __half2float(__low2half(xv)), x1 = __half2float(__high2half(xv));
        float c = f[2*i], sn = f[2*i+1];
        __half2* dst = (__half2*)(kh + ((size_t)(b*NKV + h) * SS + s) * HD + 2*i);
        *dst = __floats2half2_rn(x0*c - x1*sn, x1*c + x0*sn);
    }
}

// ---------------- Coalesced V transpose: [b,s,(kvh,d)] -> [b,kvh,d,s] --------
__global__ __launch_bounds__(256) void vtrans_kernel(
    const __half* __restrict__ qkv, __half* __restrict__ vh)
{
    __shared__ __half t[64*136];   // [64 s][128 d] padded
    int s0 = blockIdx.x * 64, h = blockIdx.y, b = blockIdx.z;
    int tid = threadIdx.x;
    const __half* src = qkv + ((size_t)b * SS + s0) * QKV_N + (size_t)(NH + NKV)*HD + h*HD;
    for (int i = tid; i < 64*16; i += 256) {
        int r = i >> 4, c = i & 15;
        *(uint4*)&t[r*136 + c*8] = *(const uint4*)(src + (size_t)r * QKV_N + c*8);
    }
    __syncthreads();
    __half* dst = vh + ((size_t)(b*NKV + h) * HD) * SS + s0;
    for (int i = tid; i < 128*8; i += 256) {
        int d = i >> 3, c = i & 7;
        __half v[8];
        #pragma unroll
        for (int j = 0; j < 8; j++) v[j] = t[(c*8 + j)*136 + d];
        *(uint4*)(dst + (size_t)d * SS + c*8) = *(uint4*)v;
    }
}

// ---------------- Tensor-core flash attention (fp16 mma, f16x2 exp2) ---------
#define FLH_SMEM_BYTES ((128*136 + 2*64*136 + 2*128*72) * 2)
__global__ __launch_bounds__(256) void flash_tc_kernel(
    const __half* __restrict__ qh, const __half* __restrict__ kh,
    const __half* __restrict__ vh, __half* __restrict__ oh)
{
    extern __shared__ __half smh[];
    __half* Qs  = smh;                      // [128][136]
    __half* Ks0 = Qs + 128*136;             // [64][136] x2
    __half* Ks1 = Ks0 + 64*136;
    __half* Vs0 = Ks1 + 64*136;             // [128][72] x2 (Vt: [d][kc])
    __half* Vs1 = Vs0 + 128*72;
    int tid = threadIdx.x, lane = tid & 31, wid = tid >> 5;
    int g = lane >> 2, tig = lane & 3;
    int qb = gridDim.x - 1 - blockIdx.x;    // biggest workload first
    int hb = blockIdx.y, bb = blockIdx.z;
    uint32_t ksb[2] = {smem_u32(Ks0), smem_u32(Ks1)};
    uint32_t vsb[2] = {smem_u32(Vs0), smem_u32(Vs1)};
    uint32_t qsb = smem_u32(Qs);

    const __half* Qg = qh + ((size_t)(bb*NH + hb) * SS + (size_t)qb*128) * HD;
    const __half* Kg = kh + (size_t)(bb*NKV + (hb >> 2)) * SS * HD;
    const __half* Vg = vh + (size_t)(bb*NKV + (hb >> 2)) * HD * SS;

    for (int i = tid; i < 128*16; i += 256) {
        int r = i >> 4, c = i & 15;
        cpa16(qsb + (uint32_t)(r*136 + c*8)*2, Qg + r*HD + c*8);
    }
    {   // stage 0
        for (int i = tid; i < 64*16; i += 256) {
            int r = i >> 4, c = i & 15;
            cpa16(ksb[0] + (uint32_t)(r*136 + c*8)*2, Kg + (size_t)r*HD + c*8);
        }
        for (int i = tid; i < 128*8; i += 256) {
            int r = i >> 3, c = i & 7;
            cpa16(vsb[0] + (uint32_t)(r*72 + c*8)*2, Vg + (size_t)r*SS + c*8);
        }
        CP_COMMIT();
    }

    float accO[16][4];
    #pragma unroll
    for (int nd = 0; nd < 16; nd++)
        #pragma unroll
        for (int q = 0; q < 4; q++) accO[nd][q] = 0.f;
    float accL[4] = {0.f, 0.f, 0.f, 0.f};   // row sums via ones-MMA
    const uint32_t ONES2 = 0x3C003C00u;     // half2(1,1)
    uint32_t b_ones[2] = {ONES2, ONES2};
    int r0 = qb*128 + wid*16 + g;
    int r1 = r0 + 8;

    int nkb = 2*(qb + 1);
    for (int kb = 0; kb < nkb; kb++) {
        int st = kb & 1;
        if (kb + 1 < nkb) {
            int st2 = st ^ 1;
            for (int i = tid; i < 64*16; i += 256) {
                int r = i >> 4, c = i & 15;
                cpa16(ksb[st2] + (uint32_t)(r*136 + c*8)*2,
                      Kg + (size_t)((kb+1)*64 + r)*HD + c*8);
            }
            for (int i = tid; i < 128*8; i += 256) {
                int r = i >> 3, c = i & 7;
                cpa16(vsb[st2] + (uint32_t)(r*72 + c*8)*2,
                      Vg + (size_t)r*SS + (kb+1)*64 + c*8);
            }
            CP_COMMIT(); CP_WAIT1();
        } else {
            CP_WAIT0();
        }
        __syncthreads();
        const __half* Ks = (st == 0) ? Ks0 : Ks1;
        const __half* Vs = (st == 0) ? Vs0 : Vs1;

        float sacc[8][4];
        #pragma unroll
        for (int nt = 0; nt < 8; nt++)
            #pragma unroll
            for (int q = 0; q < 4; q++) sacc[nt][q] = 0.f;
        #pragma unroll
        for (int ks = 0; ks < 8; ks++) {
            uint32_t a[4];
            const __half* qr = &Qs[(wid*16 + g)*136 + ks*16 + 2*tig];
            a[0] = *(const uint32_t*)qr;
            a[1] = *(const uint32_t*)(qr + 8*136);
            a[2] = *(const uint32_t*)(qr + 8);
            a[3] = *(const uint32_t*)(qr + 8*136 + 8);
            #pragma unroll
            for (int nt = 0; nt < 8; nt++) {
                uint32_t b[2];
                const __half* kr = &Ks[(nt*8 + g)*136 + ks*16 + 2*tig];
                b[0] = *(const uint32_t*)kr;
                b[1] = *(const uint32_t*)(kr + 8);
                mma16816(sacc[nt], a, b);
            }
        }
        if (kb >= 2*qb) {
            #pragma unroll
            for (int nt = 0; nt < 8; nt++) {
                int col = kb*64 + nt*8 + 2*tig;
                if (col     > r0) sacc[nt][0] = -10000.f;
                if (col + 1 > r0) sacc[nt][1] = -10000.f;
                if (col     > r1) sacc[nt][2] = -10000.f;
                if (col + 1 > r1) sacc[nt][3] = -10000.f;
            }
        }
        #pragma unroll
        for (int j = 0; j < 4; j++) {
            uint32_t a[4];
            __half2 t;
            t = __floats2half2_rn(sacc[2*j][0],   sacc[2*j][1]);   a[0] = ex2h2(*(uint32_t*)&t);
            t = __floats2half2_rn(sacc[2*j][2],   sacc[2*j][3]);   a[1] = ex2h2(*(uint32_t*)&t);
            t = __floats2half2_rn(sacc[2*j+1][0], sacc[2*j+1][1]); a[2] = ex2h2(*(uint32_t*)&t);
            t = __floats2half2_rn(sacc[2*j+1][2], sacc[2*j+1][3]); a[3] = ex2h2(*(uint32_t*)&t);
            mma16816(accL, a, b_ones);
            #pragma unroll
            for (int nd = 0; nd < 16; nd++) {
                uint32_t b[2];
                const __half* vr = &Vs[(nd*8 + g)*72 + j*16 + 2*tig];
                b[0] = *(const uint32_t*)vr;
                b[1] = *(const uint32_t*)(vr + 8);
                mma16816(accO[nd], a, b);
            }
        }
        __syncthreads();
    }
    float inv0 = 1.f / accL[0], inv1 = 1.f / accL[2];
    __half* stg = smh;
    int lr = wid*16 + g;
    size_t obase = ((size_t)bb*SS + (size_t)qb*128) * EMBED + hb*HD;
    #pragma unroll
    for (int nd = 0; nd < 16; nd++) {
        int col = nd*8 + 2*tig;
        *(__half2*)&stg[lr*136 + col] =
            __floats2half2_rn(accO[nd][0]*inv0, accO[nd][1]*inv0);
        *(__half2*)&stg[(lr+8)*136 + col] =
            __floats2half2_rn(accO[nd][2]*inv1, accO[nd][3]*inv1);
    }
    __syncthreads();
    for (int i = tid; i < 128*16; i += 256) {
        int r = i >> 4, c = i & 15;
        *(uint4*)(oh + obase + (size_t)r*EMBED + c*8) = *(uint4*)&stg[r*136 + c*8];
    }
}

// ---------------- driver ------------------------------------------------------
static inline void conv_launch(const float* src, __half* dst, size_t n)
{
    int n4 = (int)(n / 4);
    conv_kernel<<<(n4 + 255)/256, 256>>>(src, dst, n4);
}

extern "C" void kernel_launch(void* const* d_in, const int* in_sizes, int n_in,
                              void* d_out, int out_size)
{
    const float* x       = (const float*)d_in[0];
    const float* freqs   = (const float*)d_in[2];
    const float* w_qkv   = (const float*)d_in[4];
    const float* w_fc    = (const float*)d_in[5];
    const float* w1      = (const float*)d_in[6];
    const float* w2      = (const float*)d_in[7];
    const float* w3      = (const float*)d_in[8];
    const float* attn_nw = (const float*)d_in[9];
    const float* ff_nw   = (const float*)d_in[10];
    float* out = (float*)d_out;

    float *h1;
    __half *qkvh, *qh, *kh, *vh, *ah, *sw, *wh;
    cudaGetSymbolAddress((void**)&qkvh, g_qkvh);
    cudaGetSymbolAddress((void**)&qh,  g_qh2);
    cudaGetSymbolAddress((void**)&kh,  g_kh2);
    cudaGetSymbolAddress((void**)&vh,  g_vh2);
    cudaGetSymbolAddress((void**)&h1,  g_h1);
    cudaGetSymbolAddress((void**)&ah,  g_ah);
    cudaGetSymbolAddress((void**)&sw,  g_sw);
    cudaGetSymbolAddress((void**)&wh,  g_wh);

    cudaFuncSetAttribute(tc_gemm, cudaFuncAttributeMaxDynamicSharedMemorySize, GM_SMEM_BYTES);
    cudaFuncSetAttribute(flash_tc_kernel, cudaFuncAttributeMaxDynamicSharedMemorySize, FLH_SMEM_BYTES);

    // 1. attn rmsnorm -> fp16
    rmsnorm_h_kernel<<<ROWS, 256>>>(x, attn_nw, ah);
    // 2. qkv projection -> fp16 qkvh
    conv_launch(w_qkv, wh, (size_t)QKV_N*EMBED);
    tc_gemm<<<dim3(QKV_N/256, ROWS/256), 256, GM_SMEM_BYTES>>>(
        ah, wh, nullptr, qkvh, nullptr, ROWS, QKV_N, EMBED, 1);
    // 3. rope (q,k) + coalesced V transpose
    rope_kernel<<<dim3(SS, BB), 256>>>(qkvh, freqs, qh, kh);
    vtrans_kernel<<<dim3(SS/64, NKV, BB), 256>>>(qkvh, vh);
    // 4. tensor-core flash attention -> fp16 attn into g_ah
    flash_tc_kernel<<<dim3(SS/128, NH, BB), 256, FLH_SMEM_BYTES>>>(qh, kh, vh, ah);
    // 5. output projection + residual -> fp32 h1
    conv_launch(w_fc, wh, (size_t)EMBED*EMBED);
    tc_gemm<<<dim3(EMBED/256, ROWS/256), 256, GM_SMEM_BYTES>>>(
        ah, wh, h1, nullptr, x, ROWS, EMBED, EMBED, 0);
    // 6. ffn rmsnorm -> fp16
    rmsnorm_h_kernel<<<ROWS, 256>>>(h1, ff_nw, ah);
    // 7. interleaved gate|up projection with FUSED swiglu -> g_sw (distinct buffer!)
    {
        int n4 = FF*EMBED/4;
        conv_inter_kernel<<<(n4 + 255)/256, 256>>>(w1, w2, wh, n4);
    }
    tc_gemm<<<dim3(2*FF/256, ROWS/256), 256, GM_SMEM_BYTES>>>(
        ah, wh, nullptr, sw, nullptr, ROWS, 2*FF, EMBED, 2);
    // 8. down projection + residual -> out
    conv_launch(w3, wh, (size_t)EMBED*FF);
    tc_gemm<<<dim3(EMBED/256, ROWS/256), 256, GM_SMEM_BYTES>>>(
        sw, wh, out, nullptr, h1, ROWS, EMBED, FF, 0);
}

// round 14
// speedup vs baseline: 28.2710x; 1.0022x over previous
#include <cuda_runtime.h>
#include <cuda_bf16.h>
#include <cuda_fp16.h>
#include <math.h>
#include <stdint.h>

#define EMBED 2048
#define NH 16
#define NKV 4
#define HD 128
#define FF 5632
#define BB 2
#define SS 2048
#define ROWS (BB*SS)                 // 4096 tokens
#define QKV_N ((NH + 2*NKV)*HD)      // 3072

#if defined(__CUDA_ARCH_FEAT_SM103_ALL) || defined(__CUDA_ARCH_FEAT_SM100_ALL)
#define USE_TCGEN05 1
#else
#define USE_TCGEN05 0
#endif

// ---------------- scratch (device globals; no allocations allowed) ----------
__device__ __half g_qkvh[ROWS*QKV_N];     // fp16 qkv gemm output
__device__ __half g_qh2[BB*NH *SS*HD];    // fp16 Q (scaled by 1/sqrt(E)*log2e), [b,h,s,d]
__device__ __half g_kh2[BB*NKV*SS*HD];    // fp16 K, [b,kvh,s,d]
__device__ __half g_vh2[BB*NKV*HD*SS];    // fp16 V transposed, [b,kvh,d,s]
__device__ float  g_h1 [ROWS*EMBED];
__device__ __half g_ah [ROWS*FF];         // fp16 activations (gemm A operand)
__device__ __half g_sw [ROWS*FF];         // fp16 fused-swiglu output (down-proj A)
__device__ __half g_wh [2*FF*EMBED];      // fp16 weights     (gemm B operand)

#define GM_STAGE_BYTES 65536              // A0 16K + A1 16K + B 32K
#define GM_NSTAGE 3
#define GM_SMEM_BYTES (1024 + GM_NSTAGE*GM_STAGE_BYTES)

// ---------- common helpers (legal on plain sm_103 PTX) ----------------------
__device__ __forceinline__ uint32_t smem_u32(const void* p) {
    uint32_t a;
    asm("{ .reg .u64 t; cvta.to.shared.u64 t, %1; cvt.u32.u64 %0, t; }" : "=r"(a) : "l"(p));
    return a;
}
#define CP_COMMIT() asm volatile("cp.async.commit_group;" ::: "memory")
#define CP_WAIT0()  asm volatile("cp.async.wait_group 0;" ::: "memory")
#define CP_WAIT1()  asm volatile("cp.async.wait_group 1;" ::: "memory")
__device__ __forceinline__ void cpa16(uint32_t saddr, const void* g) {
    asm volatile("cp.async.cg.shared.global [%0], [%1], 16;" :: "r"(saddr), "l"(g) : "memory");
}
__device__ __forceinline__ void mma16816(float* c, const uint32_t* a, const uint32_t* b) {
    asm volatile("mma.sync.aligned.m16n8k16.row.col.f32.f16.f16.f32 "
        "{%0,%1,%2,%3}, {%4,%5,%6,%7}, {%8,%9}, {%0,%1,%2,%3};"
        : "+f"(c[0]), "+f"(c[1]), "+f"(c[2]), "+f"(c[3])
        : "r"(a[0]), "r"(a[1]), "r"(a[2]), "r"(a[3]), "r"(b[0]), "r"(b[1]));
}
__device__ __forceinline__ uint32_t ex2h2(uint32_t x) {
    uint32_t y; asm("ex2.approx.f16x2 %0, %1;" : "=r"(y) : "r"(x)); return y;
}
__device__ __forceinline__ float siluf(float a) {
    return a / (1.f + __expf(-a));
}

// ======================= fp32 -> fp16 convert (weights) ======================
__global__ __launch_bounds__(256) void conv_kernel(
    const float* __restrict__ x, __half* __restrict__ y, int n4)
{
    int i = blockIdx.x * 256 + threadIdx.x;
    if (i >= n4) return;
    float4 v = ((const float4*)x)[i];
    __half2* Y = (__half2*)y;
    Y[2*i]   = __floats2half2_rn(v.x, v.y);
    Y[2*i+1] = __floats2half2_rn(v.z, v.w);
}

// interleave rows: w1 row j -> dst row 2j, w2 row j -> dst row 2j+1
__global__ __launch_bounds__(256) void conv_inter_kernel(
    const float* __restrict__ w1, const float* __restrict__ w2,
    __half* __restrict__ y, int n4)   // n4 = FF*EMBED/4
{
    int i = blockIdx.x * 256 + threadIdx.x;
    if (i >= n4) return;
    const int RQ = EMBED / 4;
    int row = i / RQ, q = i % RQ;
    float4 a = ((const float4*)w1)[i];
    float4 b = ((const float4*)w2)[i];
    __half2* Y1 = (__half2*)(y + ((size_t)(2*row)   * EMBED) + q*4);
    __half2* Y2 = (__half2*)(y + ((size_t)(2*row+1) * EMBED) + q*4);
    Y1[0] = __floats2half2_rn(a.x, a.y);
    Y1[1] = __floats2half2_rn(a.z, a.w);
    Y2[0] = __floats2half2_rn(b.x, b.y);
    Y2[1] = __floats2half2_rn(b.z, b.w);
}

// supertile rasterization: chunks of NW N-tiles, M varies fastest inside
__device__ __forceinline__ void raster_map(int& bm, int& bn) {
    const int NW = 4;
    int num_n = gridDim.x, num_m = gridDim.y;
    int bid = blockIdx.y * num_n + blockIdx.x;
    int chunk = bid / (num_m * NW);
    int local = bid - chunk * num_m * NW;
    bm = (local / NW) * 256;
    bn = (chunk * NW + (local % NW)) * 256;
}

#if USE_TCGEN05
// ======================= tcgen05 GEMM (sm_103a pass) =========================
__device__ __forceinline__ uint32_t elect_one_pred() {
    uint32_t pred;
    asm volatile(
        "{\n\t.reg .pred p;\n\telect.sync _|p, 0xFFFFFFFF;\n\tselp.b32 %0, 1, 0, p;\n\t}"
        : "=r"(pred));
    return pred;
}
#define MBAR_INIT(addr, cnt) \
    asm volatile("mbarrier.init.shared.b64 [%0], %1;" :: "r"(addr), "r"((uint32_t)(cnt)) : "memory")
#define MBAR_INVAL(addr) \
    asm volatile("mbarrier.inval.shared.b64 [%0];" :: "r"(addr) : "memory")
#define MBAR_WAIT(addr, parity) do { \
    uint32_t _m = (addr); uint32_t _p = (parity); uint32_t _d; \
    asm volatile("{\n\t.reg .pred p;\n\tmbarrier.try_wait.parity.acquire.cta.shared::cta.b64 p, [%1], %2;\n\tselp.b32 %0, 1, 0, p;\n\t}" \
        : "=r"(_d) : "r"(_m), "r"(_p) : "memory"); \
    if (!_d) { \
        asm volatile("{\n\t.reg .pred P1;\n\tWL_%=:\n\tmbarrier.try_wait.parity.acquire.cta.shared::cta.b64 P1, [%0], %1, 0x989680;\n\t@P1 bra.uni WD_%=;\n\tbra.uni WL_%=;\n\tWD_%=:\n\t}" \
            :: "r"(_m), "r"(_p) : "memory"); \
    } } while(0)
#define TC_ALLOC(smem_addr, n) \
    asm volatile("tcgen05.alloc.cta_group::1.sync.aligned.shared::cta.b32 [%0], %1;" \
        :: "r"((uint32_t)(smem_addr)), "r"((uint32_t)(n)) : "memory")
#define TC_DEALLOC(tmem_addr, n) \
    asm volatile("tcgen05.dealloc.cta_group::1.sync.aligned.b32 %0, %1;" :: "r"(tmem_addr), "r"((uint32_t)(n)))
#define TC_RELINQ() \
    asm volatile("tcgen05.relinquish_alloc_permit.cta_group::1.sync.aligned;")
#define TC_COMMIT(mbar) \
    asm volatile("tcgen05.commit.cta_group::1.mbarrier::arrive::one.shared::cluster.b64 [%0];" \
        :: "r"((uint32_t)(mbar)) : "memory")
#define TC_FENCE_AFTER() asm volatile("tcgen05.fence::after_thread_sync;" ::: "memory")
#define TC_FENCE_BEFORE() asm volatile("tcgen05.fence::before_thread_sync;" ::: "memory")
#define TC_WAIT_LD() asm volatile("tcgen05.wait::ld.sync.aligned;" ::: "memory")
#define FENCE_ASYNC_SHARED() asm volatile("fence.proxy.async.shared::cta;" ::: "memory")
#define TC_LD_X32(r, tmem_addr) \
    asm volatile("tcgen05.ld.sync.aligned.32x32b.x32.b32 " \
        "{%0, %1, %2, %3, %4, %5, %6, %7, %8, %9, %10, %11, %12, %13, %14, %15, " \
        " %16, %17, %18, %19, %20, %21, %22, %23, %24, %25, %26, %27, %28, %29, %30, %31}, [%32];" \
        : "=r"((r)[0]),  "=r"((r)[1]),  "=r"((r)[2]),  "=r"((r)[3]), \
          "=r"((r)[4]),  "=r"((r)[5]),  "=r"((r)[6]),  "=r"((r)[7]), \
          "=r"((r)[8]),  "=r"((r)[9]),  "=r"((r)[10]), "=r"((r)[11]), \
          "=r"((r)[12]), "=r"((r)[13]), "=r"((r)[14]), "=r"((r)[15]), \
          "=r"((r)[16]), "=r"((r)[17]), "=r"((r)[18]), "=r"((r)[19]), \
          "=r"((r)[20]), "=r"((r)[21]), "=r"((r)[22]), "=r"((r)[23]), \
          "=r"((r)[24]), "=r"((r)[25]), "=r"((r)[26]), "=r"((r)[27]), \
          "=r"((r)[28]), "=r"((r)[29]), "=r"((r)[30]), "=r"((r)[31]) \
        : "r"(tmem_addr))

__device__ __forceinline__ uint64_t mk_desc(uint32_t addr) {
    const uint64_t base = (2ull << 61) | (1ull << 46) | (64ull << 32) | (1ull << 16);
    return base | ((uint64_t)(addr >> 4) & 0x3FFF);
}
__device__ __forceinline__ void mma_f16_ss(uint32_t d, uint64_t da, uint64_t db,
                                           uint32_t idesc, uint32_t en) {
    asm volatile(
        "{\n\t.reg .pred p;\n\tsetp.ne.u32 p, %5, 0;\n\t"
        "tcgen05.mma.cta_group::1.kind::f16 [%0], %1, %2, %3, {%4,%4,%4,%4}, p;\n\t}"
        :: "r"(d), "l"(da), "l"(db), "r"(idesc), "r"(0u), "r"(en) : "memory");
}

#define GM_IDESC 0x8400010u              // F32 acc, fp16 a/b, M=128, N=256

__device__ __forceinline__ void gm_load_stage(
    uint32_t stb,
    const __half* __restrict__ A, const __half* __restrict__ B,
    int bm, int bn, int K, int kc, int tid)
{
    #pragma unroll
    for (int it = 0; it < 8; it++) {                 // A: 256 rows x 8 vec8
        int v = tid + it * 256;
        int r = v >> 3, cv = v & 7;
        uint32_t off = (uint32_t)((r & 127)*128 + cv*16);
        uint32_t sw = off ^ ((off >> 3) & 0x70);
        cpa16(stb + (uint32_t)(r >> 7)*16384 + sw,
              A + (size_t)(bm + r) * K + kc + cv*8);
    }
    #pragma unroll
    for (int it = 0; it < 8; it++) {                 // B: 256 rows x 8 vec8
        int v = tid + it * 256;
        int r = v >> 3, cv = v & 7;
        uint32_t off = (uint32_t)(r*128 + cv*16);
        uint32_t sw = off ^ ((off >> 3) & 0x70);
        cpa16(stb + 32768 + sw, B + (size_t)(bn + r) * K + kc + cv*8);
    }
    CP_COMMIT();
}

// mode: 0 = fp32 out (+optional addend), 1 = fp16 out, 2 = fused silu (pairs)
__global__ __launch_bounds__(256, 1) void tc_gemm(
    const __half* __restrict__ A, const __half* __restrict__ B,
    float* __restrict__ Cf, __half* __restrict__ Ch,
    const float* __restrict__ addend,
    int M, int N, int K, int mode)
{
    extern __shared__ char smem[];
    uint32_t sb = smem_u32(smem);
    int tid = threadIdx.x;
    int wid = tid >> 5, lane = tid & 31;
    int bm, bn;
    raster_map(bm, bn);

    if (wid == 0) { TC_ALLOC(sb, 512); TC_RELINQ(); }
    if (tid == 0) { MBAR_INIT(sb + 8, 1); MBAR_INIT(sb + 16, 1); MBAR_INIT(sb + 24, 1); }
    __syncthreads();
    uint32_t tmem;
    asm volatile("ld.shared.b32 %0, [%1];" : "=r"(tmem) : "r"(sb));

    const int NC = K / 64;
    int ph0 = 0, ph1 = 0;

    gm_load_stage(sb + 1024, A, B, bm, bn, K, 0, tid);
    gm_load_stage(sb + 1024 + GM_STAGE_BYTES, A, B, bm, bn, K, 64, tid);

    for (int c = 0; c < NC; c++) {
        int s = c % GM_NSTAGE;
        if (c + 1 < NC) { CP_WAIT1(); } else { CP_WAIT0(); }
        __syncthreads();
        uint32_t stb = sb + 1024 + (uint32_t)s * GM_STAGE_BYTES;
        if (wid == 0 && elect_one_pred()) {
            FENCE_ASYNC_SHARED();
            uint64_t dA0 = mk_desc(stb);
            uint64_t dA1 = mk_desc(stb + 16384);
            uint64_t dB  = mk_desc(stb + 32768);
            #pragma unroll
            for (int k = 0; k < 4; k++) {
                uint32_t en = (c > 0) || (k > 0);
                mma_f16_ss(tmem,       dA0 + k*2, dB + k*2, GM_IDESC, en);
                mma_f16_ss(tmem + 256, dA1 + k*2, dB + k*2, GM_IDESC, en);
            }
            TC_COMMIT(sb + 8 + (uint32_t)(c & 1) * 8);
            if (c == NC - 1) TC_COMMIT(sb + 24);   // dedicated final-completion mbar
        }
        if (c + 2 < NC) {
            if (c >= 1) {
                int m = (c - 1) & 1;
                if (m == 0) { MBAR_WAIT(sb + 8, ph0);  ph0 ^= 1; }
                else        { MBAR_WAIT(sb + 16, ph1); ph1 ^= 1; }
            }
            gm_load_stage(sb + 1024 + (uint32_t)((c + 2) % GM_NSTAGE) * GM_STAGE_BYTES,
                          A, B, bm, bn, K, (c + 2) * 64, tid);
        }
    }
    MBAR_WAIT(sb + 24, 0);
    TC_FENCE_AFTER();

    int wg = wid >> 2, ws = wid & 3;
    #pragma unroll
    for (int h = 0; h < 2; h++) {
        size_t row = (size_t)(bm + h*128 + ws * 32 + lane);
        #pragma unroll
        for (int cb = 0; cb < 4; cb++) {
            uint32_t regs[32];
            TC_LD_X32(regs, tmem + (uint32_t)(h*256 + wg * 128 + cb * 32));
            TC_WAIT_LD();
            int col = bn + wg * 128 + cb * 32;
            if (mode == 2) {
                // fused swiglu: cols are (gate,up) pairs; out feature = col/2
                __half2 o[8];
                #pragma unroll
                for (int t = 0; t < 16; t += 2) {
                    float r0 = siluf(__uint_as_float(regs[2*t]))   * __uint_as_float(regs[2*t+1]);
                    float r1 = siluf(__uint_as_float(regs[2*t+2])) * __uint_as_float(regs[2*t+3]);
                    o[t >> 1] = __floats2half2_rn(r0, r1);
                }
                __half* Cp = Ch + row * (size_t)FF + (col >> 1);
                *(uint4*)(Cp)     = *(uint4*)&o[0];
                *(uint4*)(Cp + 8) = *(uint4*)&o[4];
            } else if (mode == 1) {
                __half* Cp = Ch + row * (size_t)N + col;
                #pragma unroll
                for (int j = 0; j < 32; j += 8) {
                    __half2 o[4];
                    o[0] = __floats2half2_rn(__uint_as_float(regs[j]),   __uint_as_float(regs[j+1]));
                    o[1] = __floats2half2_rn(__uint_as_float(regs[j+2]), __uint_as_float(regs[j+3]));
                    o[2] = __floats2half2_rn(__uint_as_float(regs[j+4]), __uint_as_float(regs[j+5]));
                    o[3] = __floats2half2_rn(__uint_as_float(regs[j+6]), __uint_as_float(regs[j+7]));
                    *(uint4*)(Cp + j) = *(uint4*)o;
                }
            } else {
                float* Cp = Cf + row * (size_t)N + col;
                if (addend) {
                    const float* Ap = addend + row * (size_t)N + col;
                    #pragma unroll
                    for (int j = 0; j < 32; j += 4) {
                        float4 a = *(const float4*)(Ap + j);
                        float4 o = make_float4(__uint_as_float(regs[j])   + a.x,
                                               __uint_as_float(regs[j+1]) + a.y,
                                               __uint_as_float(regs[j+2]) + a.z,
                                               __uint_as_float(regs[j+3]) + a.w);
                        *(float4*)(Cp + j) = o;
                    }
                } else {
                    #pragma unroll
                    for (int j = 0; j < 32; j += 4) {
                        float4 o = make_float4(__uint_as_float(regs[j]),
                                               __uint_as_float(regs[j+1]),
                                               __uint_as_float(regs[j+2]),
                                               __uint_as_float(regs[j+3]));
                        *(float4*)(Cp + j) = o;
                    }
                }
            }
        }
    }
    TC_FENCE_BEFORE();
    __syncthreads();
    if (tid == 0) { MBAR_INVAL(sb + 8); MBAR_INVAL(sb + 16); MBAR_INVAL(sb + 24); }
    if (wid == 0) { TC_DEALLOC(tmem, 512); }
}

#else
// ======================= mma.sync GEMM fallback ==============================
#define FB_LD 40

__global__ __launch_bounds__(256, 1) void tc_gemm(
    const __half* __restrict__ A, const __half* __restrict__ B,
    float* __restrict__ Cf, __half* __restrict__ Ch,
    const float* __restrict__ addend,
    int M, int N, int K, int mode)
{
    extern __shared__ char smem[];
    __half* sA = (__half*)smem;               // [128][40]
    __half* sB = sA + 128*FB_LD;              // [256][40]
    int tid = threadIdx.x, lane = tid & 31, wid = tid >> 5;
    int bm0, bn;
    raster_map(bm0, bn);
    int wm = wid >> 2, wn = wid & 3;
    int g = lane >> 2, tig = lane & 3;

    for (int half = 0; half < 2; half++) {
        int bm = bm0 + half * 128;
        float acc[4][8][4];
        #pragma unroll
        for (int mt = 0; mt < 4; mt++)
            #pragma unroll
            for (int nt = 0; nt < 8; nt++)
                #pragma unroll
                for (int q = 0; q < 4; q++) acc[mt][nt][q] = 0.f;

        for (int k0 = 0; k0 < K; k0 += 32) {
            __syncthreads();
            for (int v = tid; v < 512; v += 256) {
                int r = v >> 2, q = v & 3;
                *(uint4*)&sA[r*FB_LD + q*8] = *(const uint4*)(A + (size_t)(bm+r)*K + k0 + q*8);
            }
            for (int v = tid; v < 1024; v += 256) {
                int r = v >> 2, q = v & 3;
                *(uint4*)&sB[r*FB_LD + q*8] = *(const uint4*)(B + (size_t)(bn+r)*K + k0 + q*8);
            }
            __syncthreads();
            #pragma unroll
            for (int ks = 0; ks < 2; ks++) {
                int kk = ks * 16 + tig * 2;
                uint32_t a[4][4], b[8][2];
                #pragma unroll
                for (int mt = 0; mt < 4; mt++) {
                    int mr = (wm*64 + mt*16 + g)*FB_LD + kk;
                    a[mt][0] = *(const uint32_t*)&sA[mr];
                    a[mt][1] = *(const uint32_t*)&sA[mr + 8*FB_LD];
                    a[mt][2] = *(const uint32_t*)&sA[mr + 8];
                    a[mt][3] = *(const uint32_t*)&sA[mr + 8*FB_LD + 8];
                }
                #pragma unroll
                for (int nt = 0; nt < 8; nt++) {
                    int nr = (wn*64 + nt*8 + g)*FB_LD + kk;
                    b[nt][0] = *(const uint32_t*)&sB[nr];
                    b[nt][1] = *(const uint32_t*)&sB[nr + 8];
                }
                #pragma unroll
                for (int mt = 0; mt < 4; mt++)
                    #pragma unroll
                    for (int nt = 0; nt < 8; nt++)
                        mma16816(acc[mt][nt], a[mt], b[nt]);
            }
        }
        #pragma unroll
        for (int mt = 0; mt < 4; mt++) {
            #pragma unroll
            for (int nt = 0; nt < 8; nt++) {
                size_t r0 = (size_t)(bm + wm*64 + mt*16 + g);
                int col = bn + wn*64 + nt*8 + tig*2;
                if (mode == 2) {
                    float v0 = siluf(acc[mt][nt][0]) * acc[mt][nt][1];
                    float v1 = siluf(acc[mt][nt][2]) * acc[mt][nt][3];
                    Ch[r0*FF + (col>>1)]     = __float2half_rn(v0);
                    Ch[(r0+8)*FF + (col>>1)] = __float2half_rn(v1);
                } else if (mode == 1) {
                    *(__half2*)(Ch + r0*N + col)     = __floats2half2_rn(acc[mt][nt][0], acc[mt][nt][1]);
                    *(__half2*)(Ch + (r0+8)*N + col) = __floats2half2_rn(acc[mt][nt][2], acc[mt][nt][3]);
                } else {
                    float2 v0 = make_float2(acc[mt][nt][0], acc[mt][nt][1]);
                    float2 v1 = make_float2(acc[mt][nt][2], acc[mt][nt][3]);
                    if (addend) {
                        float2 a0 = *(const float2*)(addend + r0*N + col);
                        float2 a1 = *(const float2*)(addend + (r0+8)*N + col);
                        v0.x += a0.x; v0.y += a0.y; v1.x += a1.x; v1.y += a1.y;
                    }
                    *(float2*)(Cf + r0*N + col)     = v0;
                    *(float2*)(Cf + (r0+8)*N + col) = v1;
                }
            }
        }
        __syncthreads();
    }
}
#endif  // USE_TCGEN05

// ---------------- RMSNorm -> fp16 --------------------------------------------
__global__ __launch_bounds__(256) void rmsnorm_h_kernel(
    const float* __restrict__ x, const float* __restrict__ w,
    __half* __restrict__ out)
{
    __shared__ float red[8];
    int row = blockIdx.x;
    int tid = threadIdx.x;
    const float4* xr = (const float4*)(x + (size_t)row * EMBED);
    const float4* w4 = (const float4*)w;
    float4 v0 = xr[tid];
    float4 v1 = xr[tid + 256];
    float ss = v0.x*v0.x + v0.y*v0.y + v0.z*v0.z + v0.w*v0.w
             + v1.x*v1.x + v1.y*v1.y + v1.z*v1.z + v1.w*v1.w;
    #pragma unroll
    for (int o = 16; o > 0; o >>= 1) ss += __shfl_xor_sync(0xffffffffu, ss, o);
    if ((tid & 31) == 0) red[tid >> 5] = ss;
    __syncthreads();
    float tot = red[0] + red[1] + red[2] + red[3] + red[4] + red[5] + red[6] + red[7];
    float inv = rsqrtf(tot * (1.0f / EMBED) + 1e-5f);
    float4 wa = w4[tid], wb = w4[tid + 256];
    __half2* O = (__half2*)(out + (size_t)row * EMBED);
    O[2*tid]         = __floats2half2_rn(v0.x*inv*wa.x, v0.y*inv*wa.y);
    O[2*tid+1]       = __floats2half2_rn(v0.z*inv*wa.z, v0.w*inv*wa.w);
    O[2*(tid+256)]   = __floats2half2_rn(v1.x*inv*wb.x, v1.y*inv*wb.y);
    O[2*(tid+256)+1] = __floats2half2_rn(v1.z*inv*wb.z, v1.w*inv*wb.w);
}

// ---------------- RoPE (q,k only; fp16 in -> fp16 out) -----------------------
__global__ __launch_bounds__(256) void rope_kernel(
    const __half* __restrict__ qkv, const float* __restrict__ freqs,
    __half* __restrict__ qh, __half* __restrict__ kh)
{
    int s = blockIdx.x, b = blockIdx.y, tid = threadIdx.x;
    const __half* row = qkv + ((size_t)b * SS + s) * QKV_N;
    const float* f = freqs + (size_t)s * HD;
    // 1/sqrt(EMBED) * log2(e): softmax done in exp2 domain
    const float scale = 0.02209708691207961f * 1.4426950408889634f;

    for (int p = tid; p < NH * 64; p += 256) {
        int h = p >> 6, i = p & 63;
        __half2 xv = *(const __half2*)(row + h*HD + 2*i);
        float x0 = __half2float(__low2half(xv)), x1 = __half2float(__high2half(xv));
        float c = f[2*i], sn = f[2*i+1];
        __half2* dst = (__half2*)(qh + ((size_t)(b*NH + h) * SS + s) * HD + 2*i);
        *dst = __floats2half2_rn((x0*c - x1*sn) * scale, (x1*c + x0*sn) * scale);
    }
    for (int p = tid; p < NKV * 64; p += 256) {
        int h = p >> 6, i = p & 63;
        __half2 xv = *(const __half2*)(row + NH*HD + h*HD + 2*i);
        float x0 = __half2float(__low2half(xv)), x1 = __half2float(__high2half(xv));
        float c = f[2*i], sn = f[2*i+1];
        __half2* dst = (__half2*)(kh + ((size_t)(b*NKV + h) * SS + s) * HD + 2*i);
        *dst = __floats2half2_rn(x0*c - x1*sn, x1*c + x0*sn);
    }
}

// ---------------- Coalesced V transpose: [b,s,(kvh,d)] -> [b,kvh,d,s] --------
__global__ __launch_bounds__(256) void vtrans_kernel(
    const __half* __restrict__ qkv, __half* __restrict__ vh)
{
    __shared__ __half t[64*136];   // [64 s][128 d] padded
    int s0 = blockIdx.x * 64, h = blockIdx.y, b = blockIdx.z;
    int tid = threadIdx.x;
    const __half* src = qkv + ((size_t)b * SS + s0) * QKV_N + (size_t)(NH + NKV)*HD + h*HD;
    for (int i = tid; i < 64*16; i += 256) {
        int r = i >> 4, c = i & 15;
        *(uint4*)&t[r*136 + c*8] = *(const uint4*)(src + (size_t)r * QKV_N + c*8);
    }
    __syncthreads();
    __half* dst = vh + ((size_t)(b*NKV + h) * HD) * SS + s0;
    for (int i = tid; i < 128*8; i += 256) {
        int d = i >> 3, c = i & 7;
        __half v[8];
        #pragma unroll
        for (int j = 0; j < 8; j++) v[j] = t[(c*8 + j)*136 + d];
        *(uint4*)(dst + (size_t)d * SS + c*8) = *(uint4*)v;
    }
}

// ---------------- Tensor-core flash attention (fp16 mma, f16x2 exp2) ---------
#define FLH_SMEM_BYTES ((128*136 + 2*64*136 + 2*128*72) * 2)
__global__ __launch_bounds__(256) void flash_tc_kernel(
    const __half* __restrict__ qh, const __half* __restrict__ kh,
    const __half* __restrict__ vh, __half* __restrict__ oh)
{
    extern __shared__ __half smh[];
    __half* Qs  = smh;                      // [128][136]
    __half* Ks0 = Qs + 128*136;             // [64][136] x2
    __half* Ks1 = Ks0 + 64*136;
    __half* Vs0 = Ks1 + 64*136;             // [128][72] x2 (Vt: [d][kc])
    __half* Vs1 = Vs0 + 128*72;
    int tid = threadIdx.x, lane = tid & 31, wid = tid >> 5;
    int g = lane >> 2, tig = lane & 3;
    int qb = gridDim.x - 1 - blockIdx.x;    // biggest workload first
    int hb = blockIdx.y, bb = blockIdx.z;
    uint32_t ksb[2] = {smem_u32(Ks0), smem_u32(Ks1)};
    uint32_t vsb[2] = {smem_u32(Vs0), smem_u32(Vs1)};
    uint32_t qsb = smem_u32(Qs);

    const __half* Qg = qh + ((size_t)(bb*NH + hb) * SS + (size_t)qb*128) * HD;
    const __half* Kg = kh + (size_t)(bb*NKV + (hb >> 2)) * SS * HD;
    const __half* Vg = vh + (size_t)(bb*NKV + (hb >> 2)) * HD * SS;

    for (int i = tid; i < 128*16; i += 256) {
        int r = i >> 4, c = i & 15;
        cpa16(qsb + (uint32_t)(r*136 + c*8)*2, Qg + r*HD + c*8);
    }
    {   // stage 0
        for (int i = tid; i < 64*16; i += 256) {
            int r = i >> 4, c = i & 15;
            cpa16(ksb[0] + (uint32_t)(r*136 + c*8)*2, Kg + (size_t)r*HD + c*8);
        }
        for (int i = tid; i < 128*8; i += 256) {
            int r = i >> 3, c = i & 7;
            cpa16(vsb[0] + (uint32_t)(r*72 + c*8)*2, Vg + (size_t)r*SS + c*8);
        }
        CP_COMMIT();
    }

    float accO[16][4];
    #pragma unroll
    for (int nd = 0; nd < 16; nd++)
        #pragma unroll
        for (int q = 0; q < 4; q++) accO[nd][q] = 0.f;
    float accL[4] = {0.f, 0.f, 0.f, 0.f};   // row sums via ones-MMA
    const uint32_t ONES2 = 0x3C003C00u;     // half2(1,1)
    uint32_t b_ones[2] = {ONES2, ONES2};
    int r0 = qb*128 + wid*16 + g;
    int r1 = r0 + 8;

    int nkb = 2*(qb + 1);
    for (int kb = 0; kb < nkb; kb++) {
        int st = kb & 1;
        if (kb + 1 < nkb) {
            int st2 = st ^ 1;
            for (int i = tid; i < 64*16; i += 256) {
                int r = i >> 4, c = i & 15;
                cpa16(ksb[st2] + (uint32_t)(r*136 + c*8)*2,
                      Kg + (size_t)((kb+1)*64 + r)*HD + c*8);
            }
            for (int i = tid; i < 128*8; i += 256) {
                int r = i >> 3, c = i & 7;
                cpa16(vsb[st2] + (uint32_t)(r*72 + c*8)*2,
                      Vg + (size_t)r*SS + (kb+1)*64 + c*8);
            }
            CP_COMMIT(); CP_WAIT1();
        } else {
            CP_WAIT0();
        }
        __syncthreads();
        const __half* Ks = (st == 0) ? Ks0 : Ks1;
        const __half* Vs = (st == 0) ? Vs0 : Vs1;

        float sacc[8][4];
        #pragma unroll
        for (int nt = 0; nt < 8; nt++)
            #pragma unroll
            for (int q = 0; q < 4; q++) sacc[nt][q] = 0.f;
        #pragma unroll
        for (int ks = 0; ks < 8; ks++) {
            uint32_t a[4];
            const __half* qr = &Qs[(wid*16 + g)*136 + ks*16 + 2*tig];
            a[0] = *(const uint32_t*)qr;
            a[1] = *(const uint32_t*)(qr + 8*136);
            a[2] = *(const uint32_t*)(qr + 8);
            a[3] = *(const uint32_t*)(qr + 8*136 + 8);
            #pragma unroll
            for (int nt = 0; nt < 8; nt++) {
                uint32_t b[2];
                const __half* kr = &Ks[(nt*8 + g)*136 + ks*16 + 2*tig];
                b[0] = *(const uint32_t*)kr;
                b[1] = *(const uint32_t*)(kr + 8);
                mma16816(sacc[nt], a, b);
            }
        }
        if (kb >= 2*qb) {
            #pragma unroll
            for (int nt = 0; nt < 8; nt++) {
                int col = kb*64 + nt*8 + 2*tig;
                if (col     > r0) sacc[nt][0] = -10000.f;
                if (col + 1 > r0) sacc[nt][1] = -10000.f;
                if (col     > r1) sacc[nt][2] = -10000.f;
                if (col + 1 > r1) sacc[nt][3] = -10000.f;
            }
        }
        #pragma unroll
        for (int j = 0; j < 4; j++) {
            uint32_t a[4];
            __half2 t;
            t = __floats2half2_rn(sacc[2*j][0],   sacc[2*j][1]);   a[0] = ex2h2(*(uint32_t*)&t);
            t = __floats2half2_rn(sacc[2*j][2],   sacc[2*j][3]);   a[1] = ex2h2(*(uint32_t*)&t);
            t = __floats2half2_rn(sacc[2*j+1][0], sacc[2*j+1][1]); a[2] = ex2h2(*(uint32_t*)&t);
            t = __floats2half2_rn(sacc[2*j+1][2], sacc[2*j+1][3]); a[3] = ex2h2(*(uint32_t*)&t);
            mma16816(accL, a, b_ones);
            #pragma unroll
            for (int nd = 0; nd < 16; nd++) {
                uint32_t b[2];
                const __half* vr = &Vs[(nd*8 + g)*72 + j*16 + 2*tig];
                b[0] = *(const uint32_t*)vr;
                b[1] = *(const uint32_t*)(vr + 8);
                mma16816(accO[nd], a, b);
            }
        }
        __syncthreads();
    }
    float inv0 = 1.f / accL[0], inv1 = 1.f / accL[2];
    __half* stg = smh;
    int lr = wid*16 + g;
    size_t obase = ((size_t)bb*SS + (size_t)qb*128) * EMBED + hb*HD;
    #pragma unroll
    for (int nd = 0; nd < 16; nd++) {
        int col = nd*8 + 2*tig;
        *(__half2*)&stg[lr*136 + col] =
            __floats2half2_rn(accO[nd][0]*inv0, accO[nd][1]*inv0);
        *(__half2*)&stg[(lr+8)*136 + col] =
            __floats2half2_rn(accO[nd][2]*inv1, accO[nd][3]*inv1);
    }
    __syncthreads();
    for (int i = tid; i < 128*16; i += 256) {
        int r = i >> 4, c = i & 15;
        *(uint4*)(oh + obase + (size_t)r*EMBED + c*8) = *(uint4*)&stg[r*136 + c*8];
    }
}

// ---------------- driver ------------------------------------------------------
static inline void conv_launch(const float* src, __half* dst, size_t n)
{
    int n4 = (int)(n / 4);
    conv_kernel<<<(n4 + 255)/256, 256>>>(src, dst, n4);
}

extern "C" void kernel_launch(void* const* d_in, const int* in_sizes, int n_in,
                              void* d_out, int out_size)
{
    const float* x       = (const float*)d_in[0];
    const float* freqs   = (const float*)d_in[2];
    const float* w_qkv   = (const float*)d_in[4];
    const float* w_fc    = (const float*)d_in[5];
    const float* w1      = (const float*)d_in[6];
    const float* w2      = (const float*)d_in[7];
    const float* w3      = (const float*)d_in[8];
    const float* attn_nw = (const float*)d_in[9];
    const float* ff_nw   = (const float*)d_in[10];
    float* out = (float*)d_out;

    float *h1;
    __half *qkvh, *qh, *kh, *vh, *ah, *sw, *wh;
    cudaGetSymbolAddress((void**)&qkvh, g_qkvh);
    cudaGetSymbolAddress((void**)&qh,  g_qh2);
    cudaGetSymbolAddress((void**)&kh,  g_kh2);
    cudaGetSymbolAddress((void**)&vh,  g_vh2);
    cudaGetSymbolAddress((void**)&h1,  g_h1);
    cudaGetSymbolAddress((void**)&ah,  g_ah);
    cudaGetSymbolAddress((void**)&sw,  g_sw);
    cudaGetSymbolAddress((void**)&wh,  g_wh);

    cudaFuncSetAttribute(tc_gemm, cudaFuncAttributeMaxDynamicSharedMemorySize, GM_SMEM_BYTES);
    cudaFuncSetAttribute(flash_tc_kernel, cudaFuncAttributeMaxDynamicSharedMemorySize, FLH_SMEM_BYTES);

    // 1. attn rmsnorm -> fp16
    rmsnorm_h_kernel<<<ROWS, 256>>>(x, attn_nw, ah);
    // 2. qkv projection -> fp16 qkvh
    conv_launch(w_qkv, wh, (size_t)QKV_N*EMBED);
    tc_gemm<<<dim3(QKV_N/256, ROWS/256), 256, GM_SMEM_BYTES>>>(
        ah, wh, nullptr, qkvh, nullptr, ROWS, QKV_N, EMBED, 1);
    // 3. rope (q,k) + coalesced V transpose
    rope_kernel<<<dim3(SS, BB), 256>>>(qkvh, freqs, qh, kh);
    vtrans_kernel<<<dim3(SS/64, NKV, BB), 256>>>(qkvh, vh);
    // 4. tensor-core flash attention -> fp16 attn into g_ah
    flash_tc_kernel<<<dim3(SS/128, NH, BB), 256, FLH_SMEM_BYTES>>>(qh, kh, vh, ah);
    // 5. output projection + residual -> fp32 h1
    conv_launch(w_fc, wh, (size_t)EMBED*EMBED);
    tc_gemm<<<dim3(EMBED/256, ROWS/256), 256, GM_SMEM_BYTES>>>(
        ah, wh, h1, nullptr, x, ROWS, EMBED, EMBED, 0);
    // 6. ffn rmsnorm -> fp16
    rmsnorm_h_kernel<<<ROWS, 256>>>(h1, ff_nw, ah);
    // 7. interleaved gate|up projection with FUSED swiglu -> g_sw
    {
        int n4 = FF*EMBED/4;
        conv_inter_kernel<<<(n4 + 255)/256, 256>>>(w1, w2, wh, n4);
    }
    tc_gemm<<<dim3(2*FF/256, ROWS/256), 256, GM_SMEM_BYTES>>>(
        ah, wh, nullptr, sw, nullptr, ROWS, 2*FF, EMBED, 2);
    // 8. down projection + residual -> out
    conv_launch(w3, wh, (size_t)EMBED*FF);
    tc_gemm<<<dim3(EMBED/256, ROWS/256), 256, GM_SMEM_BYTES>>>(
        sw, wh, out, nullptr, h1, ROWS, EMBED, FF, 0);
}

// round 15
// speedup vs baseline: 28.3759x; 1.0037x over previous
#include <cuda_runtime.h>
#include <cuda.h>
#include <cuda_bf16.h>
#include <cuda_fp16.h>
#include <math.h>
#include <stdint.h>

#define EMBED 2048
#define NH 16
#define NKV 4
#define HD 128
#define FF 5632
#define BB 2
#define SS 2048
#define ROWS (BB*SS)                 // 4096 tokens
#define QKV_N ((NH + 2*NKV)*HD)      // 3072

#if defined(__CUDA_ARCH_FEAT_SM103_ALL) || defined(__CUDA_ARCH_FEAT_SM100_ALL)
#define USE_TCGEN05 1
#else
#define USE_TCGEN05 0
#endif

// ---------------- scratch (device globals; no allocations allowed) ----------
__device__ __half g_qkvh[ROWS*QKV_N];     // fp16 qkv gemm output
__device__ __half g_qh2[BB*NH *SS*HD];    // fp16 Q (scaled by 1/sqrt(E)*log2e), [b,h,s,d]
__device__ __half g_kh2[BB*NKV*SS*HD];    // fp16 K, [b,kvh,s,d]
__device__ __half g_vh2[BB*NKV*HD*SS];    // fp16 V transposed, [b,kvh,d,s]
__device__ float  g_h1 [ROWS*EMBED];
__device__ __half g_ah [ROWS*FF];         // fp16 activations (gemm A operand)
__device__ __half g_sw [ROWS*FF];         // fp16 fused-swiglu output (down-proj A)
__device__ __half g_wh [2*FF*EMBED];      // fp16 weights     (gemm B operand)

#define GM_STAGE_BYTES 65536              // A 32K + B 32K
#define GM_NSTAGE 3
#define GM_SMEM_BYTES (1024 + GM_NSTAGE*GM_STAGE_BYTES)

// ---------- common helpers (legal on plain sm_103 PTX) ----------------------
__device__ __forceinline__ uint32_t smem_u32(const void* p) {
    uint32_t a;
    asm("{ .reg .u64 t; cvta.to.shared.u64 t, %1; cvt.u32.u64 %0, t; }" : "=r"(a) : "l"(p));
    return a;
}
#define CP_COMMIT() asm volatile("cp.async.commit_group;" ::: "memory")
#define CP_WAIT0()  asm volatile("cp.async.wait_group 0;" ::: "memory")
#define CP_WAIT1()  asm volatile("cp.async.wait_group 1;" ::: "memory")
__device__ __forceinline__ void cpa16(uint32_t saddr, const void* g) {
    asm volatile("cp.async.cg.shared.global [%0], [%1], 16;" :: "r"(saddr), "l"(g) : "memory");
}
__device__ __forceinline__ void mma16816(float* c, const uint32_t* a, const uint32_t* b) {
    asm volatile("mma.sync.aligned.m16n8k16.row.col.f32.f16.f16.f32 "
        "{%0,%1,%2,%3}, {%4,%5,%6,%7}, {%8,%9}, {%0,%1,%2,%3};"
        : "+f"(c[0]), "+f"(c[1]), "+f"(c[2]), "+f"(c[3])
        : "r"(a[0]), "r"(a[1]), "r"(a[2]), "r"(a[3]), "r"(b[0]), "r"(b[1]));
}
__device__ __forceinline__ uint32_t ex2h2(uint32_t x) {
    uint32_t y; asm("ex2.approx.f16x2 %0, %1;" : "=r"(y) : "r"(x)); return y;
}
__device__ __forceinline__ float siluf(float a) {
    return a / (1.f + __expf(-a));
}

// ======================= fp32 -> fp16 convert (weights) ======================
__global__ __launch_bounds__(256) void conv_kernel(
    const float* __restrict__ x, __half* __restrict__ y, int n4)
{
    int i = blockIdx.x * 256 + threadIdx.x;
    if (i >= n4) return;
    float4 v = ((const float4*)x)[i];
    __half2* Y = (__half2*)y;
    Y[2*i]   = __floats2half2_rn(v.x, v.y);
    Y[2*i+1] = __floats2half2_rn(v.z, v.w);
}

// interleave rows: w1 row j -> dst row 2j, w2 row j -> dst row 2j+1
__global__ __launch_bounds__(256) void conv_inter_kernel(
    const float* __restrict__ w1, const float* __restrict__ w2,
    __half* __restrict__ y, int n4)   // n4 = FF*EMBED/4
{
    int i = blockIdx.x * 256 + threadIdx.x;
    if (i >= n4) return;
    const int RQ = EMBED / 4;
    int row = i / RQ, q = i % RQ;
    float4 a = ((const float4*)w1)[i];
    float4 b = ((const float4*)w2)[i];
    __half2* Y1 = (__half2*)(y + ((size_t)(2*row)   * EMBED) + q*4);
    __half2* Y2 = (__half2*)(y + ((size_t)(2*row+1) * EMBED) + q*4);
    Y1[0] = __floats2half2_rn(a.x, a.y);
    Y1[1] = __floats2half2_rn(a.z, a.w);
    Y2[0] = __floats2half2_rn(b.x, b.y);
    Y2[1] = __floats2half2_rn(b.z, b.w);
}

#if USE_TCGEN05
// ======================= tcgen05 GEMM + TMA multicast (sm_103a) ==============
__device__ __forceinline__ uint32_t elect_one_pred() {
    uint32_t pred;
    asm volatile(
        "{\n\t.reg .pred p;\n\telect.sync _|p, 0xFFFFFFFF;\n\tselp.b32 %0, 1, 0, p;\n\t}"
        : "=r"(pred));
    return pred;
}
__device__ __forceinline__ uint32_t cluster_rank() {
    uint32_t r; asm("mov.u32 %0, %%cluster_ctarank;" : "=r"(r)); return r;
}
#define MBAR_INIT(addr, cnt) \
    asm volatile("mbarrier.init.shared.b64 [%0], %1;" :: "r"(addr), "r"((uint32_t)(cnt)) : "memory")
#define MBAR_INVAL(addr) \
    asm volatile("mbarrier.inval.shared.b64 [%0];" :: "r"(addr) : "memory")
#define MBAR_EXPECT_TX(addr, bytes) \
    asm volatile("mbarrier.arrive.expect_tx.shared.b64 _, [%0], %1;" \
        :: "r"((uint32_t)(addr)), "r"((uint32_t)(bytes)) : "memory")
#define MBAR_WAIT(addr, parity) do { \
    uint32_t _m = (addr); uint32_t _p = (parity); uint32_t _d; \
    asm volatile("{\n\t.reg .pred p;\n\tmbarrier.try_wait.parity.acquire.cta.shared::cta.b64 p, [%1], %2;\n\tselp.b32 %0, 1, 0, p;\n\t}" \
        : "=r"(_d) : "r"(_m), "r"(_p) : "memory"); \
    if (!_d) { \
        asm volatile("{\n\t.reg .pred P1;\n\tWL_%=:\n\tmbarrier.try_wait.parity.acquire.cta.shared::cta.b64 P1, [%0], %1, 0x989680;\n\t@P1 bra.uni WD_%=;\n\tbra.uni WL_%=;\n\tWD_%=:\n\t}" \
            :: "r"(_m), "r"(_p) : "memory"); \
    } } while(0)
#define TC_ALLOC(smem_addr, n) \
    asm volatile("tcgen05.alloc.cta_group::1.sync.aligned.shared::cta.b32 [%0], %1;" \
        :: "r"((uint32_t)(smem_addr)), "r"((uint32_t)(n)) : "memory")
#define TC_DEALLOC(tmem_addr, n) \
    asm volatile("tcgen05.dealloc.cta_group::1.sync.aligned.b32 %0, %1;" :: "r"(tmem_addr), "r"((uint32_t)(n)))
#define TC_RELINQ() \
    asm volatile("tcgen05.relinquish_alloc_permit.cta_group::1.sync.aligned;")
#define TC_COMMIT(mbar) \
    asm volatile("tcgen05.commit.cta_group::1.mbarrier::arrive::one.shared::cluster.b64 [%0];" \
        :: "r"((uint32_t)(mbar)) : "memory")
#define TC_COMMIT_MC(mbar, mask) \
    asm volatile("tcgen05.commit.cta_group::1.mbarrier::arrive::one.shared::cluster.multicast::cluster.b64 [%0], %1;" \
        :: "r"((uint32_t)(mbar)), "h"((uint16_t)(mask)) : "memory")
#define TC_FENCE_AFTER() asm volatile("tcgen05.fence::after_thread_sync;" ::: "memory")
#define TC_FENCE_BEFORE() asm volatile("tcgen05.fence::before_thread_sync;" ::: "memory")
#define TC_WAIT_LD() asm volatile("tcgen05.wait::ld.sync.aligned;" ::: "memory")
#define CLUSTER_SYNC() do { \
    asm volatile("barrier.cluster.arrive.aligned;" ::: "memory"); \
    asm volatile("barrier.cluster.wait.aligned;" ::: "memory"); } while(0)
#define TMA_2D(smem, map, x, y, mbar) \
    asm volatile("cp.async.bulk.tensor.2d.shared::cta.global.tile.mbarrier::complete_tx::bytes " \
        "[%0], [%1, {%2, %3}], [%4];" \
        :: "r"((uint32_t)(smem)), "l"(map), "r"((int)(x)), "r"((int)(y)), "r"((uint32_t)(mbar)) : "memory")
#define TMA_2D_MC(smem, map, x, y, mbar, mask) \
    asm volatile("cp.async.bulk.tensor.2d.shared::cluster.global.tile.mbarrier::complete_tx::bytes.multicast::cluster " \
        "[%0], [%1, {%2, %3}], [%4], %5;" \
        :: "r"((uint32_t)(smem)), "l"(map), "r"((int)(x)), "r"((int)(y)), "r"((uint32_t)(mbar)), "h"((uint16_t)(mask)) : "memory")
#define TC_LD_X32(r, tmem_addr) \
    asm volatile("tcgen05.ld.sync.aligned.32x32b.x32.b32 " \
        "{%0, %1, %2, %3, %4, %5, %6, %7, %8, %9, %10, %11, %12, %13, %14, %15, " \
        " %16, %17, %18, %19, %20, %21, %22, %23, %24, %25, %26, %27, %28, %29, %30, %31}, [%32];" \
        : "=r"((r)[0]),  "=r"((r)[1]),  "=r"((r)[2]),  "=r"((r)[3]), \
          "=r"((r)[4]),  "=r"((r)[5]),  "=r"((r)[6]),  "=r"((r)[7]), \
          "=r"((r)[8]),  "=r"((r)[9]),  "=r"((r)[10]), "=r"((r)[11]), \
          "=r"((r)[12]), "=r"((r)[13]), "=r"((r)[14]), "=r"((r)[15]), \
          "=r"((r)[16]), "=r"((r)[17]), "=r"((r)[18]), "=r"((r)[19]), \
          "=r"((r)[20]), "=r"((r)[21]), "=r"((r)[22]), "=r"((r)[23]), \
          "=r"((r)[24]), "=r"((r)[25]), "=r"((r)[26]), "=r"((r)[27]), \
          "=r"((r)[28]), "=r"((r)[29]), "=r"((r)[30]), "=r"((r)[31]) \
        : "r"(tmem_addr))

__device__ __forceinline__ uint64_t mk_desc(uint32_t addr) {
    const uint64_t base = (2ull << 61) | (1ull << 46) | (64ull << 32) | (1ull << 16);
    return base | ((uint64_t)(addr >> 4) & 0x3FFF);
}
__device__ __forceinline__ void mma_f16_ss(uint32_t d, uint64_t da, uint64_t db,
                                           uint32_t idesc, uint32_t en) {
    asm volatile(
        "{\n\t.reg .pred p;\n\tsetp.ne.u32 p, %5, 0;\n\t"
        "tcgen05.mma.cta_group::1.kind::f16 [%0], %1, %2, %3, {%4,%4,%4,%4}, p;\n\t}"
        :: "r"(d), "l"(da), "l"(db), "r"(idesc), "r"(0u), "r"(en) : "memory");
}

#define GM_IDESC 0x8400010u              // F32 acc, fp16 a/b, M=128, N=256

// smem barrier offsets: full[0..2] at +8,+16,+24; done[0,1] at +32,+40; final +48
// mode: 0 = fp32 out (+optional addend), 1 = fp16 out, 2 = fused silu (pairs)
__global__ __launch_bounds__(256, 1) void tc_gemm(
    const __grid_constant__ CUtensorMap mA, const __grid_constant__ CUtensorMap mB,
    const __half* __restrict__ A, const __half* __restrict__ B,
    float* __restrict__ Cf, __half* __restrict__ Ch,
    const float* __restrict__ addend,
    int M, int N, int K, int mode)
{
    extern __shared__ char smem[];
    uint32_t sb = smem_u32(smem);
    int tid = threadIdx.x;
    int wid = tid >> 5, lane = tid & 31;
    int bn = blockIdx.x * 256, bm = blockIdx.y * 256;
    uint32_t rank = cluster_rank();     // cluster {1,2,1}: pair shares bn

    if (wid == 0) { TC_ALLOC(sb, 512); TC_RELINQ(); }
    if (tid == 0) {
        MBAR_INIT(sb + 8, 1);  MBAR_INIT(sb + 16, 1); MBAR_INIT(sb + 24, 1);  // full
        MBAR_INIT(sb + 32, 2); MBAR_INIT(sb + 40, 2);                          // done (2 commits)
        MBAR_INIT(sb + 48, 1);                                                 // final
    }
    __syncthreads();
    uint32_t tmem;
    asm volatile("ld.shared.b32 %0, [%1];" : "=r"(tmem) : "r"(sb));
    CLUSTER_SYNC();   // peer barriers initialized before any multicast

    const int NC = K / 64;
    if (tid == 0) {
        int phf[3] = {0, 0, 0};
        int phd0 = 0, phd1 = 0;
        // prologue: issue loads for chunks 0 and 1
        #pragma unroll
        for (int c0 = 0; c0 < 2; c0++) {
            uint32_t stb = sb + 1024 + (uint32_t)c0 * GM_STAGE_BYTES;
            MBAR_EXPECT_TX(sb + 8 + c0*8, GM_STAGE_BYTES);
            TMA_2D(stb, &mA, c0*64, bm, sb + 8 + c0*8);
            if (rank == 0) TMA_2D_MC(stb + 32768, &mB, c0*64, bn, sb + 8 + c0*8, 3);
        }
        for (int c = 0; c < NC; c++) {
            int s = c % GM_NSTAGE;
            MBAR_WAIT(sb + 8 + s*8, phf[s]); phf[s] ^= 1;
            uint32_t stb = sb + 1024 + (uint32_t)s * GM_STAGE_BYTES;
            uint64_t dA0 = mk_desc(stb);
            uint64_t dA1 = mk_desc(stb + 16384);
            uint64_t dB  = mk_desc(stb + 32768);
            #pragma unroll
            for (int k = 0; k < 4; k++) {
                uint32_t en = (c > 0) || (k > 0);
                mma_f16_ss(tmem,       dA0 + k*2, dB + k*2, GM_IDESC, en);
                mma_f16_ss(tmem + 256, dA1 + k*2, dB + k*2, GM_IDESC, en);
            }
            TC_COMMIT_MC(sb + 32 + (uint32_t)(c & 1) * 8, 3);
            if (c == NC - 1) TC_COMMIT(sb + 48);
            if (c + 2 < NC) {
                // loads of chunk c+2 reuse (in BOTH CTAs, via multicast) the stage
                // consumed by chunk c-1 -> wait both CTAs' MMA c-1 done
                if (c >= 1) {
                    int m = (c - 1) & 1;
                    if (m == 0) { MBAR_WAIT(sb + 32, phd0); phd0 ^= 1; }
                    else        { MBAR_WAIT(sb + 40, phd1); phd1 ^= 1; }
                }
                int s2 = (c + 2) % GM_NSTAGE;
                uint32_t stb2 = sb + 1024 + (uint32_t)s2 * GM_STAGE_BYTES;
                MBAR_EXPECT_TX(sb + 8 + s2*8, GM_STAGE_BYTES);
                TMA_2D(stb2, &mA, (c+2)*64, bm, sb + 8 + s2*8);
                if (rank == 0) TMA_2D_MC(stb2 + 32768, &mB, (c+2)*64, bn, sb + 8 + s2*8, 3);
            }
        }
    }
    // all threads wait for final MMA completion (first & only wait: parity 0)
    MBAR_WAIT(sb + 48, 0);
    TC_FENCE_AFTER();

    int wg = wid >> 2, ws = wid & 3;
    #pragma unroll
    for (int h = 0; h < 2; h++) {
        size_t row = (size_t)(bm + h*128 + ws * 32 + lane);
        #pragma unroll
        for (int cb = 0; cb < 4; cb++) {
            uint32_t regs[32];
            TC_LD_X32(regs, tmem + (uint32_t)(h*256 + wg * 128 + cb * 32));
            TC_WAIT_LD();
            int col = bn + wg * 128 + cb * 32;
            if (mode == 2) {
                __half2 o[8];
                #pragma unroll
                for (int t = 0; t < 16; t += 2) {
                    float r0 = siluf(__uint_as_float(regs[2*t]))   * __uint_as_float(regs[2*t+1]);
                    float r1 = siluf(__uint_as_float(regs[2*t+2])) * __uint_as_float(regs[2*t+3]);
                    o[t >> 1] = __floats2half2_rn(r0, r1);
                }
                __half* Cp = Ch + row * (size_t)FF + (col >> 1);
                *(uint4*)(Cp)     = *(uint4*)&o[0];
                *(uint4*)(Cp + 8) = *(uint4*)&o[4];
            } else if (mode == 1) {
                __half* Cp = Ch + row * (size_t)N + col;
                #pragma unroll
                for (int j = 0; j < 32; j += 8) {
                    __half2 o[4];
                    o[0] = __floats2half2_rn(__uint_as_float(regs[j]),   __uint_as_float(regs[j+1]));
                    o[1] = __floats2half2_rn(__uint_as_float(regs[j+2]), __uint_as_float(regs[j+3]));
                    o[2] = __floats2half2_rn(__uint_as_float(regs[j+4]), __uint_as_float(regs[j+5]));
                    o[3] = __floats2half2_rn(__uint_as_float(regs[j+6]), __uint_as_float(regs[j+7]));
                    *(uint4*)(Cp + j) = *(uint4*)o;
                }
            } else {
                float* Cp = Cf + row * (size_t)N + col;
                if (addend) {
                    const float* Ap = addend + row * (size_t)N + col;
                    #pragma unroll
                    for (int j = 0; j < 32; j += 4) {
                        float4 a = *(const float4*)(Ap + j);
                        float4 o = make_float4(__uint_as_float(regs[j])   + a.x,
                                               __uint_as_float(regs[j+1]) + a.y,
                                               __uint_as_float(regs[j+2]) + a.z,
                                               __uint_as_float(regs[j+3]) + a.w);
                        *(float4*)(Cp + j) = o;
                    }
                } else {
                    #pragma unroll
                    for (int j = 0; j < 32; j += 4) {
                        float4 o = make_float4(__uint_as_float(regs[j]),
                                               __uint_as_float(regs[j+1]),
                                               __uint_as_float(regs[j+2]),
                                               __uint_as_float(regs[j+3]));
                        *(float4*)(Cp + j) = o;
                    }
                }
            }
        }
    }
    TC_FENCE_BEFORE();
    __syncthreads();
    if (tid == 0) {
        MBAR_INVAL(sb + 8);  MBAR_INVAL(sb + 16); MBAR_INVAL(sb + 24);
        MBAR_INVAL(sb + 32); MBAR_INVAL(sb + 40); MBAR_INVAL(sb + 48);
    }
    if (wid == 0) { TC_DEALLOC(tmem, 512); }
    CLUSTER_SYNC();
}

#else
// ======================= mma.sync GEMM fallback ==============================
#define FB_LD 40

__global__ __launch_bounds__(256, 1) void tc_gemm(
    const __grid_constant__ CUtensorMap mA, const __grid_constant__ CUtensorMap mB,
    const __half* __restrict__ A, const __half* __restrict__ B,
    float* __restrict__ Cf, __half* __restrict__ Ch,
    const float* __restrict__ addend,
    int M, int N, int K, int mode)
{
    extern __shared__ char smem[];
    __half* sA = (__half*)smem;               // [128][40]
    __half* sB = sA + 128*FB_LD;              // [256][40]
    int tid = threadIdx.x, lane = tid & 31, wid = tid >> 5;
    int bn = blockIdx.x * 256;
    int wm = wid >> 2, wn = wid & 3;
    int g = lane >> 2, tig = lane & 3;

    for (int half = 0; half < 2; half++) {
        int bm = blockIdx.y * 256 + half * 128;
        float acc[4][8][4];
        #pragma unroll
        for (int mt = 0; mt < 4; mt++)
            #pragma unroll
            for (int nt = 0; nt < 8; nt++)
                #pragma unroll
                for (int q = 0; q < 4; q++) acc[mt][nt][q] = 0.f;

        for (int k0 = 0; k0 < K; k0 += 32) {
            __syncthreads();
            for (int v = tid; v < 512; v += 256) {
                int r = v >> 2, q = v & 3;
                *(uint4*)&sA[r*FB_LD + q*8] = *(const uint4*)(A + (size_t)(bm+r)*K + k0 + q*8);
            }
            for (int v = tid; v < 1024; v += 256) {
                int r = v >> 2, q = v & 3;
                *(uint4*)&sB[r*FB_LD + q*8] = *(const uint4*)(B + (size_t)(bn+r)*K + k0 + q*8);
            }
            __syncthreads();
            #pragma unroll
            for (int ks = 0; ks < 2; ks++) {
                int kk = ks * 16 + tig * 2;
                uint32_t a[4][4], b[8][2];
                #pragma unroll
                for (int mt = 0; mt < 4; mt++) {
                    int mr = (wm*64 + mt*16 + g)*FB_LD + kk;
                    a[mt][0] = *(const uint32_t*)&sA[mr];
                    a[mt][1] = *(const uint32_t*)&sA[mr + 8*FB_LD];
                    a[mt][2] = *(const uint32_t*)&sA[mr + 8];
                    a[mt][3] = *(const uint32_t*)&sA[mr + 8*FB_LD + 8];
                }
                #pragma unroll
                for (int nt = 0; nt < 8; nt++) {
                    int nr = (wn*64 + nt*8 + g)*FB_LD + kk;
                    b[nt][0] = *(const uint32_t*)&sB[nr];
                    b[nt][1] = *(const uint32_t*)&sB[nr + 8];
                }
                #pragma unroll
                for (int mt = 0; mt < 4; mt++)
                    #pragma unroll
                    for (int nt = 0; nt < 8; nt++)
                        mma16816(acc[mt][nt], a[mt], b[nt]);
            }
        }
        #pragma unroll
        for (int mt = 0; mt < 4; mt++) {
            #pragma unroll
            for (int nt = 0; nt < 8; nt++) {
                size_t r0 = (size_t)(bm + wm*64 + mt*16 + g);
                int col = bn + wn*64 + nt*8 + tig*2;
                if (mode == 2) {
                    float v0 = siluf(acc[mt][nt][0]) * acc[mt][nt][1];
                    float v1 = siluf(acc[mt][nt][2]) * acc[mt][nt][3];
                    Ch[r0*FF + (col>>1)]     = __float2half_rn(v0);
                    Ch[(r0+8)*FF + (col>>1)] = __float2half_rn(v1);
                } else if (mode == 1) {
                    *(__half2*)(Ch + r0*N + col)     = __floats2half2_rn(acc[mt][nt][0], acc[mt][nt][1]);
                    *(__half2*)(Ch + (r0+8)*N + col) = __floats2half2_rn(acc[mt][nt][2], acc[mt][nt][3]);
                } else {
                    float2 v0 = make_float2(acc[mt][nt][0], acc[mt][nt][1]);
                    float2 v1 = make_float2(acc[mt][nt][2], acc[mt][nt][3]);
                    if (addend) {
                        float2 a0 = *(const float2*)(addend + r0*N + col);
                        float2 a1 = *(const float2*)(addend + (r0+8)*N + col);
                        v0.x += a0.x; v0.y += a0.y; v1.x += a1.x; v1.y += a1.y;
                    }
                    *(float2*)(Cf + r0*N + col)     = v0;
                    *(float2*)(Cf + (r0+8)*N + col) = v1;
                }
            }
        }
        __syncthreads();
    }
}
#endif  // USE_TCGEN05

// ---------------- RMSNorm -> fp16 --------------------------------------------
__global__ __launch_bounds__(256) void rmsnorm_h_kernel(
    const float* __restrict__ x, const float* __restrict__ w,
    __half* __restrict__ out)
{
    __shared__ float red[8];
    int row = blockIdx.x;
    int tid = threadIdx.x;
    const float4* xr = (const float4*)(x + (size_t)row * EMBED);
    const float4* w4 = (const float4*)w;
    float4 v0 = xr[tid];
    float4 v1 = xr[tid + 256];
    float ss = v0.x*v0.x + v0.y*v0.y + v0.z*v0.z + v0.w*v0.w
             + v1.x*v1.x + v1.y*v1.y + v1.z*v1.z + v1.w*v1.w;
    #pragma unroll
    for (int o = 16; o > 0; o >>= 1) ss += __shfl_xor_sync(0xffffffffu, ss, o);
    if ((tid & 31) == 0) red[tid >> 5] = ss;
    __syncthreads();
    float tot = red[0] + red[1] + red[2] + red[3] + red[4] + red[5] + red[6] + red[7];
    float inv = rsqrtf(tot * (1.0f / EMBED) + 1e-5f);
    float4 wa = w4[tid], wb = w4[tid + 256];
    __half2* O = (__half2*)(out + (size_t)row * EMBED);
    O[2*tid]         = __floats2half2_rn(v0.x*inv*wa.x, v0.y*inv*wa.y);
    O[2*tid+1]       = __floats2half2_rn(v0.z*inv*wa.z, v0.w*inv*wa.w);
    O[2*(tid+256)]   = __floats2half2_rn(v1.x*inv*wb.x, v1.y*inv*wb.y);
    O[2*(tid+256)+1] = __floats2half2_rn(v1.z*inv*wb.z, v1.w*inv*wb.w);
}

// ---------------- RoPE (q,k only; fp16 in -> fp16 out) -----------------------
__global__ __launch_bounds__(256) void rope_kernel(
    const __half* __restrict__ qkv, const float* __restrict__ freqs,
    __half* __restrict__ qh, __half* __restrict__ kh)
{
    int s = blockIdx.x, b = blockIdx.y, tid = threadIdx.x;
    const __half* row = qkv + ((size_t)b * SS + s) * QKV_N;
    const float* f = freqs + (size_t)s * HD;
    const float scale = 0.02209708691207961f * 1.4426950408889634f;

    for (int p = tid; p < NH * 64; p += 256) {
        int h = p >> 6, i = p & 63;
        __half2 xv = *(const __half2*)(row + h*HD + 2*i);
        float x0 = __half2float(__low2half(xv)), x1 = __half2float(__high2half(xv));
        float c = f[2*i], sn = f[2*i+1];
        __half2* dst = (__half2*)(qh + ((size_t)(b*NH + h) * SS + s) * HD + 2*i);
        *dst = __floats2half2_rn((x0*c - x1*sn) * scale, (x1*c + x0*sn) * scale);
    }
    for (int p = tid; p < NKV * 64; p += 256) {
        int h = p >> 6, i = p & 63;
        __half2 xv = *(const __half2*)(row + NH*HD + h*HD + 2*i);
        float x0 = __half2float(__low2half(xv)), x1 = __half2float(__high2half(xv));
        float c = f[2*i], sn = f[2*i+1];
        __half2* dst = (__half2*)(kh + ((size_t)(b*NKV + h) * SS + s) * HD + 2*i);
        *dst = __floats2half2_rn(x0*c - x1*sn, x1*c + x0*sn);
    }
}

// ---------------- Coalesced V transpose: [b,s,(kvh,d)] -> [b,kvh,d,s] --------
__global__ __launch_bounds__(256) void vtrans_kernel(
    const __half* __restrict__ qkv, __half* __restrict__ vh)
{
    __shared__ __half t[64*136];   // [64 s][128 d] padded
    int s0 = blockIdx.x * 64, h = blockIdx.y, b = blockIdx.z;
    int tid = threadIdx.x;
    const __half* src = qkv + ((size_t)b * SS + s0) * QKV_N + (size_t)(NH + NKV)*HD + h*HD;
    for (int i = tid; i < 64*16; i += 256) {
        int r = i >> 4, c = i & 15;
        *(uint4*)&t[r*136 + c*8] = *(const uint4*)(src + (size_t)r * QKV_N + c*8);
    }
    __syncthreads();
    __half* dst = vh + ((size_t)(b*NKV + h) * HD) * SS + s0;
    for (int i = tid; i < 128*8; i += 256) {
        int d = i >> 3, c = i & 7;
        __half v[8];
        #pragma unroll
        for (int j = 0; j < 8; j++) v[j] = t[(c*8 + j)*136 + d];
        *(uint4*)(dst + (size_t)d * SS + c*8) = *(uint4*)v;
    }
}

// ---------------- Tensor-core flash attention (fp16 mma, f16x2 exp2) ---------
#define FLH_SMEM_BYTES ((128*136 + 2*64*136 + 2*128*72) * 2)
__global__ __launch_bounds__(256) void flash_tc_kernel(
    const __half* __restrict__ qh, const __half* __restrict__ kh,
    const __half* __restrict__ vh, __half* __restrict__ oh)
{
    extern __shared__ __half smh[];
    __half* Qs  = smh;                      // [128][136]
    __half* Ks0 = Qs + 128*136;             // [64][136] x2
    __half* Ks1 = Ks0 + 64*136;
    __half* Vs0 = Ks1 + 64*136;             // [128][72] x2 (Vt: [d][kc])
    __half* Vs1 = Vs0 + 128*72;
    int tid = threadIdx.x, lane = tid & 31, wid = tid >> 5;
    int g = lane >> 2, tig = lane & 3;
    int qb = gridDim.x - 1 - blockIdx.x;    // biggest workload first
    int hb = blockIdx.y, bb = blockIdx.z;
    uint32_t ksb[2] = {smem_u32(Ks0), smem_u32(Ks1)};
    uint32_t vsb[2] = {smem_u32(Vs0), smem_u32(Vs1)};
    uint32_t qsb = smem_u32(Qs);

    const __half* Qg = qh + ((size_t)(bb*NH + hb) * SS + (size_t)qb*128) * HD;
    const __half* Kg = kh + (size_t)(bb*NKV + (hb >> 2)) * SS * HD;
    const __half* Vg = vh + (size_t)(bb*NKV + (hb >> 2)) * HD * SS;

    for (int i = tid; i < 128*16; i += 256) {
        int r = i >> 4, c = i & 15;
        cpa16(qsb + (uint32_t)(r*136 + c*8)*2, Qg + r*HD + c*8);
    }
    {   // stage 0
        for (int i = tid; i < 64*16; i += 256) {
            int r = i >> 4, c = i & 15;
            cpa16(ksb[0] + (uint32_t)(r*136 + c*8)*2, Kg + (size_t)r*HD + c*8);
        }
        for (int i = tid; i < 128*8; i += 256) {
            int r = i >> 3, c = i & 7;
            cpa16(vsb[0] + (uint32_t)(r*72 + c*8)*2, Vg + (size_t)r*SS + c*8);
        }
        CP_COMMIT();
    }

    float accO[16][4];
    #pragma unroll
    for (int nd = 0; nd < 16; nd++)
        #pragma unroll
        for (int q = 0; q < 4; q++) accO[nd][q] = 0.f;
    float accL[4] = {0.f, 0.f, 0.f, 0.f};
    const uint32_t ONES2 = 0x3C003C00u;
    uint32_t b_ones[2] = {ONES2, ONES2};
    int r0 = qb*128 + wid*16 + g;
    int r1 = r0 + 8;

    int nkb = 2*(qb + 1);
    for (int kb = 0; kb < nkb; kb++) {
        int st = kb & 1;
        if (kb + 1 < nkb) {
            int st2 = st ^ 1;
            for (int i = tid; i < 64*16; i += 256) {
                int r = i >> 4, c = i & 15;
                cpa16(ksb[st2] + (uint32_t)(r*136 + c*8)*2,
                      Kg + (size_t)((kb+1)*64 + r)*HD + c*8);
            }
            for (int i = tid; i < 128*8; i += 256) {
                int r = i >> 3, c = i & 7;
                cpa16(vsb[st2] + (uint32_t)(r*72 + c*8)*2,
                      Vg + (size_t)r*SS + (kb+1)*64 + c*8);
            }
            CP_COMMIT(); CP_WAIT1();
        } else {
            CP_WAIT0();
        }
        __syncthreads();
        const __half* Ks = (st == 0) ? Ks0 : Ks1;
        const __half* Vs = (st == 0) ? Vs0 : Vs1;

        float sacc[8][4];
        #pragma unroll
        for (int nt = 0; nt < 8; nt++)
            #pragma unroll
            for (int q = 0; q < 4; q++) sacc[nt][q] = 0.f;
        #pragma unroll
        for (int ks = 0; ks < 8; ks++) {
            uint32_t a[4];
            const __half* qr = &Qs[(wid*16 + g)*136 + ks*16 + 2*tig];
            a[0] = *(const uint32_t*)qr;
            a[1] = *(const uint32_t*)(qr + 8*136);
            a[2] = *(const uint32_t*)(qr + 8);
            a[3] = *(const uint32_t*)(qr + 8*136 + 8);
            #pragma unroll
            for (int nt = 0; nt < 8; nt++) {
                uint32_t b[2];
                const __half* kr = &Ks[(nt*8 + g)*136 + ks*16 + 2*tig];
                b[0] = *(const uint32_t*)kr;
                b[1] = *(const uint32_t*)(kr + 8);
                mma16816(sacc[nt], a, b);
            }
        }
        if (kb >= 2*qb) {
            #pragma unroll
            for (int nt = 0; nt < 8; nt++) {
                int col = kb*64 + nt*8 + 2*tig;
                if (col     > r0) sacc[nt][0] = -10000.f;
                if (col + 1 > r0) sacc[nt][1] = -10000.f;
                if (col     > r1) sacc[nt][2] = -10000.f;
                if (col + 1 > r1) sacc[nt][3] = -10000.f;
            }
        }
        #pragma unroll
        for (int j = 0; j < 4; j++) {
            uint32_t a[4];
            __half2 t;
            t = __floats2half2_rn(sacc[2*j][0],   sacc[2*j][1]);   a[0] = ex2h2(*(uint32_t*)&t);
            t = __floats2half2_rn(sacc[2*j][2],   sacc[2*j][3]);   a[1] = ex2h2(*(uint32_t*)&t);
            t = __floats2half2_rn(sacc[2*j+1][0], sacc[2*j+1][1]); a[2] = ex2h2(*(uint32_t*)&t);
            t = __floats2half2_rn(sacc[2*j+1][2], sacc[2*j+1][3]); a[3] = ex2h2(*(uint32_t*)&t);
            mma16816(accL, a, b_ones);
            #pragma unroll
            for (int nd = 0; nd < 16; nd++) {
                uint32_t b[2];
                const __half* vr = &Vs[(nd*8 + g)*72 + j*16 + 2*tig];
                b[0] = *(const uint32_t*)vr;
                b[1] = *(const uint32_t*)(vr + 8);
                mma16816(accO[nd], a, b);
            }
        }
        __syncthreads();
    }
    float inv0 = 1.f / accL[0], inv1 = 1.f / accL[2];
    __half* stg = smh;
    int lr = wid*16 + g;
    size_t obase = ((size_t)bb*SS + (size_t)qb*128) * EMBED + hb*HD;
    #pragma unroll
    for (int nd = 0; nd < 16; nd++) {
        int col = nd*8 + 2*tig;
        *(__half2*)&stg[lr*136 + col] =
            __floats2half2_rn(accO[nd][0]*inv0, accO[nd][1]*inv0);
        *(__half2*)&stg[(lr+8)*136 + col] =
            __floats2half2_rn(accO[nd][2]*inv1, accO[nd][3]*inv1);
    }
    __syncthreads();
    for (int i = tid; i < 128*16; i += 256) {
        int r = i >> 4, c = i & 15;
        *(uint4*)(oh + obase + (size_t)r*EMBED + c*8) = *(uint4*)&stg[r*136 + c*8];
    }
}

// ---------------- driver ------------------------------------------------------
typedef CUresult (CUDAAPI *tmap_fn_t)(
    CUtensorMap*, CUtensorMapDataType, cuuint32_t, void*,
    const cuuint64_t*, const cuuint64_t*, const cuuint32_t*, const cuuint32_t*,
    CUtensorMapInterleave, CUtensorMapSwizzle, CUtensorMapL2promotion,
    CUtensorMapFloatOOBfill);

static void make_map(tmap_fn_t fn, CUtensorMap* m, const __half* base,
                     uint64_t K, uint64_t rows)
{
    cuuint64_t dims[2]    = {(cuuint64_t)K, (cuuint64_t)rows};
    cuuint64_t strides[1] = {(cuuint64_t)(K * 2)};
    cuuint32_t box[2]     = {64, 256};
    cuuint32_t es[2]      = {1, 1};
    fn(m, CU_TENSOR_MAP_DATA_TYPE_FLOAT16, 2, (void*)base,
       dims, strides, box, es,
       CU_TENSOR_MAP_INTERLEAVE_NONE, CU_TENSOR_MAP_SWIZZLE_128B,
       CU_TENSOR_MAP_L2_PROMOTION_L2_128B, CU_TENSOR_MAP_FLOAT_OOB_FILL_NONE);
}

static inline void conv_launch(const float* src, __half* dst, size_t n)
{
    int n4 = (int)(n / 4);
    conv_kernel<<<(n4 + 255)/256, 256>>>(src, dst, n4);
}

static void gemm_launch(tmap_fn_t fn,
                        const __half* A, const __half* B,
                        float* Cf, __half* Ch, const float* addend,
                        int M, int N, int K, int mode, uint64_t Brows)
{
    CUtensorMap mA, mB;
    make_map(fn, &mA, A, (uint64_t)K, (uint64_t)M);
    make_map(fn, &mB, B, (uint64_t)K, Brows);
    cudaLaunchConfig_t cfg = {};
    cfg.gridDim = dim3(N/256, M/256);
    cfg.blockDim = dim3(256);
    cfg.dynamicSmemBytes = GM_SMEM_BYTES;
    cudaLaunchAttribute at[1];
    at[0].id = cudaLaunchAttributeClusterDimension;
    at[0].val.clusterDim.x = 1; at[0].val.clusterDim.y = 2; at[0].val.clusterDim.z = 1;
    cfg.attrs = at; cfg.numAttrs = 1;
    cudaLaunchKernelEx(&cfg, tc_gemm, mA, mB, A, B, Cf, Ch, addend, M, N, K, mode);
}

extern "C" void kernel_launch(void* const* d_in, const int* in_sizes, int n_in,
                              void* d_out, int out_size)
{
    const float* x       = (const float*)d_in[0];
    const float* freqs   = (const float*)d_in[2];
    const float* w_qkv   = (const float*)d_in[4];
    const float* w_fc    = (const float*)d_in[5];
    const float* w1      = (const float*)d_in[6];
    const float* w2      = (const float*)d_in[7];
    const float* w3      = (const float*)d_in[8];
    const float* attn_nw = (const float*)d_in[9];
    const float* ff_nw   = (const float*)d_in[10];
    float* out = (float*)d_out;

    float *h1;
    __half *qkvh, *qh, *kh, *vh, *ah, *sw, *wh;
    cudaGetSymbolAddress((void**)&qkvh, g_qkvh);
    cudaGetSymbolAddress((void**)&qh,  g_qh2);
    cudaGetSymbolAddress((void**)&kh,  g_kh2);
    cudaGetSymbolAddress((void**)&vh,  g_vh2);
    cudaGetSymbolAddress((void**)&h1,  g_h1);
    cudaGetSymbolAddress((void**)&ah,  g_ah);
    cudaGetSymbolAddress((void**)&sw,  g_sw);
    cudaGetSymbolAddress((void**)&wh,  g_wh);

    void* pfn = nullptr;
    cudaDriverEntryPointQueryResult qr;
    cudaGetDriverEntryPointByVersion("cuTensorMapEncodeTiled", &pfn, 12000,
                                     cudaEnableDefault, &qr);
    tmap_fn_t fn = (tmap_fn_t)pfn;

    cudaFuncSetAttribute(tc_gemm, cudaFuncAttributeMaxDynamicSharedMemorySize, GM_SMEM_BYTES);
    cudaFuncSetAttribute(flash_tc_kernel, cudaFuncAttributeMaxDynamicSharedMemorySize, FLH_SMEM_BYTES);

    // 1. attn rmsnorm -> fp16
    rmsnorm_h_kernel<<<ROWS, 256>>>(x, attn_nw, ah);
    // 2. qkv projection -> fp16 qkvh
    conv_launch(w_qkv, wh, (size_t)QKV_N*EMBED);
    gemm_launch(fn, ah, wh, nullptr, qkvh, nullptr, ROWS, QKV_N, EMBED, 1, QKV_N);
    // 3. rope (q,k) + coalesced V transpose
    rope_kernel<<<dim3(SS, BB), 256>>>(qkvh, freqs, qh, kh);
    vtrans_kernel<<<dim3(SS/64, NKV, BB), 256>>>(qkvh, vh);
    // 4. tensor-core flash attention -> fp16 attn into g_ah
    flash_tc_kernel<<<dim3(SS/128, NH, BB), 256, FLH_SMEM_BYTES>>>(qh, kh, vh, ah);
    // 5. output projection + residual -> fp32 h1
    conv_launch(w_fc, wh, (size_t)EMBED*EMBED);
    gemm_launch(fn, ah, wh, h1, nullptr, x, ROWS, EMBED, EMBED, 0, EMBED);
    // 6. ffn rmsnorm -> fp16
    rmsnorm_h_kernel<<<ROWS, 256>>>(h1, ff_nw, ah);
    // 7. interleaved gate|up projection with FUSED swiglu -> g_sw
    {
        int n4 = FF*EMBED/4;
        conv_inter_kernel<<<(n4 + 255)/256, 256>>>(w1, w2, wh, n4);
    }
    gemm_launch(fn, ah, wh, nullptr, sw, nullptr, ROWS, 2*FF, EMBED, 2, 2*FF);
    // 8. down projection + residual -> out
    conv_launch(w3, wh, (size_t)EMBED*FF);
    gemm_launch(fn, sw, wh, out, nullptr, h1, ROWS, EMBED, FF, 0, EMBED);
}